// round 8
// baseline (speedup 1.0000x reference)
#include <cuda_runtime.h>
#include <cuda_bf16.h>
#include <cstdint>
#include <cstddef>

// ----------------------------------------------------------------------------
// FocalTransformerBlock  B=2, H=W=256, C=128, HEADS=4, HD=32, WS=8, EXP=3
// bf16 mma.m16n8k16 + ldmatrix; fp32 residual trunk
// ----------------------------------------------------------------------------

#define BATCH   2
#define HW      65536
#define CDIM    128
#define MROWS   (BATCH*HW)      // 131072
#define NWH     32
#define NWIN    1024
#define WA      64
#define NROLL   220
#define NALL    229
#define NPAD    256
#define HEADS   4
#define HD      32
#define SCALE   0.17677669529663687f

typedef __nv_bfloat16 bf16;

// -------------------------- scratch (static device) -------------------------
__device__ bf16  g_xh[MROWS * CDIM];
__device__ bf16  g_qkv[MROWS * 3 * CDIM];
__device__ bf16  g_pooled[BATCH * NWIN * CDIM];
__device__ bf16  g_qkvp[BATCH * NWIN * 3 * CDIM];
__device__ bf16  g_attnout[MROWS * CDIM];
__device__ float g_x2[MROWS * CDIM];
__device__ bf16  g_fc1[MROWS * 512];
__device__ int   g_rolled[156];

__constant__ int c_sh[4] = {-3,-3, 3, 3};
__constant__ int c_sw[4] = {-3, 3,-3, 3};

// -------------------------- helpers -----------------------------------------
__device__ __forceinline__ uint32_t pack_bf2(float x, float y) {
    __nv_bfloat162 p = __floats2bfloat162_rn(x, y);
    return *reinterpret_cast<uint32_t*>(&p);
}

__device__ __forceinline__ void mma_bf16(float c[4], const uint32_t a[4],
                                         const uint32_t b[2]) {
    asm volatile(
        "mma.sync.aligned.m16n8k16.row.col.f32.bf16.bf16.f32 "
        "{%0,%1,%2,%3},{%4,%5,%6,%7},{%8,%9},{%0,%1,%2,%3};"
        : "+f"(c[0]), "+f"(c[1]), "+f"(c[2]), "+f"(c[3])
        : "r"(a[0]), "r"(a[1]), "r"(a[2]), "r"(a[3]), "r"(b[0]), "r"(b[1]));
}

__device__ __forceinline__ void ldsm_x4(uint32_t r[4], uint32_t saddr) {
    asm volatile("ldmatrix.sync.aligned.m8n8.x4.shared.b16 {%0,%1,%2,%3}, [%4];"
        : "=r"(r[0]), "=r"(r[1]), "=r"(r[2]), "=r"(r[3]) : "r"(saddr));
}
__device__ __forceinline__ void ldsm_x2(uint32_t r[2], uint32_t saddr) {
    asm volatile("ldmatrix.sync.aligned.m8n8.x2.shared.b16 {%0,%1}, [%2];"
        : "=r"(r[0]), "=r"(r[1]) : "r"(saddr));
}
__device__ __forceinline__ uint32_t smem_u32(const void* p) {
    return (uint32_t)__cvta_generic_to_shared(p);
}

// -------------------------- init rolled index table -------------------------
__global__ void init_rolled_kernel() {
    if (threadIdx.x == 0 && blockIdx.x == 0) {
        int cnt = 0;
        for (int idx = 0; idx < 256; idx++) {
            int m = idx >> 6, r = (idx >> 3) & 7, c = idx & 7;
            bool valid;
            if      (m == 0) valid = (r >= 5) || (c >= 5);
            else if (m == 1) valid = (r >= 5) || (c < 3);
            else if (m == 2) valid = (r < 3)  || (c >= 5);
            else             valid = (r < 3)  || (c < 3);
            if (valid) g_rolled[cnt++] = idx;
        }
    }
}

// -------------------------- layernorm (fp32 in -> bf16 out) ------------------
__global__ void __launch_bounds__(256) ln_kernel(
    const float* __restrict__ x, const float* __restrict__ g,
    const float* __restrict__ b, bf16* __restrict__ out, int rows)
{
    int row = (blockIdx.x * blockDim.x + threadIdx.x) >> 5;
    if (row >= rows) return;
    int lane = threadIdx.x & 31;
    const float4* xr = (const float4*)(x + (size_t)row * CDIM);
    float4 v = xr[lane];
    float s = v.x + v.y + v.z + v.w;
    #pragma unroll
    for (int o = 16; o > 0; o >>= 1) s += __shfl_xor_sync(~0u, s, o);
    float mu = s * (1.0f / CDIM);
    float dx = v.x-mu, dy = v.y-mu, dz = v.z-mu, dw = v.w-mu;
    float s2 = dx*dx + dy*dy + dz*dz + dw*dw;
    #pragma unroll
    for (int o = 16; o > 0; o >>= 1) s2 += __shfl_xor_sync(~0u, s2, o);
    float rs = rsqrtf(s2 * (1.0f / CDIM) + 1e-5f);
    float4 gg = ((const float4*)g)[lane];
    float4 bb = ((const float4*)b)[lane];
    uint2 o2;
    o2.x = pack_bf2(dx*rs*gg.x + bb.x, dy*rs*gg.y + bb.y);
    o2.y = pack_bf2(dz*rs*gg.z + bb.z, dw*rs*gg.w + bb.w);
    ((uint2*)(out + (size_t)row * CDIM))[lane] = o2;
}

// -------------------------- bf16 GEMM: out = A @ W^T + bias (+epilogue) -----
// A:(M,K) bf16 rm, W:(N,K) fp32 rm. Block 128x128x32, 8 warps, warp 32x64.
// epi: 0 = bf16 out, 1 = gelu -> bf16 out, 2 = +res(fp32) -> fp32 out
__global__ void __launch_bounds__(256) gemm_tc(
    const bf16* __restrict__ A, const float* __restrict__ W,
    const float* __restrict__ bias, const float* __restrict__ res,
    void* __restrict__ outv, int M, int N, int K, int epi)
{
    __shared__ uint32_t As[128][20];   // rows of 32 bf16 (16 u32), pad 20
    __shared__ uint32_t Ws[128][20];
    int tid = threadIdx.x, lane = tid & 31, warp = tid >> 5;
    int wm = warp >> 1, wn = warp & 1;
    int grp = lane >> 2, tig = lane & 3;
    int m0 = blockIdx.y * 128, n0 = blockIdx.x * 128;

    // per-lane ldmatrix addresses (byte offsets; add base*4 per kstep)
    uint32_t aA0 = smem_u32(&As[wm * 32      + (lane & 15)][(lane >> 4) * 4]);
    uint32_t aA1 = smem_u32(&As[wm * 32 + 16 + (lane & 15)][(lane >> 4) * 4]);
    int brow = ((lane >> 4) << 3) + (lane & 7), bcol = ((lane >> 3) & 1) * 4;
    uint32_t aB[4];
    #pragma unroll
    for (int ng = 0; ng < 4; ng++)
        aB[ng] = smem_u32(&Ws[wn * 64 + ng * 16 + brow][bcol]);

    float c[2][8][4];
    #pragma unroll
    for (int mt = 0; mt < 2; mt++)
        #pragma unroll
        for (int nt = 0; nt < 8; nt++)
            #pragma unroll
            for (int j = 0; j < 4; j++) c[mt][nt][j] = 0.f;

    for (int k0 = 0; k0 < K; k0 += 32) {
        // A chunk: 128 rows x 32 bf16 = 512 uint4, 2 per thread
        #pragma unroll
        for (int i = 0; i < 2; i++) {
            int idx = tid + i * 256;
            int r = idx >> 2, c8 = (idx & 3) * 8;
            uint4 v = *(const uint4*)&A[(size_t)(m0 + r) * K + k0 + c8];
            *(uint4*)&As[r][c8 >> 1] = v;
        }
        // W chunk: 128 rows x 32 fp32 -> bf16; 4 float4 per thread
        #pragma unroll
        for (int i = 0; i < 4; i++) {
            int idx = tid + i * 256;
            int r = idx >> 3, c4 = (idx & 7) * 4;
            float4 v = *(const float4*)&W[(size_t)(n0 + r) * K + k0 + c4];
            Ws[r][(c4 >> 1)    ] = pack_bf2(v.x, v.y);
            Ws[r][(c4 >> 1) + 1] = pack_bf2(v.z, v.w);
        }
        __syncthreads();
        #pragma unroll
        for (int ks = 0; ks < 2; ks++) {
            uint32_t boff = ks * 32;          // 8 u32 * 4 bytes
            uint32_t a[2][4], b[8][2];
            ldsm_x4(a[0], aA0 + boff);
            ldsm_x4(a[1], aA1 + boff);
            #pragma unroll
            for (int ng = 0; ng < 4; ng++) {
                uint32_t r4[4];
                ldsm_x4(r4, aB[ng] + boff);
                b[2*ng  ][0] = r4[0]; b[2*ng  ][1] = r4[1];
                b[2*ng+1][0] = r4[2]; b[2*ng+1][1] = r4[3];
            }
            #pragma unroll
            for (int mt = 0; mt < 2; mt++)
                #pragma unroll
                for (int nt = 0; nt < 8; nt++)
                    mma_bf16(c[mt][nt], a[mt], b[nt]);
        }
        __syncthreads();
    }

    #pragma unroll
    for (int mt = 0; mt < 2; mt++) {
        int r0 = m0 + wm * 32 + mt * 16 + grp;
        #pragma unroll
        for (int nt = 0; nt < 8; nt++) {
            int cn = n0 + wn * 64 + nt * 8 + tig * 2;
            float2 bp = *(const float2*)&bias[cn];
            #pragma unroll
            for (int half = 0; half < 2; half++) {
                int row = r0 + half * 8;
                float v0 = c[mt][nt][half * 2 + 0] + bp.x;
                float v1 = c[mt][nt][half * 2 + 1] + bp.y;
                if (epi == 1) {
                    v0 = 0.5f * v0 * (1.0f + erff(v0 * 0.70710678118654752f));
                    v1 = 0.5f * v1 * (1.0f + erff(v1 * 0.70710678118654752f));
                }
                if (epi == 2) {
                    float2 rr = *(const float2*)&res[(size_t)row * N + cn];
                    *(float2*)&((float*)outv)[(size_t)row * N + cn] =
                        make_float2(v0 + rr.x, v1 + rr.y);
                } else {
                    ((uint32_t*)outv)[((size_t)row * N + cn) >> 1] = pack_bf2(v0, v1);
                }
            }
        }
    }
}

// -------------------------- window pooling (bf16 in/out) ---------------------
__global__ void __launch_bounds__(128) pool_kernel(
    const bf16* __restrict__ xh, const float* __restrict__ pw,
    const float* __restrict__ pb, bf16* __restrict__ pooled)
{
    int w = blockIdx.x;
    int b = w >> 10, ij = w & 1023;
    int i = ij >> 5, j = ij & 31;
    int c = threadIdx.x;
    float acc = 0.f;
    #pragma unroll
    for (int n = 0; n < 64; n++) {
        int r = n >> 3, cc = n & 7;
        size_t tok = (size_t)(b * HW + (i * 8 + r) * 256 + (j * 8 + cc));
        acc += __bfloat162float(xh[tok * CDIM + c]) * pw[n];
    }
    pooled[(size_t)w * CDIM + c] = __float2bfloat16(acc + pb[0]);
}

// -------------------------- attention bias ----------------------------------
__device__ __forceinline__ float attn_bias(
    int q, int k, int h, int wi, int wj,
    const float* __restrict__ rpbt, const float* __restrict__ rpbn,
    const float* __restrict__ rpbw)
{
    int qr = q >> 3, qc = q & 7;
    if (k < 64) {
        int kr = k >> 3, kc = k & 7;
        return rpbt[((qr - kr + 7) * 15 + (qc - kc + 7)) * HEADS + h];
    }
    if (k < NROLL) return rpbn[(size_t)(h * 64 + q) * 156 + (k - 64)];
    int p = k - NROLL;
    int kr = p / 3, kc = p % 3;
    float b = rpbw[h * 100 + (qr - kr + 2) * 10 + (qc - kc + 2)];
    int pi = wi + kr - 1, pj = wj + kc - 1;
    if (!(pi >= 0 && pi < 32 && pj >= 0 && pj < 32)) b -= 100.f;
    return b;
}

// -------------------------- attention (bf16 mma + ldmatrix) ------------------
// grid (2048, 4), 512 threads (16 warps)
#define LDS_F 260               // sAttn fp32 row stride
#define LDP_H 264               // sP / sVt bf16 row stride (132 u32)
__global__ void __launch_bounds__(512) attn_kernel(
    const bf16* __restrict__ qkv, const bf16* __restrict__ qkvp,
    const float* __restrict__ rpbt, const float* __restrict__ rpbn,
    const float* __restrict__ rpbw, bf16* __restrict__ out)
{
    extern __shared__ char smraw[];
    float*    sAttn = (float*)smraw;                        // 64*260*4 = 66560
    uint32_t* sQ    = (uint32_t*)(smraw + 66560);           // [64][20]  = 5120
    uint32_t* sK    = (uint32_t*)(smraw + 66560 + 5120);    // [256][20] = 20480
    bf16*     sVt   = (bf16*)(smraw + 92160);               // [32][264] = 16896
    bf16*     sP    = (bf16*)(smraw + 109056);              // [64][264] = 33792
    float*    sInv  = (float*)(smraw + 142848);             // 64*4

    int tid = threadIdx.x, lane = tid & 31, warp = tid >> 5;
    int grp = lane >> 2, tig = lane & 3;
    int w = blockIdx.x, h = blockIdx.y;
    int b = w >> 10, wi = (w >> 5) & 31, wj = w & 31;
    int bt = b << 16;

    // ---- load Q: sQ[q][d], rows of 32 bf16 pad 40 (20 u32) ----
    {
        int q = tid >> 3, d4 = (tid & 7) * 4;
        int gi = wi * 8 + (q >> 3), gj = wj * 8 + (q & 7);
        uint2 v = *(const uint2*)&qkv[(size_t)(bt + gi * 256 + gj) * 384 + h * 32 + d4];
        *(uint2*)&sQ[q * 20 + (d4 >> 1)] = v;
    }
    // ---- gather K (sK[kpos][d]) and V^T (sVt[d][kpos]); pads zero ----
    #pragma unroll
    for (int it = 0; it < 4; it++) {
        int idx = tid + it * 512;
        int krow = idx >> 3, d4 = (idx & 7) * 4;
        uint2 kv = make_uint2(0u, 0u), vv = kv;
        if (krow < NROLL) {
            int gi, gj;
            if (krow < 64) {
                gi = wi * 8 + (krow >> 3);
                gj = wj * 8 + (krow & 7);
            } else {
                int raw = g_rolled[krow - 64];
                int m = raw >> 6, r = (raw >> 3) & 7, c = raw & 7;
                gi = (wi * 8 + r - c_sh[m]) & 255;
                gj = (wj * 8 + c - c_sw[m]) & 255;
            }
            size_t base = (size_t)(bt + gi * 256 + gj) * 384 + 128 + h * 32 + d4;
            kv = *(const uint2*)&qkv[base];
            vv = *(const uint2*)&qkv[base + 128];
        } else if (krow < NALL) {
            int p = krow - NROLL;
            int pi = wi + p / 3 - 1, pj = wj + p % 3 - 1;
            if (pi >= 0 && pi < 32 && pj >= 0 && pj < 32) {
                size_t base = (size_t)((b << 10) + pi * 32 + pj) * 384 + 128 + h * 32 + d4;
                kv = *(const uint2*)&qkvp[base];
                vv = *(const uint2*)&qkvp[base + 128];
            }
        }
        *(uint2*)&sK[krow * 20 + (d4 >> 1)] = kv;
        __nv_bfloat162 v0 = *reinterpret_cast<__nv_bfloat162*>(&vv.x);
        __nv_bfloat162 v1 = *reinterpret_cast<__nv_bfloat162*>(&vv.y);
        sVt[(d4 + 0) * LDP_H + krow] = v0.x;
        sVt[(d4 + 1) * LDP_H + krow] = v0.y;
        sVt[(d4 + 2) * LDP_H + krow] = v1.x;
        sVt[(d4 + 3) * LDP_H + krow] = v1.y;
    }
    __syncthreads();

    // ---- QK^T (bf16 mma): warp = (wm mtile, ng group of 8 ntiles) ----
    {
        int wm = warp >> 2, ng = warp & 3;
        uint32_t aQ = smem_u32(&sQ[(wm * 16 + (lane & 15)) * 20 + (lane >> 4) * 4]);
        int brow = ((lane >> 4) << 3) + (lane & 7), bcol = ((lane >> 3) & 1) * 4;
        uint32_t aK[4];
        #pragma unroll
        for (int p = 0; p < 4; p++)
            aK[p] = smem_u32(&sK[(ng * 64 + p * 16 + brow) * 20 + bcol]);

        float c[8][4];
        #pragma unroll
        for (int nt = 0; nt < 8; nt++)
            #pragma unroll
            for (int j = 0; j < 4; j++) c[nt][j] = 0.f;
        #pragma unroll
        for (int ks = 0; ks < 2; ks++) {
            uint32_t boff = ks * 32;
            uint32_t a[4], bfr[8][2];
            ldsm_x4(a, aQ + boff);
            #pragma unroll
            for (int p = 0; p < 4; p++) {
                uint32_t r4[4];
                ldsm_x4(r4, aK[p] + boff);
                bfr[2*p  ][0] = r4[0]; bfr[2*p  ][1] = r4[1];
                bfr[2*p+1][0] = r4[2]; bfr[2*p+1][1] = r4[3];
            }
            #pragma unroll
            for (int nt = 0; nt < 8; nt++)
                mma_bf16(c[nt], a, bfr[nt]);
        }
        // epilogue: v = c*SCALE + bias; pads -> 0
        int r0 = wm * 16 + grp;
        #pragma unroll
        for (int nt = 0; nt < 8; nt++) {
            int cn = ng * 64 + nt * 8 + tig * 2;
            #pragma unroll
            for (int half = 0; half < 2; half++) {
                int row = r0 + half * 8;
                float v0 = (cn < NALL)
                    ? c[nt][half * 2 + 0] * SCALE + attn_bias(row, cn, h, wi, wj, rpbt, rpbn, rpbw)
                    : 0.f;
                float v1 = (cn + 1 < NALL)
                    ? c[nt][half * 2 + 1] * SCALE + attn_bias(row, cn + 1, h, wi, wj, rpbt, rpbn, rpbw)
                    : 0.f;
                sAttn[row * LDS_F + cn]     = v0;
                sAttn[row * LDS_F + cn + 1] = v1;
            }
        }
    }
    __syncthreads();

    // ---- softmax: 8 threads per row; write bf16 P; zero pads ----
    {
        int row = tid >> 3, l8 = tid & 7;
        const float* pr = sAttn + row * LDS_F;
        bf16* pp = sP + row * LDP_H;
        float mx = -1e30f;
        for (int k = l8; k < NALL; k += 8) mx = fmaxf(mx, pr[k]);
        mx = fmaxf(mx, __shfl_xor_sync(~0u, mx, 1));
        mx = fmaxf(mx, __shfl_xor_sync(~0u, mx, 2));
        mx = fmaxf(mx, __shfl_xor_sync(~0u, mx, 4));
        float s = 0.f;
        for (int k = l8; k < NALL; k += 8) {
            float e = __expf(pr[k] - mx);
            pp[k] = __float2bfloat16(e);
            s += e;
        }
        for (int k = NALL + l8; k < NPAD; k += 8) pp[k] = __float2bfloat16(0.f);
        s += __shfl_xor_sync(~0u, s, 1);
        s += __shfl_xor_sync(~0u, s, 2);
        s += __shfl_xor_sync(~0u, s, 4);
        if (l8 == 0) sInv[row] = 1.0f / s;
    }
    __syncthreads();

    // ---- P @ V (bf16 mma): warp = (wm mtile, wn group of 8 dims) ----
    {
        int wm = warp >> 2, wn = warp & 3;
        uint32_t aP = smem_u32(&((uint32_t*)sP)[(wm * 16 + (lane & 15)) * 132 + (lane >> 4) * 4]);
        int l2 = lane & 15;
        uint32_t aV = smem_u32(&((uint32_t*)sVt)[(wn * 8 + (l2 & 7)) * 132 + ((l2 >> 3) & 1) * 4]);

        float c[4] = {0.f, 0.f, 0.f, 0.f};
        int r0 = wm * 16 + grp;
        int vn = wn * 8;
        #pragma unroll 4
        for (int kk = 0; kk < NPAD; kk += 16) {
            uint32_t boff = (kk >> 1) * 4;
            uint32_t a[4], bfr[2];
            ldsm_x4(a, aP + boff);
            ldsm_x2(bfr, aV + boff);
            mma_bf16(c, a, bfr);
        }
        int d0 = vn + tig * 2;
        #pragma unroll
        for (int half = 0; half < 2; half++) {
            int row = r0 + half * 8;
            float inv = sInv[row];
            int gi = wi * 8 + (row >> 3), gj = wj * 8 + (row & 7);
            uint32_t* o = (uint32_t*)&out[(size_t)(bt + gi * 256 + gj) * CDIM + h * 32 + d0];
            *o = pack_bf2(c[half * 2 + 0] * inv, c[half * 2 + 1] * inv);
        }
    }
}

// ----------------------------------------------------------------------------
extern "C" void kernel_launch(void* const* d_in, const int* in_sizes, int n_in,
                              void* d_out, int out_size)
{
    const float* x      = (const float*)d_in[0];
    const float* qkv_w  = (const float*)d_in[1];
    const float* qkv_b  = (const float*)d_in[2];
    const float* proj_w = (const float*)d_in[3];
    const float* proj_b = (const float*)d_in[4];
    const float* n1g    = (const float*)d_in[5];
    const float* n1b    = (const float*)d_in[6];
    const float* n2g    = (const float*)d_in[7];
    const float* n2b    = (const float*)d_in[8];
    const float* rpbt   = (const float*)d_in[9];
    const float* rpbn   = (const float*)d_in[10];
    const float* rpbw   = (const float*)d_in[11];
    const float* poolw  = (const float*)d_in[12];
    const float* poolb  = (const float*)d_in[13];
    const float* fc1_w  = (const float*)d_in[14];
    const float* fc1_b  = (const float*)d_in[15];
    const float* fc2_w  = (const float*)d_in[16];
    const float* fc2_b  = (const float*)d_in[17];
    float* outp = (float*)d_out;

    bf16 *p_xh, *p_qkv, *p_pooled, *p_qkvp, *p_attnout, *p_fc1;
    float *p_x2;
    cudaGetSymbolAddress((void**)&p_xh, g_xh);
    cudaGetSymbolAddress((void**)&p_qkv, g_qkv);
    cudaGetSymbolAddress((void**)&p_pooled, g_pooled);
    cudaGetSymbolAddress((void**)&p_qkvp, g_qkvp);
    cudaGetSymbolAddress((void**)&p_attnout, g_attnout);
    cudaGetSymbolAddress((void**)&p_x2, g_x2);
    cudaGetSymbolAddress((void**)&p_fc1, g_fc1);

    const int ATTN_SMEM = 142848 + 256;   // 143104 B
    cudaFuncSetAttribute(attn_kernel,
                         cudaFuncAttributeMaxDynamicSharedMemorySize, ATTN_SMEM);

    // 0. rolled index table
    init_rolled_kernel<<<1, 1>>>();
    // 1. LN1 -> bf16 xh
    ln_kernel<<<MROWS / 8, 256>>>(x, n1g, n1b, p_xh, MROWS);
    // 2. qkv GEMM  (131072 x 384, K=128) -> bf16
    gemm_tc<<<dim3(384 / 128, MROWS / 128), 256>>>(
        p_xh, qkv_w, qkv_b, nullptr, p_qkv, MROWS, 384, 128, 0);
    // 3. window pooling
    pool_kernel<<<BATCH * NWIN, 128>>>(p_xh, poolw, poolb, p_pooled);
    // 4. qkv of pooled (2048 x 384, K=128) -> bf16
    gemm_tc<<<dim3(384 / 128, (BATCH * NWIN) / 128), 256>>>(
        p_pooled, qkv_w, qkv_b, nullptr, p_qkvp, BATCH * NWIN, 384, 128, 0);
    // 5. focal attention (bf16 mma) -> bf16 attnout
    attn_kernel<<<dim3(BATCH * NWIN, HEADS), 512, ATTN_SMEM>>>(
        p_qkv, p_qkvp, rpbt, rpbn, rpbw, p_attnout);
    // 6. proj + residual(x) -> fp32 x2
    gemm_tc<<<dim3(CDIM / 128, MROWS / 128), 256>>>(
        p_attnout, proj_w, proj_b, x, p_x2, MROWS, CDIM, 128, 2);
    // 7. LN2 -> bf16 xh
    ln_kernel<<<MROWS / 8, 256>>>(p_x2, n2g, n2b, p_xh, MROWS);
    // 8. fc1 + exact GELU (131072 x 512, K=128) -> bf16
    gemm_tc<<<dim3(512 / 128, MROWS / 128), 256>>>(
        p_xh, fc1_w, fc1_b, nullptr, p_fc1, MROWS, 512, 128, 1);
    // 9. fc2 + residual(x2) -> fp32 out (131072 x 128, K=512)
    gemm_tc<<<dim3(CDIM / 128, MROWS / 128), 256>>>(
        p_fc1, fc2_w, fc2_b, p_x2, outp, MROWS, CDIM, 512, 2);
}

// round 9
// speedup vs baseline: 1.2887x; 1.2887x over previous
#include <cuda_runtime.h>
#include <cuda_bf16.h>
#include <cstdint>
#include <cstddef>

// ----------------------------------------------------------------------------
// FocalTransformerBlock  B=2, H=W=256, C=128, HEADS=4, HD=32, WS=8, EXP=3
// bf16 mma.m16n8k16 + ldmatrix + cp.async pipelined GEMM; fp32 residual trunk
// ----------------------------------------------------------------------------

#define BATCH   2
#define HW      65536
#define CDIM    128
#define MROWS   (BATCH*HW)      // 131072
#define NWH     32
#define NWIN    1024
#define WA      64
#define NROLL   220
#define NALL    229
#define NPAD    256
#define HEADS   4
#define HD      32
#define SCALE   0.17677669529663687f

typedef __nv_bfloat16 bf16;

// -------------------------- scratch (static device) -------------------------
__device__ bf16  g_xh[MROWS * CDIM];
__device__ bf16  g_qkv[MROWS * 3 * CDIM];
__device__ bf16  g_pooled[BATCH * NWIN * CDIM];
__device__ bf16  g_qkvp[BATCH * NWIN * 3 * CDIM];
__device__ bf16  g_attnout[MROWS * CDIM];
__device__ float g_x2[MROWS * CDIM];
__device__ bf16  g_fc1[MROWS * 512];
__device__ int   g_rolled[156];
__device__ float g_btab[HEADS * WA * NPAD];     // precomputed attention bias
__device__ bf16  g_wqkv[384 * 128];             // bf16 weights
__device__ bf16  g_wproj[128 * 128];
__device__ bf16  g_wfc1[512 * 128];
__device__ bf16  g_wfc2[128 * 512];

__constant__ int c_sh[4] = {-3,-3, 3, 3};
__constant__ int c_sw[4] = {-3, 3,-3, 3};

// -------------------------- helpers -----------------------------------------
__device__ __forceinline__ uint32_t pack_bf2(float x, float y) {
    __nv_bfloat162 p = __floats2bfloat162_rn(x, y);
    return *reinterpret_cast<uint32_t*>(&p);
}

__device__ __forceinline__ void mma_bf16(float c[4], const uint32_t a[4],
                                         const uint32_t b[2]) {
    asm volatile(
        "mma.sync.aligned.m16n8k16.row.col.f32.bf16.bf16.f32 "
        "{%0,%1,%2,%3},{%4,%5,%6,%7},{%8,%9},{%0,%1,%2,%3};"
        : "+f"(c[0]), "+f"(c[1]), "+f"(c[2]), "+f"(c[3])
        : "r"(a[0]), "r"(a[1]), "r"(a[2]), "r"(a[3]), "r"(b[0]), "r"(b[1]));
}

__device__ __forceinline__ void ldsm_x4(uint32_t r[4], uint32_t saddr) {
    asm volatile("ldmatrix.sync.aligned.m8n8.x4.shared.b16 {%0,%1,%2,%3}, [%4];"
        : "=r"(r[0]), "=r"(r[1]), "=r"(r[2]), "=r"(r[3]) : "r"(saddr));
}
__device__ __forceinline__ void ldsm_x2(uint32_t r[2], uint32_t saddr) {
    asm volatile("ldmatrix.sync.aligned.m8n8.x2.shared.b16 {%0,%1}, [%2];"
        : "=r"(r[0]), "=r"(r[1]) : "r"(saddr));
}
__device__ __forceinline__ uint32_t smem_u32(const void* p) {
    return (uint32_t)__cvta_generic_to_shared(p);
}
__device__ __forceinline__ void cp16(uint32_t dst, const void* src) {
    asm volatile("cp.async.cg.shared.global [%0], [%1], 16;" :: "r"(dst), "l"(src));
}
#define CP_COMMIT() asm volatile("cp.async.commit_group;")
#define CP_WAIT1()  asm volatile("cp.async.wait_group 1;" ::: "memory")

// -------------------------- one-shot init kernels ----------------------------
__global__ void init_rolled_kernel() {
    if (threadIdx.x == 0 && blockIdx.x == 0) {
        int cnt = 0;
        for (int idx = 0; idx < 256; idx++) {
            int m = idx >> 6, r = (idx >> 3) & 7, c = idx & 7;
            bool valid;
            if      (m == 0) valid = (r >= 5) || (c >= 5);
            else if (m == 1) valid = (r >= 5) || (c < 3);
            else if (m == 2) valid = (r < 3)  || (c >= 5);
            else             valid = (r < 3)  || (c < 3);
            if (valid) g_rolled[cnt++] = idx;
        }
    }
}

__global__ void init_btab_kernel(const float* __restrict__ rpbt,
                                 const float* __restrict__ rpbn,
                                 const float* __restrict__ rpbw) {
    int h = blockIdx.x, q = blockIdx.y;
    int k = threadIdx.x;            // 256
    float v = 0.f;
    int qr = q >> 3, qc = q & 7;
    if (k < 64) {
        int kr = k >> 3, kc = k & 7;
        v = rpbt[((qr - kr + 7) * 15 + (qc - kc + 7)) * HEADS + h];
    } else if (k < NROLL) {
        v = rpbn[(size_t)(h * 64 + q) * 156 + (k - 64)];
    } else if (k < NALL) {
        int p = k - NROLL;
        int kr = p / 3, kc = p % 3;
        v = rpbw[h * 100 + (qr - kr + 2) * 10 + (qc - kc + 2)];
    }
    g_btab[(h * 64 + q) * NPAD + k] = v;
}

__global__ void __launch_bounds__(256) cvt_w_kernel(
    const float* __restrict__ w, bf16* __restrict__ o, int n) {
    int i = (blockIdx.x * 256 + threadIdx.x) * 4;
    if (i < n) {
        float4 v = *(const float4*)&w[i];
        uint2 p;
        p.x = pack_bf2(v.x, v.y);
        p.y = pack_bf2(v.z, v.w);
        *(uint2*)&o[i] = p;
    }
}

// -------------------------- layernorm (fp32 in -> bf16 out) ------------------
__global__ void __launch_bounds__(256) ln_kernel(
    const float* __restrict__ x, const float* __restrict__ g,
    const float* __restrict__ b, bf16* __restrict__ out, int rows)
{
    int row = (blockIdx.x * blockDim.x + threadIdx.x) >> 5;
    if (row >= rows) return;
    int lane = threadIdx.x & 31;
    const float4* xr = (const float4*)(x + (size_t)row * CDIM);
    float4 v = xr[lane];
    float s = v.x + v.y + v.z + v.w;
    #pragma unroll
    for (int o = 16; o > 0; o >>= 1) s += __shfl_xor_sync(~0u, s, o);
    float mu = s * (1.0f / CDIM);
    float dx = v.x-mu, dy = v.y-mu, dz = v.z-mu, dw = v.w-mu;
    float s2 = dx*dx + dy*dy + dz*dz + dw*dw;
    #pragma unroll
    for (int o = 16; o > 0; o >>= 1) s2 += __shfl_xor_sync(~0u, s2, o);
    float rs = rsqrtf(s2 * (1.0f / CDIM) + 1e-5f);
    float4 gg = ((const float4*)g)[lane];
    float4 bb = ((const float4*)b)[lane];
    uint2 o2;
    o2.x = pack_bf2(dx*rs*gg.x + bb.x, dy*rs*gg.y + bb.y);
    o2.y = pack_bf2(dz*rs*gg.z + bb.z, dw*rs*gg.w + bb.w);
    ((uint2*)(out + (size_t)row * CDIM))[lane] = o2;
}

// -------------------------- bf16 GEMM (cp.async 2-stage pipeline) ------------
// A:(M,K) bf16 rm, W:(N,K) bf16 rm. Block 128x64x32, 8 warps, warp 32x32.
// epi: 0 = bf16 out, 1 = gelu -> bf16 out, 2 = +res(fp32) -> fp32 out
__global__ void __launch_bounds__(256) gemm_tc(
    const bf16* __restrict__ A, const bf16* __restrict__ W,
    const float* __restrict__ bias, const float* __restrict__ res,
    void* __restrict__ outv, int M, int N, int K, int epi)
{
    __shared__ uint32_t As[2][128][20];   // rows of 32 bf16 (16 u32), pad 20
    __shared__ uint32_t Ws[2][64][20];
    int tid = threadIdx.x, lane = tid & 31, warp = tid >> 5;
    int wm = warp >> 1, wn = warp & 1;
    int grp = lane >> 2, tig = lane & 3;
    int m0 = blockIdx.y * 128, n0 = blockIdx.x * 64;

    uint32_t sA = smem_u32(&As[0][0][0]);
    uint32_t sW = smem_u32(&Ws[0][0][0]);
    const int A_STG = 128 * 20 * 4;       // 10240 B
    const int W_STG = 64 * 20 * 4;        // 5120 B

    int wr = tid >> 2, wc8 = (tid & 3) * 8;

    auto issue = [&](int s, int k0) {
        #pragma unroll
        for (int i = 0; i < 2; i++) {
            int idx = tid + i * 256;
            int r = idx >> 2, c8 = (idx & 3) * 8;
            cp16(sA + s * A_STG + (r * 20 + (c8 >> 1)) * 4,
                 A + (size_t)(m0 + r) * K + k0 + c8);
        }
        cp16(sW + s * W_STG + (wr * 20 + (wc8 >> 1)) * 4,
             W + (size_t)(n0 + wr) * K + k0 + wc8);
    };

    // ldmatrix per-lane base addresses (stage 0)
    uint32_t aA0 = smem_u32(&As[0][wm * 32 + (lane & 15)][(lane >> 4) * 4]);
    uint32_t aA1 = aA0 + 16 * 80;
    int brow = ((lane >> 4) << 3) + (lane & 7), bcol = ((lane >> 3) & 1) * 4;
    uint32_t aB0 = smem_u32(&Ws[0][wn * 32 + brow][bcol]);
    uint32_t aB1 = aB0 + 16 * 80;

    float c[2][4][4];
    #pragma unroll
    for (int mt = 0; mt < 2; mt++)
        #pragma unroll
        for (int nt = 0; nt < 4; nt++)
            #pragma unroll
            for (int j = 0; j < 4; j++) c[mt][nt][j] = 0.f;

    int niter = K >> 5;
    issue(0, 0);
    CP_COMMIT();
    for (int it = 0; it < niter; it++) {
        int s = it & 1;
        if (it + 1 < niter) issue(s ^ 1, (it + 1) * 32);
        CP_COMMIT();
        CP_WAIT1();
        __syncthreads();
        uint32_t offA = s * A_STG, offW = s * W_STG;
        #pragma unroll
        for (int ks = 0; ks < 2; ks++) {
            uint32_t boff = ks * 32;
            uint32_t a0[4], a1[4], b0[4], b1[4];
            ldsm_x4(a0, aA0 + offA + boff);
            ldsm_x4(a1, aA1 + offA + boff);
            ldsm_x4(b0, aB0 + offW + boff);
            ldsm_x4(b1, aB1 + offW + boff);
            uint32_t bf0[2] = {b0[0], b0[1]}, bf1[2] = {b0[2], b0[3]};
            uint32_t bf2[2] = {b1[0], b1[1]}, bf3[2] = {b1[2], b1[3]};
            mma_bf16(c[0][0], a0, bf0); mma_bf16(c[0][1], a0, bf1);
            mma_bf16(c[0][2], a0, bf2); mma_bf16(c[0][3], a0, bf3);
            mma_bf16(c[1][0], a1, bf0); mma_bf16(c[1][1], a1, bf1);
            mma_bf16(c[1][2], a1, bf2); mma_bf16(c[1][3], a1, bf3);
        }
        __syncthreads();
    }

    #pragma unroll
    for (int mt = 0; mt < 2; mt++) {
        int r0 = m0 + wm * 32 + mt * 16 + grp;
        #pragma unroll
        for (int nt = 0; nt < 4; nt++) {
            int cn = n0 + wn * 32 + nt * 8 + tig * 2;
            float2 bp = *(const float2*)&bias[cn];
            #pragma unroll
            for (int half = 0; half < 2; half++) {
                int row = r0 + half * 8;
                float v0 = c[mt][nt][half * 2 + 0] + bp.x;
                float v1 = c[mt][nt][half * 2 + 1] + bp.y;
                if (epi == 1) {
                    v0 = 0.5f * v0 * (1.0f + erff(v0 * 0.70710678118654752f));
                    v1 = 0.5f * v1 * (1.0f + erff(v1 * 0.70710678118654752f));
                }
                if (epi == 2) {
                    float2 rr = *(const float2*)&res[(size_t)row * N + cn];
                    *(float2*)&((float*)outv)[(size_t)row * N + cn] =
                        make_float2(v0 + rr.x, v1 + rr.y);
                } else {
                    ((uint32_t*)outv)[((size_t)row * N + cn) >> 1] = pack_bf2(v0, v1);
                }
            }
        }
    }
}

// -------------------------- window pooling (bf16 in/out) ---------------------
__global__ void __launch_bounds__(128) pool_kernel(
    const bf16* __restrict__ xh, const float* __restrict__ pw,
    const float* __restrict__ pb, bf16* __restrict__ pooled)
{
    int w = blockIdx.x;
    int b = w >> 10, ij = w & 1023;
    int i = ij >> 5, j = ij & 31;
    int c = threadIdx.x;
    float acc = 0.f;
    #pragma unroll
    for (int n = 0; n < 64; n++) {
        int r = n >> 3, cc = n & 7;
        size_t tok = (size_t)(b * HW + (i * 8 + r) * 256 + (j * 8 + cc));
        acc += __bfloat162float(xh[tok * CDIM + c]) * pw[n];
    }
    pooled[(size_t)w * CDIM + c] = __float2bfloat16(acc + pb[0]);
}

// -------------------------- attention (bf16 mma + ldmatrix) ------------------
// grid (2048, 4), 512 threads (16 warps)
#define LDS_F 260               // sAttn fp32 row stride
#define LDP_H 264               // sP / sVt bf16 row stride (132 u32)
__global__ void __launch_bounds__(512) attn_kernel(
    const bf16* __restrict__ qkv, const bf16* __restrict__ qkvp,
    bf16* __restrict__ out)
{
    extern __shared__ char smraw[];
    float*    sAttn = (float*)smraw;                        // 64*260*4 = 66560
    uint32_t* sQ    = (uint32_t*)(smraw + 66560);           // [64][20]  = 5120
    uint32_t* sK    = (uint32_t*)(smraw + 66560 + 5120);    // [256][20] = 20480
    bf16*     sVt   = (bf16*)(smraw + 92160);               // [32][264] = 16896
    bf16*     sP    = (bf16*)(smraw + 109056);              // [64][264] = 33792
    float*    sInv  = (float*)(smraw + 142848);             // 64*4

    int tid = threadIdx.x, lane = tid & 31, warp = tid >> 5;
    int grp = lane >> 2, tig = lane & 3;
    int w = blockIdx.x, h = blockIdx.y;
    int b = w >> 10, wi = (w >> 5) & 31, wj = w & 31;
    int bt = b << 16;

    // ---- load Q: sQ[q][d], rows of 32 bf16 pad 40 (20 u32) ----
    {
        int q = tid >> 3, d4 = (tid & 7) * 4;
        int gi = wi * 8 + (q >> 3), gj = wj * 8 + (q & 7);
        uint2 v = *(const uint2*)&qkv[(size_t)(bt + gi * 256 + gj) * 384 + h * 32 + d4];
        *(uint2*)&sQ[q * 20 + (d4 >> 1)] = v;
    }
    // ---- gather K (sK[kpos][d]) and V^T (sVt[d][kpos]); pads zero ----
    #pragma unroll
    for (int it = 0; it < 4; it++) {
        int idx = tid + it * 512;
        int krow = idx >> 3, d4 = (idx & 7) * 4;
        uint2 kv = make_uint2(0u, 0u), vv = kv;
        if (krow < NROLL) {
            int gi, gj;
            if (krow < 64) {
                gi = wi * 8 + (krow >> 3);
                gj = wj * 8 + (krow & 7);
            } else {
                int raw = g_rolled[krow - 64];
                int m = raw >> 6, r = (raw >> 3) & 7, c = raw & 7;
                gi = (wi * 8 + r - c_sh[m]) & 255;
                gj = (wj * 8 + c - c_sw[m]) & 255;
            }
            size_t base = (size_t)(bt + gi * 256 + gj) * 384 + 128 + h * 32 + d4;
            kv = *(const uint2*)&qkv[base];
            vv = *(const uint2*)&qkv[base + 128];
        } else if (krow < NALL) {
            int p = krow - NROLL;
            int pi = wi + p / 3 - 1, pj = wj + p % 3 - 1;
            if (pi >= 0 && pi < 32 && pj >= 0 && pj < 32) {
                size_t base = (size_t)((b << 10) + pi * 32 + pj) * 384 + 128 + h * 32 + d4;
                kv = *(const uint2*)&qkvp[base];
                vv = *(const uint2*)&qkvp[base + 128];
            }
        }
        *(uint2*)&sK[krow * 20 + (d4 >> 1)] = kv;
        __nv_bfloat162 v0 = *reinterpret_cast<__nv_bfloat162*>(&vv.x);
        __nv_bfloat162 v1 = *reinterpret_cast<__nv_bfloat162*>(&vv.y);
        sVt[(d4 + 0) * LDP_H + krow] = v0.x;
        sVt[(d4 + 1) * LDP_H + krow] = v0.y;
        sVt[(d4 + 2) * LDP_H + krow] = v1.x;
        sVt[(d4 + 3) * LDP_H + krow] = v1.y;
    }
    __syncthreads();

    // ---- QK^T (bf16 mma): warp = (wm mtile, ng group of 8 ntiles) ----
    {
        int wm = warp >> 2, ng = warp & 3;
        uint32_t aQ = smem_u32(&sQ[(wm * 16 + (lane & 15)) * 20 + (lane >> 4) * 4]);
        int brow = ((lane >> 4) << 3) + (lane & 7), bcol = ((lane >> 3) & 1) * 4;
        uint32_t aK[4];
        #pragma unroll
        for (int p = 0; p < 4; p++)
            aK[p] = smem_u32(&sK[(ng * 64 + p * 16 + brow) * 20 + bcol]);

        float c[8][4];
        #pragma unroll
        for (int nt = 0; nt < 8; nt++)
            #pragma unroll
            for (int j = 0; j < 4; j++) c[nt][j] = 0.f;
        #pragma unroll
        for (int ks = 0; ks < 2; ks++) {
            uint32_t boff = ks * 32;
            uint32_t a[4], bfr[8][2];
            ldsm_x4(a, aQ + boff);
            #pragma unroll
            for (int p = 0; p < 4; p++) {
                uint32_t r4[4];
                ldsm_x4(r4, aK[p] + boff);
                bfr[2*p  ][0] = r4[0]; bfr[2*p  ][1] = r4[1];
                bfr[2*p+1][0] = r4[2]; bfr[2*p+1][1] = r4[3];
            }
            #pragma unroll
            for (int nt = 0; nt < 8; nt++)
                mma_bf16(c[nt], a, bfr[nt]);
        }
        // epilogue: v = c*SCALE + btab[h][row][cn]; pooled-mask fixup; pads = 0
        int r0 = wm * 16 + grp;
        const float* tabh = &g_btab[(h * 64) * NPAD];
        #pragma unroll
        for (int nt = 0; nt < 8; nt++) {
            int cn = ng * 64 + nt * 8 + tig * 2;
            #pragma unroll
            for (int half = 0; half < 2; half++) {
                int row = r0 + half * 8;
                float2 tv = *(const float2*)&tabh[row * NPAD + cn];
                float v0 = c[nt][half * 2 + 0] * SCALE + tv.x;
                float v1 = c[nt][half * 2 + 1] * SCALE + tv.y;
                if (cn + 1 >= NROLL) {              // pooled / pad region
                    #pragma unroll
                    for (int e = 0; e < 2; e++) {
                        int k = cn + e;
                        float* vp = e ? &v1 : &v0;
                        if (k >= NALL) { *vp = 0.f; }
                        else if (k >= NROLL) {
                            int p = k - NROLL;
                            int kr = p / 3, kc = p % 3;
                            int pi = wi + kr - 1, pj = wj + kc - 1;
                            if (!(pi >= 0 && pi < 32 && pj >= 0 && pj < 32))
                                *vp -= 100.f;
                        }
                    }
                }
                sAttn[row * LDS_F + cn]     = v0;
                sAttn[row * LDS_F + cn + 1] = v1;
            }
        }
    }
    __syncthreads();

    // ---- softmax: 8 threads per row; write bf16 P; zero pads ----
    {
        int row = tid >> 3, l8 = tid & 7;
        const float* pr = sAttn + row * LDS_F;
        bf16* pp = sP + row * LDP_H;
        float mx = -1e30f;
        for (int k = l8; k < NALL; k += 8) mx = fmaxf(mx, pr[k]);
        mx = fmaxf(mx, __shfl_xor_sync(~0u, mx, 1));
        mx = fmaxf(mx, __shfl_xor_sync(~0u, mx, 2));
        mx = fmaxf(mx, __shfl_xor_sync(~0u, mx, 4));
        float s = 0.f;
        for (int k = l8; k < NALL; k += 8) {
            float e = __expf(pr[k] - mx);
            pp[k] = __float2bfloat16(e);
            s += e;
        }
        for (int k = NALL + l8; k < NPAD; k += 8) pp[k] = __float2bfloat16(0.f);
        s += __shfl_xor_sync(~0u, s, 1);
        s += __shfl_xor_sync(~0u, s, 2);
        s += __shfl_xor_sync(~0u, s, 4);
        if (l8 == 0) sInv[row] = 1.0f / s;
    }
    __syncthreads();

    // ---- P @ V (bf16 mma): warp = (wm mtile, wn group of 8 dims) ----
    {
        int wm = warp >> 2, wn = warp & 3;
        uint32_t aP = smem_u32(&((uint32_t*)sP)[(wm * 16 + (lane & 15)) * 132 + (lane >> 4) * 4]);
        int l2 = lane & 15;
        uint32_t aV = smem_u32(&((uint32_t*)sVt)[(wn * 8 + (l2 & 7)) * 132 + ((l2 >> 3) & 1) * 4]);

        float c[4] = {0.f, 0.f, 0.f, 0.f};
        int r0 = wm * 16 + grp;
        int vn = wn * 8;
        #pragma unroll 4
        for (int kk = 0; kk < NPAD; kk += 16) {
            uint32_t boff = (kk >> 1) * 4;
            uint32_t a[4], bfr[2];
            ldsm_x4(a, aP + boff);
            ldsm_x2(bfr, aV + boff);
            mma_bf16(c, a, bfr);
        }
        int d0 = vn + tig * 2;
        #pragma unroll
        for (int half = 0; half < 2; half++) {
            int row = r0 + half * 8;
            float inv = sInv[row];
            int gi = wi * 8 + (row >> 3), gj = wj * 8 + (row & 7);
            uint32_t* o = (uint32_t*)&out[(size_t)(bt + gi * 256 + gj) * CDIM + h * 32 + d0];
            *o = pack_bf2(c[half * 2 + 0] * inv, c[half * 2 + 1] * inv);
        }
    }
}

// ----------------------------------------------------------------------------
extern "C" void kernel_launch(void* const* d_in, const int* in_sizes, int n_in,
                              void* d_out, int out_size)
{
    const float* x      = (const float*)d_in[0];
    const float* qkv_w  = (const float*)d_in[1];
    const float* qkv_b  = (const float*)d_in[2];
    const float* proj_w = (const float*)d_in[3];
    const float* proj_b = (const float*)d_in[4];
    const float* n1g    = (const float*)d_in[5];
    const float* n1b    = (const float*)d_in[6];
    const float* n2g    = (const float*)d_in[7];
    const float* n2b    = (const float*)d_in[8];
    const float* rpbt   = (const float*)d_in[9];
    const float* rpbn   = (const float*)d_in[10];
    const float* rpbw   = (const float*)d_in[11];
    const float* poolw  = (const float*)d_in[12];
    const float* poolb  = (const float*)d_in[13];
    const float* fc1_w  = (const float*)d_in[14];
    const float* fc1_b  = (const float*)d_in[15];
    const float* fc2_w  = (const float*)d_in[16];
    const float* fc2_b  = (const float*)d_in[17];
    float* outp = (float*)d_out;

    bf16 *p_xh, *p_qkv, *p_pooled, *p_qkvp, *p_attnout, *p_fc1;
    bf16 *p_wqkv, *p_wproj, *p_wfc1, *p_wfc2;
    float *p_x2;
    cudaGetSymbolAddress((void**)&p_xh, g_xh);
    cudaGetSymbolAddress((void**)&p_qkv, g_qkv);
    cudaGetSymbolAddress((void**)&p_pooled, g_pooled);
    cudaGetSymbolAddress((void**)&p_qkvp, g_qkvp);
    cudaGetSymbolAddress((void**)&p_attnout, g_attnout);
    cudaGetSymbolAddress((void**)&p_x2, g_x2);
    cudaGetSymbolAddress((void**)&p_fc1, g_fc1);
    cudaGetSymbolAddress((void**)&p_wqkv, g_wqkv);
    cudaGetSymbolAddress((void**)&p_wproj, g_wproj);
    cudaGetSymbolAddress((void**)&p_wfc1, g_wfc1);
    cudaGetSymbolAddress((void**)&p_wfc2, g_wfc2);

    const int ATTN_SMEM = 142848 + 256;   // 143104 B
    cudaFuncSetAttribute(attn_kernel,
                         cudaFuncAttributeMaxDynamicSharedMemorySize, ATTN_SMEM);

    // 0. one-shot tables + weight conversion
    init_rolled_kernel<<<1, 1>>>();
    init_btab_kernel<<<dim3(HEADS, WA), 256>>>(rpbt, rpbn, rpbw);
    cvt_w_kernel<<<48, 256>>>(qkv_w,  p_wqkv, 384 * 128);
    cvt_w_kernel<<<16, 256>>>(proj_w, p_wproj, 128 * 128);
    cvt_w_kernel<<<64, 256>>>(fc1_w,  p_wfc1, 512 * 128);
    cvt_w_kernel<<<64, 256>>>(fc2_w,  p_wfc2, 128 * 512);
    // 1. LN1 -> bf16 xh
    ln_kernel<<<MROWS / 8, 256>>>(x, n1g, n1b, p_xh, MROWS);
    // 2. qkv GEMM  (131072 x 384, K=128) -> bf16
    gemm_tc<<<dim3(384 / 64, MROWS / 128), 256>>>(
        p_xh, p_wqkv, qkv_b, nullptr, p_qkv, MROWS, 384, 128, 0);
    // 3. window pooling
    pool_kernel<<<BATCH * NWIN, 128>>>(p_xh, poolw, poolb, p_pooled);
    // 4. qkv of pooled (2048 x 384, K=128) -> bf16
    gemm_tc<<<dim3(384 / 64, (BATCH * NWIN) / 128), 256>>>(
        p_pooled, p_wqkv, qkv_b, nullptr, p_qkvp, BATCH * NWIN, 384, 128, 0);
    // 5. focal attention (bf16 mma) -> bf16 attnout
    attn_kernel<<<dim3(BATCH * NWIN, HEADS), 512, ATTN_SMEM>>>(
        p_qkv, p_qkvp, p_attnout);
    // 6. proj + residual(x) -> fp32 x2
    gemm_tc<<<dim3(CDIM / 64, MROWS / 128), 256>>>(
        p_attnout, p_wproj, proj_b, x, p_x2, MROWS, CDIM, 128, 2);
    // 7. LN2 -> bf16 xh
    ln_kernel<<<MROWS / 8, 256>>>(p_x2, n2g, n2b, p_xh, MROWS);
    // 8. fc1 + exact GELU (131072 x 512, K=128) -> bf16
    gemm_tc<<<dim3(512 / 64, MROWS / 128), 256>>>(
        p_xh, p_wfc1, fc1_b, nullptr, p_fc1, MROWS, 512, 128, 1);
    // 9. fc2 + residual(x2) -> fp32 out (131072 x 128, K=512)
    gemm_tc<<<dim3(CDIM / 64, MROWS / 128), 256>>>(
        p_fc1, p_wfc2, fc2_b, p_x2, outp, MROWS, CDIM, 512, 2);
}

// round 10
// speedup vs baseline: 1.6811x; 1.3045x over previous
#include <cuda_runtime.h>
#include <cuda_bf16.h>
#include <cstdint>
#include <cstddef>

// ----------------------------------------------------------------------------
// FocalTransformerBlock  B=2, H=W=256, C=128, HEADS=4, HD=32, WS=8, EXP=3
// bf16 mma.m16n8k16 + ldmatrix + cp.async; register softmax; fp32 trunk
// ----------------------------------------------------------------------------

#define BATCH   2
#define HW      65536
#define CDIM    128
#define MROWS   (BATCH*HW)      // 131072
#define NWH     32
#define NWIN    1024
#define WA      64
#define NROLL   220
#define NALL    229
#define NPAD    256
#define HEADS   4
#define HD      32
#define SCALE   0.17677669529663687f

typedef __nv_bfloat16 bf16;

// -------------------------- scratch (static device) -------------------------
__device__ bf16  g_xh[MROWS * CDIM];
__device__ bf16  g_qkv[MROWS * 3 * CDIM];
__device__ bf16  g_pooled[BATCH * NWIN * CDIM];
__device__ bf16  g_qkvp[BATCH * NWIN * 3 * CDIM];
__device__ bf16  g_attnout[MROWS * CDIM];
__device__ float g_x2[MROWS * CDIM];
__device__ bf16  g_fc1[MROWS * 512];
__device__ int   g_rolled[156];
__device__ float g_btab[HEADS * WA * NPAD];     // precomputed attention bias
__device__ bf16  g_wqkv[384 * 128];             // bf16 weights
__device__ bf16  g_wproj[128 * 128];
__device__ bf16  g_wfc1[512 * 128];
__device__ bf16  g_wfc2[128 * 512];

__constant__ int c_sh[4] = {-3,-3, 3, 3};
__constant__ int c_sw[4] = {-3, 3,-3, 3};

// -------------------------- helpers -----------------------------------------
__device__ __forceinline__ uint32_t pack_bf2(float x, float y) {
    __nv_bfloat162 p = __floats2bfloat162_rn(x, y);
    return *reinterpret_cast<uint32_t*>(&p);
}

__device__ __forceinline__ void mma_bf16(float c[4], const uint32_t a[4],
                                         const uint32_t b[2]) {
    asm volatile(
        "mma.sync.aligned.m16n8k16.row.col.f32.bf16.bf16.f32 "
        "{%0,%1,%2,%3},{%4,%5,%6,%7},{%8,%9},{%0,%1,%2,%3};"
        : "+f"(c[0]), "+f"(c[1]), "+f"(c[2]), "+f"(c[3])
        : "r"(a[0]), "r"(a[1]), "r"(a[2]), "r"(a[3]), "r"(b[0]), "r"(b[1]));
}

__device__ __forceinline__ void ldsm_x4(uint32_t r[4], uint32_t saddr) {
    asm volatile("ldmatrix.sync.aligned.m8n8.x4.shared.b16 {%0,%1,%2,%3}, [%4];"
        : "=r"(r[0]), "=r"(r[1]), "=r"(r[2]), "=r"(r[3]) : "r"(saddr));
}
__device__ __forceinline__ void ldsm_x2(uint32_t r[2], uint32_t saddr) {
    asm volatile("ldmatrix.sync.aligned.m8n8.x2.shared.b16 {%0,%1}, [%2];"
        : "=r"(r[0]), "=r"(r[1]) : "r"(saddr));
}
__device__ __forceinline__ uint32_t smem_u32(const void* p) {
    return (uint32_t)__cvta_generic_to_shared(p);
}
__device__ __forceinline__ void cp16(uint32_t dst, const void* src) {
    asm volatile("cp.async.cg.shared.global [%0], [%1], 16;" :: "r"(dst), "l"(src));
}
#define CP_COMMIT() asm volatile("cp.async.commit_group;")
#define CP_WAIT1()  asm volatile("cp.async.wait_group 1;" ::: "memory")

// -------------------------- one-shot init kernels ----------------------------
__global__ void init_rolled_kernel() {
    if (threadIdx.x == 0 && blockIdx.x == 0) {
        int cnt = 0;
        for (int idx = 0; idx < 256; idx++) {
            int m = idx >> 6, r = (idx >> 3) & 7, c = idx & 7;
            bool valid;
            if      (m == 0) valid = (r >= 5) || (c >= 5);
            else if (m == 1) valid = (r >= 5) || (c < 3);
            else if (m == 2) valid = (r < 3)  || (c >= 5);
            else             valid = (r < 3)  || (c < 3);
            if (valid) g_rolled[cnt++] = idx;
        }
    }
}

__global__ void init_btab_kernel(const float* __restrict__ rpbt,
                                 const float* __restrict__ rpbn,
                                 const float* __restrict__ rpbw) {
    int h = blockIdx.x, q = blockIdx.y;
    int k = threadIdx.x;            // 256
    float v = 0.f;
    int qr = q >> 3, qc = q & 7;
    if (k < 64) {
        int kr = k >> 3, kc = k & 7;
        v = rpbt[((qr - kr + 7) * 15 + (qc - kc + 7)) * HEADS + h];
    } else if (k < NROLL) {
        v = rpbn[(size_t)(h * 64 + q) * 156 + (k - 64)];
    } else if (k < NALL) {
        int p = k - NROLL;
        int kr = p / 3, kc = p % 3;
        v = rpbw[h * 100 + (qr - kr + 2) * 10 + (qc - kc + 2)];
    }
    g_btab[(h * 64 + q) * NPAD + k] = v;
}

__global__ void __launch_bounds__(256) cvt_w_kernel(
    const float* __restrict__ w, bf16* __restrict__ o, int n) {
    int i = (blockIdx.x * 256 + threadIdx.x) * 4;
    if (i < n) {
        float4 v = *(const float4*)&w[i];
        uint2 p;
        p.x = pack_bf2(v.x, v.y);
        p.y = pack_bf2(v.z, v.w);
        *(uint2*)&o[i] = p;
    }
}

// -------------------------- layernorm (fp32 in -> bf16 out) ------------------
__global__ void __launch_bounds__(256) ln_kernel(
    const float* __restrict__ x, const float* __restrict__ g,
    const float* __restrict__ b, bf16* __restrict__ out, int rows)
{
    int row = (blockIdx.x * blockDim.x + threadIdx.x) >> 5;
    if (row >= rows) return;
    int lane = threadIdx.x & 31;
    const float4* xr = (const float4*)(x + (size_t)row * CDIM);
    float4 v = xr[lane];
    float s = v.x + v.y + v.z + v.w;
    #pragma unroll
    for (int o = 16; o > 0; o >>= 1) s += __shfl_xor_sync(~0u, s, o);
    float mu = s * (1.0f / CDIM);
    float dx = v.x-mu, dy = v.y-mu, dz = v.z-mu, dw = v.w-mu;
    float s2 = dx*dx + dy*dy + dz*dz + dw*dw;
    #pragma unroll
    for (int o = 16; o > 0; o >>= 1) s2 += __shfl_xor_sync(~0u, s2, o);
    float rs = rsqrtf(s2 * (1.0f / CDIM) + 1e-5f);
    float4 gg = ((const float4*)g)[lane];
    float4 bb = ((const float4*)b)[lane];
    uint2 o2;
    o2.x = pack_bf2(dx*rs*gg.x + bb.x, dy*rs*gg.y + bb.y);
    o2.y = pack_bf2(dz*rs*gg.z + bb.z, dw*rs*gg.w + bb.w);
    ((uint2*)(out + (size_t)row * CDIM))[lane] = o2;
}

// -------------------------- bf16 GEMM (cp.async 2-stage pipeline) ------------
// A:(M,K) bf16 rm, W:(N,K) bf16 rm. Block 128x128x32, 16 warps, warp 32x32.
// epi: 0 = bf16 out, 1 = gelu -> bf16 out, 2 = +res(fp32) -> fp32 out
__global__ void __launch_bounds__(512, 2) gemm_tc(
    const bf16* __restrict__ A, const bf16* __restrict__ W,
    const float* __restrict__ bias, const float* __restrict__ res,
    void* __restrict__ outv, int M, int N, int K, int epi)
{
    __shared__ uint32_t As[2][128][20];   // rows of 32 bf16 (16 u32), pad 20
    __shared__ uint32_t Ws[2][128][20];
    int tid = threadIdx.x, lane = tid & 31, warp = tid >> 5;
    int wm = warp >> 2, wn = warp & 3;
    int grp = lane >> 2, tig = lane & 3;
    int m0 = blockIdx.y * 128, n0 = blockIdx.x * 128;

    uint32_t sA = smem_u32(&As[0][0][0]);
    uint32_t sW = smem_u32(&Ws[0][0][0]);
    const int STG = 128 * 20 * 4;         // 10240 B per stage

    int lr = tid >> 2, lc8 = (tid & 3) * 8;

    auto issue = [&](int s, int k0) {
        cp16(sA + s * STG + (lr * 20 + (lc8 >> 1)) * 4,
             A + (size_t)(m0 + lr) * K + k0 + lc8);
        cp16(sW + s * STG + (lr * 20 + (lc8 >> 1)) * 4,
             W + (size_t)(n0 + lr) * K + k0 + lc8);
    };

    // ldmatrix per-lane base addresses (stage 0)
    uint32_t aA0 = smem_u32(&As[0][wm * 32 + (lane & 15)][(lane >> 4) * 4]);
    uint32_t aA1 = aA0 + 16 * 80;
    int brow = ((lane >> 4) << 3) + (lane & 7), bcol = ((lane >> 3) & 1) * 4;
    uint32_t aB0 = smem_u32(&Ws[0][wn * 32 + brow][bcol]);
    uint32_t aB1 = aB0 + 16 * 80;

    float c[2][4][4];
    #pragma unroll
    for (int mt = 0; mt < 2; mt++)
        #pragma unroll
        for (int nt = 0; nt < 4; nt++)
            #pragma unroll
            for (int j = 0; j < 4; j++) c[mt][nt][j] = 0.f;

    int niter = K >> 5;
    issue(0, 0);
    CP_COMMIT();
    for (int it = 0; it < niter; it++) {
        int s = it & 1;
        if (it + 1 < niter) issue(s ^ 1, (it + 1) * 32);
        CP_COMMIT();
        CP_WAIT1();
        __syncthreads();
        uint32_t off = s * STG;
        #pragma unroll
        for (int ks = 0; ks < 2; ks++) {
            uint32_t boff = ks * 32;
            uint32_t a0[4], a1[4], b0[4], b1[4];
            ldsm_x4(a0, aA0 + off + boff);
            ldsm_x4(a1, aA1 + off + boff);
            ldsm_x4(b0, aB0 + off + boff);
            ldsm_x4(b1, aB1 + off + boff);
            uint32_t bf0[2] = {b0[0], b0[1]}, bf1[2] = {b0[2], b0[3]};
            uint32_t bf2[2] = {b1[0], b1[1]}, bf3[2] = {b1[2], b1[3]};
            mma_bf16(c[0][0], a0, bf0); mma_bf16(c[0][1], a0, bf1);
            mma_bf16(c[0][2], a0, bf2); mma_bf16(c[0][3], a0, bf3);
            mma_bf16(c[1][0], a1, bf0); mma_bf16(c[1][1], a1, bf1);
            mma_bf16(c[1][2], a1, bf2); mma_bf16(c[1][3], a1, bf3);
        }
        __syncthreads();
    }

    #pragma unroll
    for (int mt = 0; mt < 2; mt++) {
        int r0 = m0 + wm * 32 + mt * 16 + grp;
        #pragma unroll
        for (int nt = 0; nt < 4; nt++) {
            int cn = n0 + wn * 32 + nt * 8 + tig * 2;
            float2 bp = *(const float2*)&bias[cn];
            #pragma unroll
            for (int half = 0; half < 2; half++) {
                int row = r0 + half * 8;
                float v0 = c[mt][nt][half * 2 + 0] + bp.x;
                float v1 = c[mt][nt][half * 2 + 1] + bp.y;
                if (epi == 1) {
                    v0 = 0.5f * v0 * (1.0f + erff(v0 * 0.70710678118654752f));
                    v1 = 0.5f * v1 * (1.0f + erff(v1 * 0.70710678118654752f));
                }
                if (epi == 2) {
                    float2 rr = *(const float2*)&res[(size_t)row * N + cn];
                    *(float2*)&((float*)outv)[(size_t)row * N + cn] =
                        make_float2(v0 + rr.x, v1 + rr.y);
                } else {
                    ((uint32_t*)outv)[((size_t)row * N + cn) >> 1] = pack_bf2(v0, v1);
                }
            }
        }
    }
}

// -------------------------- window pooling (bf16 in/out) ---------------------
__global__ void __launch_bounds__(128) pool_kernel(
    const bf16* __restrict__ xh, const float* __restrict__ pw,
    const float* __restrict__ pb, bf16* __restrict__ pooled)
{
    int w = blockIdx.x;
    int b = w >> 10, ij = w & 1023;
    int i = ij >> 5, j = ij & 31;
    int c = threadIdx.x;
    float acc = 0.f;
    #pragma unroll
    for (int n = 0; n < 64; n++) {
        int r = n >> 3, cc = n & 7;
        size_t tok = (size_t)(b * HW + (i * 8 + r) * 256 + (j * 8 + cc));
        acc += __bfloat162float(xh[tok * CDIM + c]) * pw[n];
    }
    pooled[(size_t)w * CDIM + c] = __float2bfloat16(acc + pb[0]);
}

// -------------------------- attention (register softmax) ---------------------
// grid (2048, 4), 512 threads (16 warps), 2 CTAs/SM
// smem: sQ[64][20]u32 | sK[256][20]u32 | sVt[32][264]bf16 | sP[64][264]bf16
//       | sRedM[4][64]f32 | sRedS[4][64]f32   = 78336 B
__global__ void __launch_bounds__(512, 2) attn_kernel(
    const bf16* __restrict__ qkv, const bf16* __restrict__ qkvp,
    bf16* __restrict__ out)
{
    extern __shared__ char smraw[];
    uint32_t* sQ    = (uint32_t*)smraw;                     // 5120
    uint32_t* sK    = (uint32_t*)(smraw + 5120);            // 20480
    bf16*     sVt   = (bf16*)(smraw + 25600);               // 16896
    bf16*     sP    = (bf16*)(smraw + 42496);               // 33792
    float*    sRedM = (float*)(smraw + 76288);              // 1024
    float*    sRedS = (float*)(smraw + 77312);              // 1024

    int tid = threadIdx.x, lane = tid & 31, warp = tid >> 5;
    int grp = lane >> 2, tig = lane & 3;
    int w = blockIdx.x, h = blockIdx.y;
    int b = w >> 10, wi = (w >> 5) & 31, wj = w & 31;
    int bt = b << 16;
    int wm = warp >> 2, ng = warp & 3;

    // ---- load Q: sQ[q][d], rows of 32 bf16 pad 40 (20 u32) ----
    {
        int q = tid >> 3, d4 = (tid & 7) * 4;
        int gi = wi * 8 + (q >> 3), gj = wj * 8 + (q & 7);
        uint2 v = *(const uint2*)&qkv[(size_t)(bt + gi * 256 + gj) * 384 + h * 32 + d4];
        *(uint2*)&sQ[q * 20 + (d4 >> 1)] = v;
    }
    // ---- gather K (sK[kpos][d]) and V^T (sVt[d][kpos]); pads zero ----
    #pragma unroll
    for (int it = 0; it < 4; it++) {
        int idx = tid + it * 512;
        int krow = idx >> 3, d4 = (idx & 7) * 4;
        uint2 kv = make_uint2(0u, 0u), vv = kv;
        if (krow < NROLL) {
            int gi, gj;
            if (krow < 64) {
                gi = wi * 8 + (krow >> 3);
                gj = wj * 8 + (krow & 7);
            } else {
                int raw = g_rolled[krow - 64];
                int m = raw >> 6, r = (raw >> 3) & 7, c = raw & 7;
                gi = (wi * 8 + r - c_sh[m]) & 255;
                gj = (wj * 8 + c - c_sw[m]) & 255;
            }
            size_t base = (size_t)(bt + gi * 256 + gj) * 384 + 128 + h * 32 + d4;
            kv = *(const uint2*)&qkv[base];
            vv = *(const uint2*)&qkv[base + 128];
        } else if (krow < NALL) {
            int p = krow - NROLL;
            int pi = wi + p / 3 - 1, pj = wj + p % 3 - 1;
            if (pi >= 0 && pi < 32 && pj >= 0 && pj < 32) {
                size_t base = (size_t)((b << 10) + pi * 32 + pj) * 384 + 128 + h * 32 + d4;
                kv = *(const uint2*)&qkvp[base];
                vv = *(const uint2*)&qkvp[base + 128];
            }
        }
        *(uint2*)&sK[krow * 20 + (d4 >> 1)] = kv;
        __nv_bfloat162 v0 = *reinterpret_cast<__nv_bfloat162*>(&vv.x);
        __nv_bfloat162 v1 = *reinterpret_cast<__nv_bfloat162*>(&vv.y);
        sVt[(d4 + 0) * 264 + krow] = v0.x;
        sVt[(d4 + 1) * 264 + krow] = v0.y;
        sVt[(d4 + 2) * 264 + krow] = v1.x;
        sVt[(d4 + 3) * 264 + krow] = v1.y;
    }
    __syncthreads();

    float inv0, inv1;                     // carried into PV phase
    int r0 = wm * 16 + grp;

    // ---- QK^T + bias (registers) + cross-warp softmax ----
    {
        uint32_t aQ = smem_u32(&sQ[(wm * 16 + (lane & 15)) * 20 + (lane >> 4) * 4]);
        int brow = ((lane >> 4) << 3) + (lane & 7), bcol = ((lane >> 3) & 1) * 4;
        uint32_t aK[4];
        #pragma unroll
        for (int p = 0; p < 4; p++)
            aK[p] = smem_u32(&sK[(ng * 64 + p * 16 + brow) * 20 + bcol]);

        float c[8][4];
        #pragma unroll
        for (int nt = 0; nt < 8; nt++)
            #pragma unroll
            for (int j = 0; j < 4; j++) c[nt][j] = 0.f;
        #pragma unroll
        for (int ks = 0; ks < 2; ks++) {
            uint32_t boff = ks * 32;
            uint32_t a[4], bfr[8][2];
            ldsm_x4(a, aQ + boff);
            #pragma unroll
            for (int p = 0; p < 4; p++) {
                uint32_t r4[4];
                ldsm_x4(r4, aK[p] + boff);
                bfr[2*p  ][0] = r4[0]; bfr[2*p  ][1] = r4[1];
                bfr[2*p+1][0] = r4[2]; bfr[2*p+1][1] = r4[3];
            }
            #pragma unroll
            for (int nt = 0; nt < 8; nt++)
                mma_bf16(c[nt], a, bfr[nt]);
        }

        // bias + pooled-mask fixup; pads -> -1e30 (exp -> exactly 0)
        const float* tabh = &g_btab[(h * 64) * NPAD];
        #pragma unroll
        for (int nt = 0; nt < 8; nt++) {
            int cn = ng * 64 + nt * 8 + tig * 2;
            #pragma unroll
            for (int half = 0; half < 2; half++) {
                int row = r0 + half * 8;
                float2 tv = *(const float2*)&tabh[row * NPAD + cn];
                float v0 = c[nt][half * 2 + 0] * SCALE + tv.x;
                float v1 = c[nt][half * 2 + 1] * SCALE + tv.y;
                if (cn + 1 >= NROLL) {
                    #pragma unroll
                    for (int e = 0; e < 2; e++) {
                        int k = cn + e;
                        float* vp = e ? &v1 : &v0;
                        if (k >= NALL) { *vp = -1e30f; }
                        else if (k >= NROLL) {
                            int p = k - NROLL;
                            int kr = p / 3, kc = p % 3;
                            int pi = wi + kr - 1, pj = wj + kc - 1;
                            if (!(pi >= 0 && pi < 32 && pj >= 0 && pj < 32))
                                *vp -= 100.f;
                        }
                    }
                }
                c[nt][half * 2 + 0] = v0;
                c[nt][half * 2 + 1] = v1;
            }
        }

        // row max: per-lane over 16 vals, shfl over tig, cross-warp via smem
        float m0 = -1e30f, m1 = -1e30f;
        #pragma unroll
        for (int nt = 0; nt < 8; nt++) {
            m0 = fmaxf(m0, fmaxf(c[nt][0], c[nt][1]));
            m1 = fmaxf(m1, fmaxf(c[nt][2], c[nt][3]));
        }
        m0 = fmaxf(m0, __shfl_xor_sync(~0u, m0, 1));
        m0 = fmaxf(m0, __shfl_xor_sync(~0u, m0, 2));
        m1 = fmaxf(m1, __shfl_xor_sync(~0u, m1, 1));
        m1 = fmaxf(m1, __shfl_xor_sync(~0u, m1, 2));
        if (tig == 0) {
            sRedM[ng * 64 + r0]     = m0;
            sRedM[ng * 64 + r0 + 8] = m1;
        }
        __syncthreads();
        float M0 = fmaxf(fmaxf(sRedM[r0], sRedM[64 + r0]),
                         fmaxf(sRedM[128 + r0], sRedM[192 + r0]));
        float M1 = fmaxf(fmaxf(sRedM[r0 + 8], sRedM[64 + r0 + 8]),
                         fmaxf(sRedM[128 + r0 + 8], sRedM[192 + r0 + 8]));

        // exp + partial sums + write P (bf16)
        uint32_t* sP32 = (uint32_t*)sP;
        float s0 = 0.f, s1 = 0.f;
        #pragma unroll
        for (int nt = 0; nt < 8; nt++) {
            float e00 = __expf(c[nt][0] - M0);
            float e01 = __expf(c[nt][1] - M0);
            float e10 = __expf(c[nt][2] - M1);
            float e11 = __expf(c[nt][3] - M1);
            s0 += e00 + e01;
            s1 += e10 + e11;
            int ci = ng * 32 + nt * 4 + tig;
            sP32[r0 * 132 + ci]       = pack_bf2(e00, e01);
            sP32[(r0 + 8) * 132 + ci] = pack_bf2(e10, e11);
        }
        s0 += __shfl_xor_sync(~0u, s0, 1);
        s0 += __shfl_xor_sync(~0u, s0, 2);
        s1 += __shfl_xor_sync(~0u, s1, 1);
        s1 += __shfl_xor_sync(~0u, s1, 2);
        if (tig == 0) {
            sRedS[ng * 64 + r0]     = s0;
            sRedS[ng * 64 + r0 + 8] = s1;
        }
        __syncthreads();
        inv0 = 1.0f / (sRedS[r0] + sRedS[64 + r0] +
                       sRedS[128 + r0] + sRedS[192 + r0]);
        inv1 = 1.0f / (sRedS[r0 + 8] + sRedS[64 + r0 + 8] +
                       sRedS[128 + r0 + 8] + sRedS[192 + r0 + 8]);
    }

    // ---- P @ V (bf16 mma): warp = (wm mtile, wn=ng group of 8 dims) ----
    {
        int wn = ng;
        uint32_t aP = smem_u32(&((uint32_t*)sP)[(wm * 16 + (lane & 15)) * 132 + (lane >> 4) * 4]);
        int l2 = lane & 15;
        uint32_t aV = smem_u32(&((uint32_t*)sVt)[(wn * 8 + (l2 & 7)) * 132 + ((l2 >> 3) & 1) * 4]);

        float c[4] = {0.f, 0.f, 0.f, 0.f};
        #pragma unroll 4
        for (int kk = 0; kk < NPAD; kk += 16) {
            uint32_t boff = (kk >> 1) * 4;
            uint32_t a[4], bfr[2];
            ldsm_x4(a, aP + boff);
            ldsm_x2(bfr, aV + boff);
            mma_bf16(c, a, bfr);
        }
        int d0 = wn * 8 + tig * 2;
        #pragma unroll
        for (int half = 0; half < 2; half++) {
            int row = r0 + half * 8;
            float inv = half ? inv1 : inv0;
            int gi = wi * 8 + (row >> 3), gj = wj * 8 + (row & 7);
            uint32_t* o = (uint32_t*)&out[(size_t)(bt + gi * 256 + gj) * CDIM + h * 32 + d0];
            *o = pack_bf2(c[half * 2 + 0] * inv, c[half * 2 + 1] * inv);
        }
    }
}

// ----------------------------------------------------------------------------
extern "C" void kernel_launch(void* const* d_in, const int* in_sizes, int n_in,
                              void* d_out, int out_size)
{
    const float* x      = (const float*)d_in[0];
    const float* qkv_w  = (const float*)d_in[1];
    const float* qkv_b  = (const float*)d_in[2];
    const float* proj_w = (const float*)d_in[3];
    const float* proj_b = (const float*)d_in[4];
    const float* n1g    = (const float*)d_in[5];
    const float* n1b    = (const float*)d_in[6];
    const float* n2g    = (const float*)d_in[7];
    const float* n2b    = (const float*)d_in[8];
    const float* rpbt   = (const float*)d_in[9];
    const float* rpbn   = (const float*)d_in[10];
    const float* rpbw   = (const float*)d_in[11];
    const float* poolw  = (const float*)d_in[12];
    const float* poolb  = (const float*)d_in[13];
    const float* fc1_w  = (const float*)d_in[14];
    const float* fc1_b  = (const float*)d_in[15];
    const float* fc2_w  = (const float*)d_in[16];
    const float* fc2_b  = (const float*)d_in[17];
    float* outp = (float*)d_out;

    bf16 *p_xh, *p_qkv, *p_pooled, *p_qkvp, *p_attnout, *p_fc1;
    bf16 *p_wqkv, *p_wproj, *p_wfc1, *p_wfc2;
    float *p_x2;
    cudaGetSymbolAddress((void**)&p_xh, g_xh);
    cudaGetSymbolAddress((void**)&p_qkv, g_qkv);
    cudaGetSymbolAddress((void**)&p_pooled, g_pooled);
    cudaGetSymbolAddress((void**)&p_qkvp, g_qkvp);
    cudaGetSymbolAddress((void**)&p_attnout, g_attnout);
    cudaGetSymbolAddress((void**)&p_x2, g_x2);
    cudaGetSymbolAddress((void**)&p_fc1, g_fc1);
    cudaGetSymbolAddress((void**)&p_wqkv, g_wqkv);
    cudaGetSymbolAddress((void**)&p_wproj, g_wproj);
    cudaGetSymbolAddress((void**)&p_wfc1, g_wfc1);
    cudaGetSymbolAddress((void**)&p_wfc2, g_wfc2);

    const int ATTN_SMEM = 78336;
    cudaFuncSetAttribute(attn_kernel,
                         cudaFuncAttributeMaxDynamicSharedMemorySize, ATTN_SMEM);

    // 0. one-shot tables + weight conversion
    init_rolled_kernel<<<1, 1>>>();
    init_btab_kernel<<<dim3(HEADS, WA), 256>>>(rpbt, rpbn, rpbw);
    cvt_w_kernel<<<48, 256>>>(qkv_w,  p_wqkv, 384 * 128);
    cvt_w_kernel<<<16, 256>>>(proj_w, p_wproj, 128 * 128);
    cvt_w_kernel<<<64, 256>>>(fc1_w,  p_wfc1, 512 * 128);
    cvt_w_kernel<<<64, 256>>>(fc2_w,  p_wfc2, 128 * 512);
    // 1. LN1 -> bf16 xh
    ln_kernel<<<MROWS / 8, 256>>>(x, n1g, n1b, p_xh, MROWS);
    // 2. qkv GEMM  (131072 x 384, K=128) -> bf16
    gemm_tc<<<dim3(384 / 128, MROWS / 128), 512>>>(
        p_xh, p_wqkv, qkv_b, nullptr, p_qkv, MROWS, 384, 128, 0);
    // 3. window pooling
    pool_kernel<<<BATCH * NWIN, 128>>>(p_xh, poolw, poolb, p_pooled);
    // 4. qkv of pooled (2048 x 384, K=128) -> bf16
    gemm_tc<<<dim3(384 / 128, (BATCH * NWIN) / 128), 512>>>(
        p_pooled, p_wqkv, qkv_b, nullptr, p_qkvp, BATCH * NWIN, 384, 128, 0);
    // 5. focal attention (bf16 mma, register softmax) -> bf16 attnout
    attn_kernel<<<dim3(BATCH * NWIN, HEADS), 512, ATTN_SMEM>>>(
        p_qkv, p_qkvp, p_attnout);
    // 6. proj + residual(x) -> fp32 x2
    gemm_tc<<<dim3(CDIM / 128, MROWS / 128), 512>>>(
        p_attnout, p_wproj, proj_b, x, p_x2, MROWS, CDIM, 128, 2);
    // 7. LN2 -> bf16 xh
    ln_kernel<<<MROWS / 8, 256>>>(p_x2, n2g, n2b, p_xh, MROWS);
    // 8. fc1 + exact GELU (131072 x 512, K=128) -> bf16
    gemm_tc<<<dim3(512 / 128, MROWS / 128), 512>>>(
        p_xh, p_wfc1, fc1_b, nullptr, p_fc1, MROWS, 512, 128, 1);
    // 9. fc2 + residual(x2) -> fp32 out (131072 x 128, K=512)
    gemm_tc<<<dim3(CDIM / 128, MROWS / 128), 512>>>(
        p_fc1, p_wfc2, fc2_b, p_x2, outp, MROWS, CDIM, 512, 2);
}

// round 12
// speedup vs baseline: 1.7364x; 1.0329x over previous
#include <cuda_runtime.h>
#include <cuda_bf16.h>
#include <cstdint>
#include <cstddef>

// ----------------------------------------------------------------------------
// FocalTransformerBlock  B=2, H=W=256, C=128, HEADS=4, HD=32, WS=8, EXP=3
// bf16 mma.m16n8k16 + ldmatrix + cp.async; LN2 fused into proj epilogue
// ----------------------------------------------------------------------------

#define BATCH   2
#define HW      65536
#define CDIM    128
#define MROWS   (BATCH*HW)      // 131072
#define NWH     32
#define NWIN    1024
#define WA      64
#define NROLL   220
#define NALL    229
#define NPAD    256
#define HEADS   4
#define HD      32
#define SCALE   0.17677669529663687f

typedef __nv_bfloat16 bf16;

// -------------------------- scratch (static device) -------------------------
__device__ bf16  g_xh[MROWS * CDIM];
__device__ bf16  g_qkv[MROWS * 3 * CDIM];
__device__ bf16  g_pooled[BATCH * NWIN * CDIM];
__device__ bf16  g_qkvp[BATCH * NWIN * 3 * CDIM];
__device__ bf16  g_attnout[MROWS * CDIM];
__device__ float g_x2[MROWS * CDIM];
__device__ bf16  g_fc1[MROWS * 512];
__device__ int   g_rolled[156];
__device__ float g_btab[HEADS * WA * NPAD];
__device__ bf16  g_wqkv[384 * 128];
__device__ bf16  g_wproj[128 * 128];
__device__ bf16  g_wfc1[512 * 128];
__device__ bf16  g_wfc2[128 * 512];

__constant__ int c_sh[4] = {-3,-3, 3, 3};
__constant__ int c_sw[4] = {-3, 3,-3, 3};

// -------------------------- helpers -----------------------------------------
__device__ __forceinline__ uint32_t pack_bf2(float x, float y) {
    __nv_bfloat162 p = __floats2bfloat162_rn(x, y);
    return *reinterpret_cast<uint32_t*>(&p);
}

__device__ __forceinline__ void mma_bf16(float c[4], const uint32_t a[4],
                                         const uint32_t b[2]) {
    asm volatile(
        "mma.sync.aligned.m16n8k16.row.col.f32.bf16.bf16.f32 "
        "{%0,%1,%2,%3},{%4,%5,%6,%7},{%8,%9},{%0,%1,%2,%3};"
        : "+f"(c[0]), "+f"(c[1]), "+f"(c[2]), "+f"(c[3])
        : "r"(a[0]), "r"(a[1]), "r"(a[2]), "r"(a[3]), "r"(b[0]), "r"(b[1]));
}

__device__ __forceinline__ void ldsm_x4(uint32_t r[4], uint32_t saddr) {
    asm volatile("ldmatrix.sync.aligned.m8n8.x4.shared.b16 {%0,%1,%2,%3}, [%4];"
        : "=r"(r[0]), "=r"(r[1]), "=r"(r[2]), "=r"(r[3]) : "r"(saddr));
}
__device__ __forceinline__ void ldsm_x2_trans(uint32_t r[2], uint32_t saddr) {
    asm volatile("ldmatrix.sync.aligned.m8n8.x2.trans.shared.b16 {%0,%1}, [%2];"
        : "=r"(r[0]), "=r"(r[1]) : "r"(saddr));
}
__device__ __forceinline__ uint32_t smem_u32(const void* p) {
    return (uint32_t)__cvta_generic_to_shared(p);
}
__device__ __forceinline__ void cp16(uint32_t dst, const void* src) {
    asm volatile("cp.async.cg.shared.global [%0], [%1], 16;" :: "r"(dst), "l"(src));
}
#define CP_COMMIT() asm volatile("cp.async.commit_group;")
#define CP_WAIT1()  asm volatile("cp.async.wait_group 1;" ::: "memory")

// -------------------------- one-shot init kernels ----------------------------
__global__ void init_rolled_kernel() {
    if (threadIdx.x == 0 && blockIdx.x == 0) {
        int cnt = 0;
        for (int idx = 0; idx < 256; idx++) {
            int m = idx >> 6, r = (idx >> 3) & 7, c = idx & 7;
            bool valid;
            if      (m == 0) valid = (r >= 5) || (c >= 5);
            else if (m == 1) valid = (r >= 5) || (c < 3);
            else if (m == 2) valid = (r < 3)  || (c >= 5);
            else             valid = (r < 3)  || (c < 3);
            if (valid) g_rolled[cnt++] = idx;
        }
    }
}

__global__ void init_btab_kernel(const float* __restrict__ rpbt,
                                 const float* __restrict__ rpbn,
                                 const float* __restrict__ rpbw) {
    int h = blockIdx.x, q = blockIdx.y;
    int k = threadIdx.x;            // 256
    float v = 0.f;
    int qr = q >> 3, qc = q & 7;
    if (k < 64) {
        int kr = k >> 3, kc = k & 7;
        v = rpbt[((qr - kr + 7) * 15 + (qc - kc + 7)) * HEADS + h];
    } else if (k < NROLL) {
        v = rpbn[(size_t)(h * 64 + q) * 156 + (k - 64)];
    } else if (k < NALL) {
        int p = k - NROLL;
        int kr = p / 3, kc = p % 3;
        v = rpbw[h * 100 + (qr - kr + 2) * 10 + (qc - kc + 2)];
    }
    g_btab[(h * 64 + q) * NPAD + k] = v;
}

__global__ void __launch_bounds__(256) cvt_w_kernel(
    const float* __restrict__ w, bf16* __restrict__ o, int n) {
    int i = (blockIdx.x * 256 + threadIdx.x) * 4;
    if (i < n) {
        float4 v = *(const float4*)&w[i];
        uint2 p;
        p.x = pack_bf2(v.x, v.y);
        p.y = pack_bf2(v.z, v.w);
        *(uint2*)&o[i] = p;
    }
}

// -------------------------- layernorm (fp32 in -> bf16 out) ------------------
__global__ void __launch_bounds__(256) ln_kernel(
    const float* __restrict__ x, const float* __restrict__ g,
    const float* __restrict__ b, bf16* __restrict__ out, int rows)
{
    int row = (blockIdx.x * blockDim.x + threadIdx.x) >> 5;
    if (row >= rows) return;
    int lane = threadIdx.x & 31;
    const float4* xr = (const float4*)(x + (size_t)row * CDIM);
    float4 v = xr[lane];
    float s = v.x + v.y + v.z + v.w;
    #pragma unroll
    for (int o = 16; o > 0; o >>= 1) s += __shfl_xor_sync(~0u, s, o);
    float mu = s * (1.0f / CDIM);
    float dx = v.x-mu, dy = v.y-mu, dz = v.z-mu, dw = v.w-mu;
    float s2 = dx*dx + dy*dy + dz*dz + dw*dw;
    #pragma unroll
    for (int o = 16; o > 0; o >>= 1) s2 += __shfl_xor_sync(~0u, s2, o);
    float rs = rsqrtf(s2 * (1.0f / CDIM) + 1e-5f);
    float4 gg = ((const float4*)g)[lane];
    float4 bb = ((const float4*)b)[lane];
    uint2 o2;
    o2.x = pack_bf2(dx*rs*gg.x + bb.x, dy*rs*gg.y + bb.y);
    o2.y = pack_bf2(dz*rs*gg.z + bb.z, dw*rs*gg.w + bb.w);
    ((uint2*)(out + (size_t)row * CDIM))[lane] = o2;
}

// -------------------------- bf16 GEMM (cp.async 2-stage pipeline) ------------
// A:(M,K) bf16 rm, W:(N,K) bf16 rm. Block 128x128x32, 16 warps, warp 32x32.
// epi: 0 = bf16 out, 1 = gelu->bf16, 2 = +res(fp32)->fp32,
//      3 = +res(fp32)->fp32 x2 AND fused LN -> bf16 xh_out  (requires N==128)
__global__ void __launch_bounds__(512, 2) gemm_tc(
    const bf16* __restrict__ A, const bf16* __restrict__ W,
    const float* __restrict__ bias, const float* __restrict__ res,
    void* __restrict__ outv, bf16* __restrict__ xh_out,
    const float* __restrict__ lng, const float* __restrict__ lnb,
    int M, int N, int K, int epi)
{
    __shared__ uint32_t As[2][128][20];   // rows of 32 bf16 (16 u32), pad 20
    __shared__ uint32_t Ws[2][128][20];
    __shared__ float sRedS[4 * 128];      // LN fused reductions (epi==3)
    __shared__ float sRedQ[4 * 128];
    int tid = threadIdx.x, lane = tid & 31, warp = tid >> 5;
    int wm = warp >> 2, wn = warp & 3;
    int grp = lane >> 2, tig = lane & 3;
    int m0 = blockIdx.y * 128, n0 = blockIdx.x * 128;

    uint32_t sA = smem_u32(&As[0][0][0]);
    uint32_t sW = smem_u32(&Ws[0][0][0]);
    const int STG = 128 * 20 * 4;         // 10240 B per stage

    int lr = tid >> 2, lc8 = (tid & 3) * 8;

    auto issue = [&](int s, int k0) {
        cp16(sA + s * STG + (lr * 20 + (lc8 >> 1)) * 4,
             A + (size_t)(m0 + lr) * K + k0 + lc8);
        cp16(sW + s * STG + (lr * 20 + (lc8 >> 1)) * 4,
             W + (size_t)(n0 + lr) * K + k0 + lc8);
    };

    uint32_t aA0 = smem_u32(&As[0][wm * 32 + (lane & 15)][(lane >> 4) * 4]);
    uint32_t aA1 = aA0 + 16 * 80;
    int brow = ((lane >> 4) << 3) + (lane & 7), bcol = ((lane >> 3) & 1) * 4;
    uint32_t aB0 = smem_u32(&Ws[0][wn * 32 + brow][bcol]);
    uint32_t aB1 = aB0 + 16 * 80;

    float c[2][4][4];
    #pragma unroll
    for (int mt = 0; mt < 2; mt++)
        #pragma unroll
        for (int nt = 0; nt < 4; nt++)
            #pragma unroll
            for (int j = 0; j < 4; j++) c[mt][nt][j] = 0.f;

    int niter = K >> 5;
    issue(0, 0);
    CP_COMMIT();
    for (int it = 0; it < niter; it++) {
        int s = it & 1;
        if (it + 1 < niter) issue(s ^ 1, (it + 1) * 32);
        CP_COMMIT();
        CP_WAIT1();
        __syncthreads();
        uint32_t off = s * STG;
        #pragma unroll
        for (int ks = 0; ks < 2; ks++) {
            uint32_t boff = ks * 32;
            uint32_t a0[4], a1[4], b0[4], b1[4];
            ldsm_x4(a0, aA0 + off + boff);
            ldsm_x4(a1, aA1 + off + boff);
            ldsm_x4(b0, aB0 + off + boff);
            ldsm_x4(b1, aB1 + off + boff);
            uint32_t bf0[2] = {b0[0], b0[1]}, bf1[2] = {b0[2], b0[3]};
            uint32_t bf2[2] = {b1[0], b1[1]}, bf3[2] = {b1[2], b1[3]};
            mma_bf16(c[0][0], a0, bf0); mma_bf16(c[0][1], a0, bf1);
            mma_bf16(c[0][2], a0, bf2); mma_bf16(c[0][3], a0, bf3);
            mma_bf16(c[1][0], a1, bf0); mma_bf16(c[1][1], a1, bf1);
            mma_bf16(c[1][2], a1, bf2); mma_bf16(c[1][3], a1, bf3);
        }
        __syncthreads();
    }

    if (epi == 3) {
        // proj + residual -> x2 (fp32), then fused LN -> xh_out (bf16). N==128.
        // 1) finalize values, write x2
        #pragma unroll
        for (int mt = 0; mt < 2; mt++) {
            #pragma unroll
            for (int nt = 0; nt < 4; nt++) {
                int cn = wn * 32 + nt * 8 + tig * 2;
                float2 bp = *(const float2*)&bias[cn];
                #pragma unroll
                for (int half = 0; half < 2; half++) {
                    int row = m0 + wm * 32 + mt * 16 + half * 8 + grp;
                    float v0 = c[mt][nt][half * 2 + 0] + bp.x;
                    float v1 = c[mt][nt][half * 2 + 1] + bp.y;
                    float2 rr = *(const float2*)&res[(size_t)row * 128 + cn];
                    v0 += rr.x; v1 += rr.y;
                    c[mt][nt][half * 2 + 0] = v0;
                    c[mt][nt][half * 2 + 1] = v1;
                    *(float2*)&((float*)outv)[(size_t)row * 128 + cn] =
                        make_float2(v0, v1);
                }
            }
        }
        // 2) per-row sum / sumsq partials (8 cols per thread-row within warp)
        #pragma unroll
        for (int mt = 0; mt < 2; mt++)
            #pragma unroll
            for (int half = 0; half < 2; half++) {
                int lrow = wm * 32 + mt * 16 + half * 8 + grp;
                float s = 0.f, q = 0.f;
                #pragma unroll
                for (int nt = 0; nt < 4; nt++) {
                    float v0 = c[mt][nt][half * 2 + 0];
                    float v1 = c[mt][nt][half * 2 + 1];
                    s += v0 + v1;
                    q += v0 * v0 + v1 * v1;
                }
                s += __shfl_xor_sync(~0u, s, 1);
                s += __shfl_xor_sync(~0u, s, 2);
                q += __shfl_xor_sync(~0u, q, 1);
                q += __shfl_xor_sync(~0u, q, 2);
                if (tig == 0) {
                    sRedS[wn * 128 + lrow] = s;
                    sRedQ[wn * 128 + lrow] = q;
                }
            }
        __syncthreads();
        // 3) normalize + write xh
        #pragma unroll
        for (int mt = 0; mt < 2; mt++)
            #pragma unroll
            for (int half = 0; half < 2; half++) {
                int lrow = wm * 32 + mt * 16 + half * 8 + grp;
                float S = sRedS[lrow] + sRedS[128 + lrow] +
                          sRedS[256 + lrow] + sRedS[384 + lrow];
                float Q = sRedQ[lrow] + sRedQ[128 + lrow] +
                          sRedQ[256 + lrow] + sRedQ[384 + lrow];
                float mu = S * (1.0f / 128.0f);
                float var = Q * (1.0f / 128.0f) - mu * mu;
                float rs = rsqrtf(var + 1e-5f);
                int row = m0 + lrow;
                #pragma unroll
                for (int nt = 0; nt < 4; nt++) {
                    int cn = wn * 32 + nt * 8 + tig * 2;
                    float2 gg = *(const float2*)&lng[cn];
                    float2 bb = *(const float2*)&lnb[cn];
                    float v0 = (c[mt][nt][half * 2 + 0] - mu) * rs * gg.x + bb.x;
                    float v1 = (c[mt][nt][half * 2 + 1] - mu) * rs * gg.y + bb.y;
                    *(uint32_t*)&xh_out[(size_t)row * 128 + cn] = pack_bf2(v0, v1);
                }
            }
        return;
    }

    #pragma unroll
    for (int mt = 0; mt < 2; mt++) {
        int r0 = m0 + wm * 32 + mt * 16 + grp;
        #pragma unroll
        for (int nt = 0; nt < 4; nt++) {
            int cn = n0 + wn * 32 + nt * 8 + tig * 2;
            float2 bp = *(const float2*)&bias[cn];
            #pragma unroll
            for (int half = 0; half < 2; half++) {
                int row = r0 + half * 8;
                float v0 = c[mt][nt][half * 2 + 0] + bp.x;
                float v1 = c[mt][nt][half * 2 + 1] + bp.y;
                if (epi == 1) {
                    v0 = 0.5f * v0 * (1.0f + erff(v0 * 0.70710678118654752f));
                    v1 = 0.5f * v1 * (1.0f + erff(v1 * 0.70710678118654752f));
                }
                if (epi == 2) {
                    float2 rr = *(const float2*)&res[(size_t)row * N + cn];
                    *(float2*)&((float*)outv)[(size_t)row * N + cn] =
                        make_float2(v0 + rr.x, v1 + rr.y);
                } else {
                    ((uint32_t*)outv)[((size_t)row * N + cn) >> 1] = pack_bf2(v0, v1);
                }
            }
        }
    }
}

// -------------------------- window pooling (bf16 in/out) ---------------------
__global__ void __launch_bounds__(128) pool_kernel(
    const bf16* __restrict__ xh, const float* __restrict__ pw,
    const float* __restrict__ pb, bf16* __restrict__ pooled)
{
    int w = blockIdx.x;
    int b = w >> 10, ij = w & 1023;
    int i = ij >> 5, j = ij & 31;
    int c = threadIdx.x;
    float acc = 0.f;
    #pragma unroll
    for (int n = 0; n < 64; n++) {
        int r = n >> 3, cc = n & 7;
        size_t tok = (size_t)(b * HW + (i * 8 + r) * 256 + (j * 8 + cc));
        acc += __bfloat162float(xh[tok * CDIM + c]) * pw[n];
    }
    pooled[(size_t)w * CDIM + c] = __float2bfloat16(acc + pb[0]);
}

// -------------------------- attention (register softmax) ---------------------
// grid (2048, 4), 512 threads (16 warps), 2 CTAs/SM
// smem: sQ[64][20]u32 | sK[256][20]u32 | sV[256][20]u32 | sP[64][264]bf16
//       | sRedM[4][64] | sRedS[4][64]   = 81920 B
__global__ void __launch_bounds__(512, 2) attn_kernel(
    const bf16* __restrict__ qkv, const bf16* __restrict__ qkvp,
    bf16* __restrict__ out)
{
    extern __shared__ char smraw[];
    uint32_t* sQ    = (uint32_t*)smraw;                     // 5120
    uint32_t* sK    = (uint32_t*)(smraw + 5120);            // 20480
    uint32_t* sV    = (uint32_t*)(smraw + 25600);           // 20480
    bf16*     sP    = (bf16*)(smraw + 46080);               // 33792
    float*    sRedM = (float*)(smraw + 79872);              // 1024
    float*    sRedS = (float*)(smraw + 80896);              // 1024

    int tid = threadIdx.x, lane = tid & 31, warp = tid >> 5;
    int grp = lane >> 2, tig = lane & 3;
    int w = blockIdx.x, h = blockIdx.y;
    int b = w >> 10, wi = (w >> 5) & 31, wj = w & 31;
    int bt = b << 16;
    int wm = warp >> 2, ng = warp & 3;

    // ---- load Q: sQ[q][d], rows of 32 bf16 pad 40 (20 u32) ----
    {
        int q = tid >> 3, d4 = (tid & 7) * 4;
        int gi = wi * 8 + (q >> 3), gj = wj * 8 + (q & 7);
        uint2 v = *(const uint2*)&qkv[(size_t)(bt + gi * 256 + gj) * 384 + h * 32 + d4];
        *(uint2*)&sQ[q * 20 + (d4 >> 1)] = v;
    }
    // ---- gather K, V (both [kpos][d]); pads zero ----
    #pragma unroll
    for (int it = 0; it < 4; it++) {
        int idx = tid + it * 512;
        int krow = idx >> 3, d4 = (idx & 7) * 4;
        uint2 kv = make_uint2(0u, 0u), vv = kv;
        if (krow < NROLL) {
            int gi, gj;
            if (krow < 64) {
                gi = wi * 8 + (krow >> 3);
                gj = wj * 8 + (krow & 7);
            } else {
                int raw = g_rolled[krow - 64];
                int m = raw >> 6, r = (raw >> 3) & 7, c = raw & 7;
                gi = (wi * 8 + r - c_sh[m]) & 255;
                gj = (wj * 8 + c - c_sw[m]) & 255;
            }
            size_t base = (size_t)(bt + gi * 256 + gj) * 384 + 128 + h * 32 + d4;
            kv = *(const uint2*)&qkv[base];
            vv = *(const uint2*)&qkv[base + 128];
        } else if (krow < NALL) {
            int p = krow - NROLL;
            int pi = wi + p / 3 - 1, pj = wj + p % 3 - 1;
            if (pi >= 0 && pi < 32 && pj >= 0 && pj < 32) {
                size_t base = (size_t)((b << 10) + pi * 32 + pj) * 384 + 128 + h * 32 + d4;
                kv = *(const uint2*)&qkvp[base];
                vv = *(const uint2*)&qkvp[base + 128];
            }
        }
        *(uint2*)&sK[krow * 20 + (d4 >> 1)] = kv;
        *(uint2*)&sV[krow * 20 + (d4 >> 1)] = vv;
    }
    __syncthreads();

    float inv0, inv1;
    int r0 = wm * 16 + grp;

    // ---- QK^T + bias (registers) + cross-warp softmax ----
    {
        uint32_t aQ = smem_u32(&sQ[(wm * 16 + (lane & 15)) * 20 + (lane >> 4) * 4]);
        int brow = ((lane >> 4) << 3) + (lane & 7), bcol = ((lane >> 3) & 1) * 4;
        uint32_t aK[4];
        #pragma unroll
        for (int p = 0; p < 4; p++)
            aK[p] = smem_u32(&sK[(ng * 64 + p * 16 + brow) * 20 + bcol]);

        float c[8][4];
        #pragma unroll
        for (int nt = 0; nt < 8; nt++)
            #pragma unroll
            for (int j = 0; j < 4; j++) c[nt][j] = 0.f;
        #pragma unroll
        for (int ks = 0; ks < 2; ks++) {
            uint32_t boff = ks * 32;
            uint32_t a[4], bfr[8][2];
            ldsm_x4(a, aQ + boff);
            #pragma unroll
            for (int p = 0; p < 4; p++) {
                uint32_t r4[4];
                ldsm_x4(r4, aK[p] + boff);
                bfr[2*p  ][0] = r4[0]; bfr[2*p  ][1] = r4[1];
                bfr[2*p+1][0] = r4[2]; bfr[2*p+1][1] = r4[3];
            }
            #pragma unroll
            for (int nt = 0; nt < 8; nt++)
                mma_bf16(c[nt], a, bfr[nt]);
        }

        // bias + pooled-mask fixup; pads -> -1e30 (exp -> exactly 0)
        const float* tabh = &g_btab[(h * 64) * NPAD];
        #pragma unroll
        for (int nt = 0; nt < 8; nt++) {
            int cn = ng * 64 + nt * 8 + tig * 2;
            #pragma unroll
            for (int half = 0; half < 2; half++) {
                int row = r0 + half * 8;
                float2 tv = *(const float2*)&tabh[row * NPAD + cn];
                float v0 = c[nt][half * 2 + 0] * SCALE + tv.x;
                float v1 = c[nt][half * 2 + 1] * SCALE + tv.y;
                if (cn + 1 >= NROLL) {
                    #pragma unroll
                    for (int e = 0; e < 2; e++) {
                        int k = cn + e;
                        float* vp = e ? &v1 : &v0;
                        if (k >= NALL) { *vp = -1e30f; }
                        else if (k >= NROLL) {
                            int p = k - NROLL;
                            int kr = p / 3, kc = p % 3;
                            int pi = wi + kr - 1, pj = wj + kc - 1;
                            if (!(pi >= 0 && pi < 32 && pj >= 0 && pj < 32))
                                *vp -= 100.f;
                        }
                    }
                }
                c[nt][half * 2 + 0] = v0;
                c[nt][half * 2 + 1] = v1;
            }
        }

        float m0 = -1e30f, m1 = -1e30f;
        #pragma unroll
        for (int nt = 0; nt < 8; nt++) {
            m0 = fmaxf(m0, fmaxf(c[nt][0], c[nt][1]));
            m1 = fmaxf(m1, fmaxf(c[nt][2], c[nt][3]));
        }
        m0 = fmaxf(m0, __shfl_xor_sync(~0u, m0, 1));
        m0 = fmaxf(m0, __shfl_xor_sync(~0u, m0, 2));
        m1 = fmaxf(m1, __shfl_xor_sync(~0u, m1, 1));
        m1 = fmaxf(m1, __shfl_xor_sync(~0u, m1, 2));
        if (tig == 0) {
            sRedM[ng * 64 + r0]     = m0;
            sRedM[ng * 64 + r0 + 8] = m1;
        }
        __syncthreads();
        float M0 = fmaxf(fmaxf(sRedM[r0], sRedM[64 + r0]),
                         fmaxf(sRedM[128 + r0], sRedM[192 + r0]));
        float M1 = fmaxf(fmaxf(sRedM[r0 + 8], sRedM[64 + r0 + 8]),
                         fmaxf(sRedM[128 + r0 + 8], sRedM[192 + r0 + 8]));

        uint32_t* sP32 = (uint32_t*)sP;
        float s0 = 0.f, s1 = 0.f;
        #pragma unroll
        for (int nt = 0; nt < 8; nt++) {
            float e00 = __expf(c[nt][0] - M0);
            float e01 = __expf(c[nt][1] - M0);
            float e10 = __expf(c[nt][2] - M1);
            float e11 = __expf(c[nt][3] - M1);
            s0 += e00 + e01;
            s1 += e10 + e11;
            int ci = ng * 32 + nt * 4 + tig;
            sP32[r0 * 132 + ci]       = pack_bf2(e00, e01);
            sP32[(r0 + 8) * 132 + ci] = pack_bf2(e10, e11);
        }
        s0 += __shfl_xor_sync(~0u, s0, 1);
        s0 += __shfl_xor_sync(~0u, s0, 2);
        s1 += __shfl_xor_sync(~0u, s1, 1);
        s1 += __shfl_xor_sync(~0u, s1, 2);
        if (tig == 0) {
            sRedS[ng * 64 + r0]     = s0;
            sRedS[ng * 64 + r0 + 8] = s1;
        }
        __syncthreads();
        inv0 = 1.0f / (sRedS[r0] + sRedS[64 + r0] +
                       sRedS[128 + r0] + sRedS[192 + r0]);
        inv1 = 1.0f / (sRedS[r0 + 8] + sRedS[64 + r0 + 8] +
                       sRedS[128 + r0 + 8] + sRedS[192 + r0 + 8]);
    }

    // ---- P @ V: B via ldmatrix.trans on sV[k][d] ----
    {
        int wn = ng;
        uint32_t aP = smem_u32(&((uint32_t*)sP)[(wm * 16 + (lane & 15)) * 132 + (lane >> 4) * 4]);
        uint32_t aV = smem_u32(&sV[(lane & 15) * 20 + wn * 4]);

        float c[4] = {0.f, 0.f, 0.f, 0.f};
        #pragma unroll 4
        for (int kk = 0; kk < NPAD; kk += 16) {
            uint32_t a[4], bfr[2];
            ldsm_x4(a, aP + (kk >> 1) * 4);
            ldsm_x2_trans(bfr, aV + kk * 80);
            mma_bf16(c, a, bfr);
        }
        int d0 = wn * 8 + tig * 2;
        #pragma unroll
        for (int half = 0; half < 2; half++) {
            int row = r0 + half * 8;
            float inv = half ? inv1 : inv0;
            int gi = wi * 8 + (row >> 3), gj = wj * 8 + (row & 7);
            uint32_t* o = (uint32_t*)&out[(size_t)(bt + gi * 256 + gj) * CDIM + h * 32 + d0];
            *o = pack_bf2(c[half * 2 + 0] * inv, c[half * 2 + 1] * inv);
        }
    }
}

// ----------------------------------------------------------------------------
extern "C" void kernel_launch(void* const* d_in, const int* in_sizes, int n_in,
                              void* d_out, int out_size)
{
    const float* x      = (const float*)d_in[0];
    const float* qkv_w  = (const float*)d_in[1];
    const float* qkv_b  = (const float*)d_in[2];
    const float* proj_w = (const float*)d_in[3];
    const float* proj_b = (const float*)d_in[4];
    const float* n1g    = (const float*)d_in[5];
    const float* n1b    = (const float*)d_in[6];
    const float* n2g    = (const float*)d_in[7];
    const float* n2b    = (const float*)d_in[8];
    const float* rpbt   = (const float*)d_in[9];
    const float* rpbn   = (const float*)d_in[10];
    const float* rpbw   = (const float*)d_in[11];
    const float* poolw  = (const float*)d_in[12];
    const float* poolb  = (const float*)d_in[13];
    const float* fc1_w  = (const float*)d_in[14];
    const float* fc1_b  = (const float*)d_in[15];
    const float* fc2_w  = (const float*)d_in[16];
    const float* fc2_b  = (const float*)d_in[17];
    float* outp = (float*)d_out;

    bf16 *p_xh, *p_qkv, *p_pooled, *p_qkvp, *p_attnout, *p_fc1;
    bf16 *p_wqkv, *p_wproj, *p_wfc1, *p_wfc2;
    float *p_x2;
    cudaGetSymbolAddress((void**)&p_xh, g_xh);
    cudaGetSymbolAddress((void**)&p_qkv, g_qkv);
    cudaGetSymbolAddress((void**)&p_pooled, g_pooled);
    cudaGetSymbolAddress((void**)&p_qkvp, g_qkvp);
    cudaGetSymbolAddress((void**)&p_attnout, g_attnout);
    cudaGetSymbolAddress((void**)&p_x2, g_x2);
    cudaGetSymbolAddress((void**)&p_fc1, g_fc1);
    cudaGetSymbolAddress((void**)&p_wqkv, g_wqkv);
    cudaGetSymbolAddress((void**)&p_wproj, g_wproj);
    cudaGetSymbolAddress((void**)&p_wfc1, g_wfc1);
    cudaGetSymbolAddress((void**)&p_wfc2, g_wfc2);

    const int ATTN_SMEM = 81920;
    cudaFuncSetAttribute(attn_kernel,
                         cudaFuncAttributeMaxDynamicSharedMemorySize, ATTN_SMEM);

    // 0. one-shot tables + weight conversion
    init_rolled_kernel<<<1, 1>>>();
    init_btab_kernel<<<dim3(HEADS, WA), 256>>>(rpbt, rpbn, rpbw);
    cvt_w_kernel<<<48, 256>>>(qkv_w,  p_wqkv, 384 * 128);
    cvt_w_kernel<<<16, 256>>>(proj_w, p_wproj, 128 * 128);
    cvt_w_kernel<<<64, 256>>>(fc1_w,  p_wfc1, 512 * 128);
    cvt_w_kernel<<<64, 256>>>(fc2_w,  p_wfc2, 128 * 512);
    // 1. LN1 -> bf16 xh
    ln_kernel<<<MROWS / 8, 256>>>(x, n1g, n1b, p_xh, MROWS);
    // 2. qkv GEMM  (131072 x 384, K=128) -> bf16
    gemm_tc<<<dim3(384 / 128, MROWS / 128), 512>>>(
        p_xh, p_wqkv, qkv_b, nullptr, p_qkv, nullptr, nullptr, nullptr,
        MROWS, 384, 128, 0);
    // 3. window pooling
    pool_kernel<<<BATCH * NWIN, 128>>>(p_xh, poolw, poolb, p_pooled);
    // 4. qkv of pooled (2048 x 384, K=128) -> bf16
    gemm_tc<<<dim3(384 / 128, (BATCH * NWIN) / 128), 512>>>(
        p_pooled, p_wqkv, qkv_b, nullptr, p_qkvp, nullptr, nullptr, nullptr,
        BATCH * NWIN, 384, 128, 0);
    // 5. focal attention -> bf16 attnout
    attn_kernel<<<dim3(BATCH * NWIN, HEADS), 512, ATTN_SMEM>>>(
        p_qkv, p_qkvp, p_attnout);
    // 6. proj + residual(x) -> fp32 x2  AND fused LN2 -> bf16 xh
    gemm_tc<<<dim3(1, MROWS / 128), 512>>>(
        p_attnout, p_wproj, proj_b, x, p_x2, p_xh, n2g, n2b,
        MROWS, CDIM, 128, 3);
    // 7. fc1 + exact GELU (131072 x 512, K=128) -> bf16
    gemm_tc<<<dim3(512 / 128, MROWS / 128), 512>>>(
        p_xh, p_wfc1, fc1_b, nullptr, p_fc1, nullptr, nullptr, nullptr,
        MROWS, 512, 128, 1);
    // 8. fc2 + residual(x2) -> fp32 out (131072 x 128, K=512)
    gemm_tc<<<dim3(CDIM / 128, MROWS / 128), 512>>>(
        p_fc1, p_wfc2, fc2_b, p_x2, outp, nullptr, nullptr, nullptr,
        MROWS, CDIM, 512, 2);
}

// round 13
// speedup vs baseline: 1.8769x; 1.0809x over previous
#include <cuda_runtime.h>
#include <cuda_bf16.h>
#include <cstdint>
#include <cstddef>

// ----------------------------------------------------------------------------
// FocalTransformerBlock  B=2, H=W=256, C=128, HEADS=4, HD=32, WS=8, EXP=3
// bf16 mma + ldmatrix + cp.async; LN2 fused into proj; fc1+gelu+fc2 fused MLP
// ----------------------------------------------------------------------------

#define BATCH   2
#define HW      65536
#define CDIM    128
#define MROWS   (BATCH*HW)      // 131072
#define NWH     32
#define NWIN    1024
#define WA      64
#define NROLL   220
#define NALL    229
#define NPAD    256
#define HEADS   4
#define HD      32
#define SCALE   0.17677669529663687f

typedef __nv_bfloat16 bf16;

// -------------------------- scratch (static device) -------------------------
__device__ bf16  g_xh[MROWS * CDIM];
__device__ bf16  g_qkv[MROWS * 3 * CDIM];
__device__ bf16  g_pooled[BATCH * NWIN * CDIM];
__device__ bf16  g_qkvp[BATCH * NWIN * 3 * CDIM];
__device__ bf16  g_attnout[MROWS * CDIM];
__device__ float g_x2[MROWS * CDIM];
__device__ int   g_rolled[156];
__device__ float g_btab[HEADS * WA * NPAD];
__device__ bf16  g_wqkv[384 * 128];
__device__ bf16  g_wproj[128 * 128];
__device__ bf16  g_wfc1[512 * 128];
__device__ bf16  g_wfc2[128 * 512];

__constant__ int c_sh[4] = {-3,-3, 3, 3};
__constant__ int c_sw[4] = {-3, 3,-3, 3};

// -------------------------- helpers -----------------------------------------
__device__ __forceinline__ uint32_t pack_bf2(float x, float y) {
    __nv_bfloat162 p = __floats2bfloat162_rn(x, y);
    return *reinterpret_cast<uint32_t*>(&p);
}

__device__ __forceinline__ void mma_bf16(float c[4], const uint32_t a[4],
                                         const uint32_t b[2]) {
    asm volatile(
        "mma.sync.aligned.m16n8k16.row.col.f32.bf16.bf16.f32 "
        "{%0,%1,%2,%3},{%4,%5,%6,%7},{%8,%9},{%0,%1,%2,%3};"
        : "+f"(c[0]), "+f"(c[1]), "+f"(c[2]), "+f"(c[3])
        : "r"(a[0]), "r"(a[1]), "r"(a[2]), "r"(a[3]), "r"(b[0]), "r"(b[1]));
}

__device__ __forceinline__ void ldsm_x4(uint32_t r[4], uint32_t saddr) {
    asm volatile("ldmatrix.sync.aligned.m8n8.x4.shared.b16 {%0,%1,%2,%3}, [%4];"
        : "=r"(r[0]), "=r"(r[1]), "=r"(r[2]), "=r"(r[3]) : "r"(saddr));
}
__device__ __forceinline__ void ldsm_x2_trans(uint32_t r[2], uint32_t saddr) {
    asm volatile("ldmatrix.sync.aligned.m8n8.x2.trans.shared.b16 {%0,%1}, [%2];"
        : "=r"(r[0]), "=r"(r[1]) : "r"(saddr));
}
__device__ __forceinline__ uint32_t smem_u32(const void* p) {
    return (uint32_t)__cvta_generic_to_shared(p);
}
__device__ __forceinline__ void cp16(uint32_t dst, const void* src) {
    asm volatile("cp.async.cg.shared.global [%0], [%1], 16;" :: "r"(dst), "l"(src));
}
#define CP_COMMIT() asm volatile("cp.async.commit_group;")
#define CP_WAIT1()  asm volatile("cp.async.wait_group 1;" ::: "memory")
#define CP_WAIT0()  asm volatile("cp.async.wait_group 0;" ::: "memory")

__device__ __forceinline__ float gelu_exact(float v) {
    return 0.5f * v * (1.0f + erff(v * 0.70710678118654752f));
}

// -------------------------- one-shot init kernels ----------------------------
__global__ void init_rolled_kernel() {
    if (threadIdx.x == 0 && blockIdx.x == 0) {
        int cnt = 0;
        for (int idx = 0; idx < 256; idx++) {
            int m = idx >> 6, r = (idx >> 3) & 7, c = idx & 7;
            bool valid;
            if      (m == 0) valid = (r >= 5) || (c >= 5);
            else if (m == 1) valid = (r >= 5) || (c < 3);
            else if (m == 2) valid = (r < 3)  || (c >= 5);
            else             valid = (r < 3)  || (c < 3);
            if (valid) g_rolled[cnt++] = idx;
        }
    }
}

__global__ void init_btab_kernel(const float* __restrict__ rpbt,
                                 const float* __restrict__ rpbn,
                                 const float* __restrict__ rpbw) {
    int h = blockIdx.x, q = blockIdx.y;
    int k = threadIdx.x;            // 256
    float v = 0.f;
    int qr = q >> 3, qc = q & 7;
    if (k < 64) {
        int kr = k >> 3, kc = k & 7;
        v = rpbt[((qr - kr + 7) * 15 + (qc - kc + 7)) * HEADS + h];
    } else if (k < NROLL) {
        v = rpbn[(size_t)(h * 64 + q) * 156 + (k - 64)];
    } else if (k < NALL) {
        int p = k - NROLL;
        int kr = p / 3, kc = p % 3;
        v = rpbw[h * 100 + (qr - kr + 2) * 10 + (qc - kc + 2)];
    }
    g_btab[(h * 64 + q) * NPAD + k] = v;
}

__global__ void __launch_bounds__(256) cvt_w_kernel(
    const float* __restrict__ w, bf16* __restrict__ o, int n) {
    int i = (blockIdx.x * 256 + threadIdx.x) * 4;
    if (i < n) {
        float4 v = *(const float4*)&w[i];
        uint2 p;
        p.x = pack_bf2(v.x, v.y);
        p.y = pack_bf2(v.z, v.w);
        *(uint2*)&o[i] = p;
    }
}

// -------------------------- layernorm (fp32 in -> bf16 out) ------------------
__global__ void __launch_bounds__(256) ln_kernel(
    const float* __restrict__ x, const float* __restrict__ g,
    const float* __restrict__ b, bf16* __restrict__ out, int rows)
{
    int row = (blockIdx.x * blockDim.x + threadIdx.x) >> 5;
    if (row >= rows) return;
    int lane = threadIdx.x & 31;
    const float4* xr = (const float4*)(x + (size_t)row * CDIM);
    float4 v = xr[lane];
    float s = v.x + v.y + v.z + v.w;
    #pragma unroll
    for (int o = 16; o > 0; o >>= 1) s += __shfl_xor_sync(~0u, s, o);
    float mu = s * (1.0f / CDIM);
    float dx = v.x-mu, dy = v.y-mu, dz = v.z-mu, dw = v.w-mu;
    float s2 = dx*dx + dy*dy + dz*dz + dw*dw;
    #pragma unroll
    for (int o = 16; o > 0; o >>= 1) s2 += __shfl_xor_sync(~0u, s2, o);
    float rs = rsqrtf(s2 * (1.0f / CDIM) + 1e-5f);
    float4 gg = ((const float4*)g)[lane];
    float4 bb = ((const float4*)b)[lane];
    uint2 o2;
    o2.x = pack_bf2(dx*rs*gg.x + bb.x, dy*rs*gg.y + bb.y);
    o2.y = pack_bf2(dz*rs*gg.z + bb.z, dw*rs*gg.w + bb.w);
    ((uint2*)(out + (size_t)row * CDIM))[lane] = o2;
}

// -------------------------- bf16 GEMM (cp.async 2-stage pipeline) ------------
// A:(M,K) bf16 rm, W:(N,K) bf16 rm. Block 128x128x32, 16 warps, warp 32x32.
// epi: 0 = bf16 out, 3 = +res(fp32)->fp32 x2 AND fused LN -> bf16 xh (N==128)
__global__ void __launch_bounds__(512, 2) gemm_tc(
    const bf16* __restrict__ A, const bf16* __restrict__ W,
    const float* __restrict__ bias, const float* __restrict__ res,
    void* __restrict__ outv, bf16* __restrict__ xh_out,
    const float* __restrict__ lng, const float* __restrict__ lnb,
    int M, int N, int K, int epi)
{
    __shared__ uint32_t As[2][128][20];   // rows of 32 bf16 (16 u32), pad 20
    __shared__ uint32_t Ws[2][128][20];
    __shared__ float sRedS[4 * 128];      // LN fused reductions (epi==3)
    __shared__ float sRedQ[4 * 128];
    int tid = threadIdx.x, lane = tid & 31, warp = tid >> 5;
    int wm = warp >> 2, wn = warp & 3;
    int grp = lane >> 2, tig = lane & 3;
    int m0 = blockIdx.y * 128, n0 = blockIdx.x * 128;

    uint32_t sA = smem_u32(&As[0][0][0]);
    uint32_t sW = smem_u32(&Ws[0][0][0]);
    const int STG = 128 * 20 * 4;         // 10240 B per stage

    int lr = tid >> 2, lc8 = (tid & 3) * 8;

    auto issue = [&](int s, int k0) {
        cp16(sA + s * STG + (lr * 20 + (lc8 >> 1)) * 4,
             A + (size_t)(m0 + lr) * K + k0 + lc8);
        cp16(sW + s * STG + (lr * 20 + (lc8 >> 1)) * 4,
             W + (size_t)(n0 + lr) * K + k0 + lc8);
    };

    uint32_t aA0 = smem_u32(&As[0][wm * 32 + (lane & 15)][(lane >> 4) * 4]);
    uint32_t aA1 = aA0 + 16 * 80;
    int brow = ((lane >> 4) << 3) + (lane & 7), bcol = ((lane >> 3) & 1) * 4;
    uint32_t aB0 = smem_u32(&Ws[0][wn * 32 + brow][bcol]);
    uint32_t aB1 = aB0 + 16 * 80;

    float c[2][4][4];
    #pragma unroll
    for (int mt = 0; mt < 2; mt++)
        #pragma unroll
        for (int nt = 0; nt < 4; nt++)
            #pragma unroll
            for (int j = 0; j < 4; j++) c[mt][nt][j] = 0.f;

    int niter = K >> 5;
    issue(0, 0);
    CP_COMMIT();
    for (int it = 0; it < niter; it++) {
        int s = it & 1;
        if (it + 1 < niter) issue(s ^ 1, (it + 1) * 32);
        CP_COMMIT();
        CP_WAIT1();
        __syncthreads();
        uint32_t off = s * STG;
        #pragma unroll
        for (int ks = 0; ks < 2; ks++) {
            uint32_t boff = ks * 32;
            uint32_t a0[4], a1[4], b0[4], b1[4];
            ldsm_x4(a0, aA0 + off + boff);
            ldsm_x4(a1, aA1 + off + boff);
            ldsm_x4(b0, aB0 + off + boff);
            ldsm_x4(b1, aB1 + off + boff);
            uint32_t bf0[2] = {b0[0], b0[1]}, bf1[2] = {b0[2], b0[3]};
            uint32_t bf2[2] = {b1[0], b1[1]}, bf3[2] = {b1[2], b1[3]};
            mma_bf16(c[0][0], a0, bf0); mma_bf16(c[0][1], a0, bf1);
            mma_bf16(c[0][2], a0, bf2); mma_bf16(c[0][3], a0, bf3);
            mma_bf16(c[1][0], a1, bf0); mma_bf16(c[1][1], a1, bf1);
            mma_bf16(c[1][2], a1, bf2); mma_bf16(c[1][3], a1, bf3);
        }
        __syncthreads();
    }

    if (epi == 3) {
        #pragma unroll
        for (int mt = 0; mt < 2; mt++) {
            #pragma unroll
            for (int nt = 0; nt < 4; nt++) {
                int cn = wn * 32 + nt * 8 + tig * 2;
                float2 bp = *(const float2*)&bias[cn];
                #pragma unroll
                for (int half = 0; half < 2; half++) {
                    int row = m0 + wm * 32 + mt * 16 + half * 8 + grp;
                    float v0 = c[mt][nt][half * 2 + 0] + bp.x;
                    float v1 = c[mt][nt][half * 2 + 1] + bp.y;
                    float2 rr = *(const float2*)&res[(size_t)row * 128 + cn];
                    v0 += rr.x; v1 += rr.y;
                    c[mt][nt][half * 2 + 0] = v0;
                    c[mt][nt][half * 2 + 1] = v1;
                    *(float2*)&((float*)outv)[(size_t)row * 128 + cn] =
                        make_float2(v0, v1);
                }
            }
        }
        #pragma unroll
        for (int mt = 0; mt < 2; mt++)
            #pragma unroll
            for (int half = 0; half < 2; half++) {
                int lrow = wm * 32 + mt * 16 + half * 8 + grp;
                float s = 0.f, q = 0.f;
                #pragma unroll
                for (int nt = 0; nt < 4; nt++) {
                    float v0 = c[mt][nt][half * 2 + 0];
                    float v1 = c[mt][nt][half * 2 + 1];
                    s += v0 + v1;
                    q += v0 * v0 + v1 * v1;
                }
                s += __shfl_xor_sync(~0u, s, 1);
                s += __shfl_xor_sync(~0u, s, 2);
                q += __shfl_xor_sync(~0u, q, 1);
                q += __shfl_xor_sync(~0u, q, 2);
                if (tig == 0) {
                    sRedS[wn * 128 + lrow] = s;
                    sRedQ[wn * 128 + lrow] = q;
                }
            }
        __syncthreads();
        #pragma unroll
        for (int mt = 0; mt < 2; mt++)
            #pragma unroll
            for (int half = 0; half < 2; half++) {
                int lrow = wm * 32 + mt * 16 + half * 8 + grp;
                float S = sRedS[lrow] + sRedS[128 + lrow] +
                          sRedS[256 + lrow] + sRedS[384 + lrow];
                float Q = sRedQ[lrow] + sRedQ[128 + lrow] +
                          sRedQ[256 + lrow] + sRedQ[384 + lrow];
                float mu = S * (1.0f / 128.0f);
                float var = Q * (1.0f / 128.0f) - mu * mu;
                float rs = rsqrtf(var + 1e-5f);
                int row = m0 + lrow;
                #pragma unroll
                for (int nt = 0; nt < 4; nt++) {
                    int cn = wn * 32 + nt * 8 + tig * 2;
                    float2 gg = *(const float2*)&lng[cn];
                    float2 bb = *(const float2*)&lnb[cn];
                    float v0 = (c[mt][nt][half * 2 + 0] - mu) * rs * gg.x + bb.x;
                    float v1 = (c[mt][nt][half * 2 + 1] - mu) * rs * gg.y + bb.y;
                    *(uint32_t*)&xh_out[(size_t)row * 128 + cn] = pack_bf2(v0, v1);
                }
            }
        return;
    }

    #pragma unroll
    for (int mt = 0; mt < 2; mt++) {
        int r0 = m0 + wm * 32 + mt * 16 + grp;
        #pragma unroll
        for (int nt = 0; nt < 4; nt++) {
            int cn = n0 + wn * 32 + nt * 8 + tig * 2;
            float2 bp = *(const float2*)&bias[cn];
            #pragma unroll
            for (int half = 0; half < 2; half++) {
                int row = r0 + half * 8;
                float v0 = c[mt][nt][half * 2 + 0] + bp.x;
                float v1 = c[mt][nt][half * 2 + 1] + bp.y;
                ((uint32_t*)outv)[((size_t)row * N + cn) >> 1] = pack_bf2(v0, v1);
            }
        }
    }
}

// -------------------------- fused MLP: out = gelu(xh@W1^T+b1)@W2^T+b2+x2 -----
// grid (MROWS/128), 512 threads. Chunks of 128 fc1-units; W1 chunk in buf0,
// W2 chunk in buf1 (cp.async streamed). smem rows stride 68 u32 (136 bf16).
__global__ void __launch_bounds__(512) mlp_kernel(
    const bf16* __restrict__ xh, const bf16* __restrict__ w1,
    const float* __restrict__ b1, const bf16* __restrict__ w2,
    const float* __restrict__ b2, const float* __restrict__ x2,
    float* __restrict__ out)
{
    extern __shared__ char sm[];
    const int TSZ = 128 * 68 * 4;        // 34816 B per tile
    uint32_t* sX = (uint32_t*)sm;                    // xh block
    uint32_t* sH = (uint32_t*)(sm + TSZ);            // gelu(fc1) chunk
    uint32_t  wb0 = smem_u32(sm + 2 * TSZ);          // W1 chunk
    uint32_t  wb1 = wb0 + TSZ;                       // W2 chunk

    int tid = threadIdx.x, lane = tid & 31, warp = tid >> 5;
    int wm = warp >> 2, wn = warp & 3;
    int grp = lane >> 2, tig = lane & 3;
    int m0 = blockIdx.x * 128;

    uint32_t sXa = smem_u32(sX);
    uint32_t sHa = smem_u32(sH);

    // ---- load xh block + W1 chunk 0 (one cp.async group) ----
    #pragma unroll
    for (int i = 0; i < 4; i++) {
        int idx = tid + i * 512;
        int row = idx >> 4, c8 = (idx & 15) * 8;
        uint32_t doff = (row * 68 + (c8 >> 1)) * 4;
        cp16(sXa + doff, xh + (size_t)(m0 + row) * 128 + c8);
        cp16(wb0 + doff, w1 + (size_t)row * 128 + c8);
    }
    CP_COMMIT();

    // ldmatrix per-lane addresses
    int arow = lane & 15, aucol = (lane >> 4) * 4;
    uint32_t aX0 = sXa + ((wm * 32 + arow) * 68 + aucol) * 4;
    uint32_t aX1 = aX0 + 16 * 272;
    uint32_t aH0 = sHa + ((wm * 32 + arow) * 68 + aucol) * 4;
    uint32_t aH1 = aH0 + 16 * 272;
    int brow = ((lane >> 4) << 3) + (lane & 7), bcol = ((lane >> 3) & 1) * 4;
    uint32_t b0a = (uint32_t)((wn * 32 + brow) * 68 + bcol) * 4;
    uint32_t b1a = (uint32_t)((wn * 32 + 16 + brow) * 68 + bcol) * 4;

    float cO[2][4][4];
    #pragma unroll
    for (int mt = 0; mt < 2; mt++)
        #pragma unroll
        for (int nt = 0; nt < 4; nt++)
            #pragma unroll
            for (int j = 0; j < 4; j++) cO[mt][nt][j] = 0.f;

    for (int ch = 0; ch < 4; ch++) {
        CP_WAIT0();
        __syncthreads();                 // W1_ch (and xh) ready; sH/B done
        // prefetch W2_ch
        #pragma unroll
        for (int i = 0; i < 4; i++) {
            int idx = tid + i * 512;
            int row = idx >> 4, c8 = (idx & 15) * 8;
            cp16(wb1 + (row * 68 + (c8 >> 1)) * 4,
                 w2 + (size_t)row * 512 + ch * 128 + c8);
        }
        CP_COMMIT();

        // ---- phase A: H = xh @ W1_ch^T ----
        float cA[2][4][4];
        #pragma unroll
        for (int mt = 0; mt < 2; mt++)
            #pragma unroll
            for (int nt = 0; nt < 4; nt++)
                #pragma unroll
                for (int j = 0; j < 4; j++) cA[mt][nt][j] = 0.f;
        #pragma unroll
        for (int ks = 0; ks < 8; ks++) {
            uint32_t koff = ks * 32;
            uint32_t a0[4], a1[4], p0[4], p1[4];
            ldsm_x4(a0, aX0 + koff);
            ldsm_x4(a1, aX1 + koff);
            ldsm_x4(p0, wb0 + b0a + koff);
            ldsm_x4(p1, wb0 + b1a + koff);
            uint32_t f0[2] = {p0[0], p0[1]}, f1[2] = {p0[2], p0[3]};
            uint32_t f2[2] = {p1[0], p1[1]}, f3[2] = {p1[2], p1[3]};
            mma_bf16(cA[0][0], a0, f0); mma_bf16(cA[0][1], a0, f1);
            mma_bf16(cA[0][2], a0, f2); mma_bf16(cA[0][3], a0, f3);
            mma_bf16(cA[1][0], a1, f0); mma_bf16(cA[1][1], a1, f1);
            mma_bf16(cA[1][2], a1, f2); mma_bf16(cA[1][3], a1, f3);
        }
        // gelu(+bias) -> sH (bf16)
        #pragma unroll
        for (int mt = 0; mt < 2; mt++) {
            #pragma unroll
            for (int nt = 0; nt < 4; nt++) {
                int cn = wn * 32 + nt * 8 + tig * 2;
                float2 bp = *(const float2*)&b1[ch * 128 + cn];
                #pragma unroll
                for (int half = 0; half < 2; half++) {
                    int lrow = wm * 32 + mt * 16 + half * 8 + grp;
                    float v0 = gelu_exact(cA[mt][nt][half * 2 + 0] + bp.x);
                    float v1 = gelu_exact(cA[mt][nt][half * 2 + 1] + bp.y);
                    sH[lrow * 68 + (cn >> 1)] = pack_bf2(v0, v1);
                }
            }
        }
        CP_WAIT0();
        __syncthreads();                 // W2_ch ready; sH visible
        // prefetch W1_{ch+1} into wb0 (phase A done with it)
        if (ch < 3) {
            #pragma unroll
            for (int i = 0; i < 4; i++) {
                int idx = tid + i * 512;
                int row = idx >> 4, c8 = (idx & 15) * 8;
                cp16(wb0 + (row * 68 + (c8 >> 1)) * 4,
                     w1 + (size_t)((ch + 1) * 128 + row) * 128 + c8);
            }
            CP_COMMIT();
        }
        // ---- phase B: out += H @ W2_ch^T ----
        #pragma unroll
        for (int ks = 0; ks < 8; ks++) {
            uint32_t koff = ks * 32;
            uint32_t a0[4], a1[4], p0[4], p1[4];
            ldsm_x4(a0, aH0 + koff);
            ldsm_x4(a1, aH1 + koff);
            ldsm_x4(p0, wb1 + b0a + koff);
            ldsm_x4(p1, wb1 + b1a + koff);
            uint32_t f0[2] = {p0[0], p0[1]}, f1[2] = {p0[2], p0[3]};
            uint32_t f2[2] = {p1[0], p1[1]}, f3[2] = {p1[2], p1[3]};
            mma_bf16(cO[0][0], a0, f0); mma_bf16(cO[0][1], a0, f1);
            mma_bf16(cO[0][2], a0, f2); mma_bf16(cO[0][3], a0, f3);
            mma_bf16(cO[1][0], a1, f0); mma_bf16(cO[1][1], a1, f1);
            mma_bf16(cO[1][2], a1, f2); mma_bf16(cO[1][3], a1, f3);
        }
        __syncthreads();                 // protect sH / wb1 for next chunk
    }

    // ---- epilogue: + b2 + x2 -> fp32 out ----
    #pragma unroll
    for (int mt = 0; mt < 2; mt++) {
        #pragma unroll
        for (int nt = 0; nt < 4; nt++) {
            int cn = wn * 32 + nt * 8 + tig * 2;
            float2 bp = *(const float2*)&b2[cn];
            #pragma unroll
            for (int half = 0; half < 2; half++) {
                int row = m0 + wm * 32 + mt * 16 + half * 8 + grp;
                float v0 = cO[mt][nt][half * 2 + 0] + bp.x;
                float v1 = cO[mt][nt][half * 2 + 1] + bp.y;
                float2 rr = *(const float2*)&x2[(size_t)row * 128 + cn];
                *(float2*)&out[(size_t)row * 128 + cn] =
                    make_float2(v0 + rr.x, v1 + rr.y);
            }
        }
    }
}

// -------------------------- window pooling (bf16 in/out) ---------------------
__global__ void __launch_bounds__(128) pool_kernel(
    const bf16* __restrict__ xh, const float* __restrict__ pw,
    const float* __restrict__ pb, bf16* __restrict__ pooled)
{
    int w = blockIdx.x;
    int b = w >> 10, ij = w & 1023;
    int i = ij >> 5, j = ij & 31;
    int c = threadIdx.x;
    float acc = 0.f;
    #pragma unroll
    for (int n = 0; n < 64; n++) {
        int r = n >> 3, cc = n & 7;
        size_t tok = (size_t)(b * HW + (i * 8 + r) * 256 + (j * 8 + cc));
        acc += __bfloat162float(xh[tok * CDIM + c]) * pw[n];
    }
    pooled[(size_t)w * CDIM + c] = __float2bfloat16(acc + pb[0]);
}

// -------------------------- attention (register softmax) ---------------------
__global__ void __launch_bounds__(512, 2) attn_kernel(
    const bf16* __restrict__ qkv, const bf16* __restrict__ qkvp,
    bf16* __restrict__ out)
{
    extern __shared__ char smraw[];
    uint32_t* sQ    = (uint32_t*)smraw;                     // 5120
    uint32_t* sK    = (uint32_t*)(smraw + 5120);            // 20480
    uint32_t* sV    = (uint32_t*)(smraw + 25600);           // 20480
    bf16*     sP    = (bf16*)(smraw + 46080);               // 33792
    float*    sRedM = (float*)(smraw + 79872);              // 1024
    float*    sRedS = (float*)(smraw + 80896);              // 1024

    int tid = threadIdx.x, lane = tid & 31, warp = tid >> 5;
    int grp = lane >> 2, tig = lane & 3;
    int w = blockIdx.x, h = blockIdx.y;
    int b = w >> 10, wi = (w >> 5) & 31, wj = w & 31;
    int bt = b << 16;
    int wm = warp >> 2, ng = warp & 3;

    {
        int q = tid >> 3, d4 = (tid & 7) * 4;
        int gi = wi * 8 + (q >> 3), gj = wj * 8 + (q & 7);
        uint2 v = *(const uint2*)&qkv[(size_t)(bt + gi * 256 + gj) * 384 + h * 32 + d4];
        *(uint2*)&sQ[q * 20 + (d4 >> 1)] = v;
    }
    #pragma unroll
    for (int it = 0; it < 4; it++) {
        int idx = tid + it * 512;
        int krow = idx >> 3, d4 = (idx & 7) * 4;
        uint2 kv = make_uint2(0u, 0u), vv = kv;
        if (krow < NROLL) {
            int gi, gj;
            if (krow < 64) {
                gi = wi * 8 + (krow >> 3);
                gj = wj * 8 + (krow & 7);
            } else {
                int raw = g_rolled[krow - 64];
                int m = raw >> 6, r = (raw >> 3) & 7, c = raw & 7;
                gi = (wi * 8 + r - c_sh[m]) & 255;
                gj = (wj * 8 + c - c_sw[m]) & 255;
            }
            size_t base = (size_t)(bt + gi * 256 + gj) * 384 + 128 + h * 32 + d4;
            kv = *(const uint2*)&qkv[base];
            vv = *(const uint2*)&qkv[base + 128];
        } else if (krow < NALL) {
            int p = krow - NROLL;
            int pi = wi + p / 3 - 1, pj = wj + p % 3 - 1;
            if (pi >= 0 && pi < 32 && pj >= 0 && pj < 32) {
                size_t base = (size_t)((b << 10) + pi * 32 + pj) * 384 + 128 + h * 32 + d4;
                kv = *(const uint2*)&qkvp[base];
                vv = *(const uint2*)&qkvp[base + 128];
            }
        }
        *(uint2*)&sK[krow * 20 + (d4 >> 1)] = kv;
        *(uint2*)&sV[krow * 20 + (d4 >> 1)] = vv;
    }
    __syncthreads();

    float inv0, inv1;
    int r0 = wm * 16 + grp;

    {
        uint32_t aQ = smem_u32(&sQ[(wm * 16 + (lane & 15)) * 20 + (lane >> 4) * 4]);
        int brow = ((lane >> 4) << 3) + (lane & 7), bcol = ((lane >> 3) & 1) * 4;
        uint32_t aK[4];
        #pragma unroll
        for (int p = 0; p < 4; p++)
            aK[p] = smem_u32(&sK[(ng * 64 + p * 16 + brow) * 20 + bcol]);

        float c[8][4];
        #pragma unroll
        for (int nt = 0; nt < 8; nt++)
            #pragma unroll
            for (int j = 0; j < 4; j++) c[nt][j] = 0.f;
        #pragma unroll
        for (int ks = 0; ks < 2; ks++) {
            uint32_t boff = ks * 32;
            uint32_t a[4], bfr[8][2];
            ldsm_x4(a, aQ + boff);
            #pragma unroll
            for (int p = 0; p < 4; p++) {
                uint32_t r4[4];
                ldsm_x4(r4, aK[p] + boff);
                bfr[2*p  ][0] = r4[0]; bfr[2*p  ][1] = r4[1];
                bfr[2*p+1][0] = r4[2]; bfr[2*p+1][1] = r4[3];
            }
            #pragma unroll
            for (int nt = 0; nt < 8; nt++)
                mma_bf16(c[nt], a, bfr[nt]);
        }

        const float* tabh = &g_btab[(h * 64) * NPAD];
        #pragma unroll
        for (int nt = 0; nt < 8; nt++) {
            int cn = ng * 64 + nt * 8 + tig * 2;
            #pragma unroll
            for (int half = 0; half < 2; half++) {
                int row = r0 + half * 8;
                float2 tv = *(const float2*)&tabh[row * NPAD + cn];
                float v0 = c[nt][half * 2 + 0] * SCALE + tv.x;
                float v1 = c[nt][half * 2 + 1] * SCALE + tv.y;
                if (cn + 1 >= NROLL) {
                    #pragma unroll
                    for (int e = 0; e < 2; e++) {
                        int k = cn + e;
                        float* vp = e ? &v1 : &v0;
                        if (k >= NALL) { *vp = -1e30f; }
                        else if (k >= NROLL) {
                            int p = k - NROLL;
                            int kr = p / 3, kc = p % 3;
                            int pi = wi + kr - 1, pj = wj + kc - 1;
                            if (!(pi >= 0 && pi < 32 && pj >= 0 && pj < 32))
                                *vp -= 100.f;
                        }
                    }
                }
                c[nt][half * 2 + 0] = v0;
                c[nt][half * 2 + 1] = v1;
            }
        }

        float m0 = -1e30f, m1 = -1e30f;
        #pragma unroll
        for (int nt = 0; nt < 8; nt++) {
            m0 = fmaxf(m0, fmaxf(c[nt][0], c[nt][1]));
            m1 = fmaxf(m1, fmaxf(c[nt][2], c[nt][3]));
        }
        m0 = fmaxf(m0, __shfl_xor_sync(~0u, m0, 1));
        m0 = fmaxf(m0, __shfl_xor_sync(~0u, m0, 2));
        m1 = fmaxf(m1, __shfl_xor_sync(~0u, m1, 1));
        m1 = fmaxf(m1, __shfl_xor_sync(~0u, m1, 2));
        if (tig == 0) {
            sRedM[ng * 64 + r0]     = m0;
            sRedM[ng * 64 + r0 + 8] = m1;
        }
        __syncthreads();
        float M0 = fmaxf(fmaxf(sRedM[r0], sRedM[64 + r0]),
                         fmaxf(sRedM[128 + r0], sRedM[192 + r0]));
        float M1 = fmaxf(fmaxf(sRedM[r0 + 8], sRedM[64 + r0 + 8]),
                         fmaxf(sRedM[128 + r0 + 8], sRedM[192 + r0 + 8]));

        uint32_t* sP32 = (uint32_t*)sP;
        float s0 = 0.f, s1 = 0.f;
        #pragma unroll
        for (int nt = 0; nt < 8; nt++) {
            float e00 = __expf(c[nt][0] - M0);
            float e01 = __expf(c[nt][1] - M0);
            float e10 = __expf(c[nt][2] - M1);
            float e11 = __expf(c[nt][3] - M1);
            s0 += e00 + e01;
            s1 += e10 + e11;
            int ci = ng * 32 + nt * 4 + tig;
            sP32[r0 * 132 + ci]       = pack_bf2(e00, e01);
            sP32[(r0 + 8) * 132 + ci] = pack_bf2(e10, e11);
        }
        s0 += __shfl_xor_sync(~0u, s0, 1);
        s0 += __shfl_xor_sync(~0u, s0, 2);
        s1 += __shfl_xor_sync(~0u, s1, 1);
        s1 += __shfl_xor_sync(~0u, s1, 2);
        if (tig == 0) {
            sRedS[ng * 64 + r0]     = s0;
            sRedS[ng * 64 + r0 + 8] = s1;
        }
        __syncthreads();
        inv0 = 1.0f / (sRedS[r0] + sRedS[64 + r0] +
                       sRedS[128 + r0] + sRedS[192 + r0]);
        inv1 = 1.0f / (sRedS[r0 + 8] + sRedS[64 + r0 + 8] +
                       sRedS[128 + r0 + 8] + sRedS[192 + r0 + 8]);
    }

    {
        int wn = ng;
        uint32_t aP = smem_u32(&((uint32_t*)sP)[(wm * 16 + (lane & 15)) * 132 + (lane >> 4) * 4]);
        uint32_t aV = smem_u32(&sV[(lane & 15) * 20 + wn * 4]);

        float c[4] = {0.f, 0.f, 0.f, 0.f};
        #pragma unroll 4
        for (int kk = 0; kk < NPAD; kk += 16) {
            uint32_t a[4], bfr[2];
            ldsm_x4(a, aP + (kk >> 1) * 4);
            ldsm_x2_trans(bfr, aV + kk * 80);
            mma_bf16(c, a, bfr);
        }
        int d0 = wn * 8 + tig * 2;
        #pragma unroll
        for (int half = 0; half < 2; half++) {
            int row = r0 + half * 8;
            float inv = half ? inv1 : inv0;
            int gi = wi * 8 + (row >> 3), gj = wj * 8 + (row & 7);
            uint32_t* o = (uint32_t*)&out[(size_t)(bt + gi * 256 + gj) * CDIM + h * 32 + d0];
            *o = pack_bf2(c[half * 2 + 0] * inv, c[half * 2 + 1] * inv);
        }
    }
}

// ----------------------------------------------------------------------------
extern "C" void kernel_launch(void* const* d_in, const int* in_sizes, int n_in,
                              void* d_out, int out_size)
{
    const float* x      = (const float*)d_in[0];
    const float* qkv_w  = (const float*)d_in[1];
    const float* qkv_b  = (const float*)d_in[2];
    const float* proj_w = (const float*)d_in[3];
    const float* proj_b = (const float*)d_in[4];
    const float* n1g    = (const float*)d_in[5];
    const float* n1b    = (const float*)d_in[6];
    const float* n2g    = (const float*)d_in[7];
    const float* n2b    = (const float*)d_in[8];
    const float* rpbt   = (const float*)d_in[9];
    const float* rpbn   = (const float*)d_in[10];
    const float* rpbw   = (const float*)d_in[11];
    const float* poolw  = (const float*)d_in[12];
    const float* poolb  = (const float*)d_in[13];
    const float* fc1_w  = (const float*)d_in[14];
    const float* fc1_b  = (const float*)d_in[15];
    const float* fc2_w  = (const float*)d_in[16];
    const float* fc2_b  = (const float*)d_in[17];
    float* outp = (float*)d_out;

    bf16 *p_xh, *p_qkv, *p_pooled, *p_qkvp, *p_attnout;
    bf16 *p_wqkv, *p_wproj, *p_wfc1, *p_wfc2;
    float *p_x2;
    cudaGetSymbolAddress((void**)&p_xh, g_xh);
    cudaGetSymbolAddress((void**)&p_qkv, g_qkv);
    cudaGetSymbolAddress((void**)&p_pooled, g_pooled);
    cudaGetSymbolAddress((void**)&p_qkvp, g_qkvp);
    cudaGetSymbolAddress((void**)&p_attnout, g_attnout);
    cudaGetSymbolAddress((void**)&p_x2, g_x2);
    cudaGetSymbolAddress((void**)&p_wqkv, g_wqkv);
    cudaGetSymbolAddress((void**)&p_wproj, g_wproj);
    cudaGetSymbolAddress((void**)&p_wfc1, g_wfc1);
    cudaGetSymbolAddress((void**)&p_wfc2, g_wfc2);

    const int ATTN_SMEM = 81920;
    cudaFuncSetAttribute(attn_kernel,
                         cudaFuncAttributeMaxDynamicSharedMemorySize, ATTN_SMEM);
    const int MLP_SMEM = 4 * 128 * 68 * 4;   // 139264 B
    cudaFuncSetAttribute(mlp_kernel,
                         cudaFuncAttributeMaxDynamicSharedMemorySize, MLP_SMEM);

    // 0. one-shot tables + weight conversion
    init_rolled_kernel<<<1, 1>>>();
    init_btab_kernel<<<dim3(HEADS, WA), 256>>>(rpbt, rpbn, rpbw);
    cvt_w_kernel<<<48, 256>>>(qkv_w,  p_wqkv, 384 * 128);
    cvt_w_kernel<<<16, 256>>>(proj_w, p_wproj, 128 * 128);
    cvt_w_kernel<<<64, 256>>>(fc1_w,  p_wfc1, 512 * 128);
    cvt_w_kernel<<<64, 256>>>(fc2_w,  p_wfc2, 128 * 512);
    // 1. LN1 -> bf16 xh
    ln_kernel<<<MROWS / 8, 256>>>(x, n1g, n1b, p_xh, MROWS);
    // 2. qkv GEMM  (131072 x 384, K=128) -> bf16
    gemm_tc<<<dim3(384 / 128, MROWS / 128), 512>>>(
        p_xh, p_wqkv, qkv_b, nullptr, p_qkv, nullptr, nullptr, nullptr,
        MROWS, 384, 128, 0);
    // 3. window pooling
    pool_kernel<<<BATCH * NWIN, 128>>>(p_xh, poolw, poolb, p_pooled);
    // 4. qkv of pooled (2048 x 384, K=128) -> bf16
    gemm_tc<<<dim3(384 / 128, (BATCH * NWIN) / 128), 512>>>(
        p_pooled, p_wqkv, qkv_b, nullptr, p_qkvp, nullptr, nullptr, nullptr,
        BATCH * NWIN, 384, 128, 0);
    // 5. focal attention -> bf16 attnout
    attn_kernel<<<dim3(BATCH * NWIN, HEADS), 512, ATTN_SMEM>>>(
        p_qkv, p_qkvp, p_attnout);
    // 6. proj + residual(x) -> fp32 x2  AND fused LN2 -> bf16 xh
    gemm_tc<<<dim3(1, MROWS / 128), 512>>>(
        p_attnout, p_wproj, proj_b, x, p_x2, p_xh, n2g, n2b,
        MROWS, CDIM, 128, 3);
    // 7. fused MLP: out = gelu(xh@W1^T+b1)@W2^T + b2 + x2
    mlp_kernel<<<MROWS / 128, 512, MLP_SMEM>>>(
        p_xh, p_wfc1, fc1_b, p_wfc2, fc2_b, p_x2, outp);
}

// round 14
// speedup vs baseline: 1.8770x; 1.0001x over previous
#include <cuda_runtime.h>
#include <cuda_bf16.h>
#include <cstdint>
#include <cstddef>

// ----------------------------------------------------------------------------
// FocalTransformerBlock  B=2, H=W=256, C=128, HEADS=4, HD=32, WS=8, EXP=3
// bf16 mma + ldmatrix + cp.async; LN2 fused into proj; fc1+gelu+fc2 fused MLP
// ----------------------------------------------------------------------------

#define BATCH   2
#define HW      65536
#define CDIM    128
#define MROWS   (BATCH*HW)      // 131072
#define NWH     32
#define NWIN    1024
#define WA      64
#define NROLL   220
#define NALL    229
#define NPAD    256
#define HEADS   4
#define HD      32
#define SCALE   0.17677669529663687f

typedef __nv_bfloat16 bf16;

// -------------------------- scratch (static device) -------------------------
__device__ bf16  g_xh[MROWS * CDIM];
__device__ bf16  g_qkv[MROWS * 3 * CDIM];
__device__ bf16  g_pooled[BATCH * NWIN * CDIM];
__device__ bf16  g_qkvp[BATCH * NWIN * 3 * CDIM];
__device__ bf16  g_attnout[MROWS * CDIM];
__device__ float g_x2[MROWS * CDIM];
__device__ int   g_rolled[156];
__device__ float g_btab[HEADS * WA * NPAD];
__device__ bf16  g_wqkv[384 * 128];
__device__ bf16  g_wproj[128 * 128];
__device__ bf16  g_wfc1[512 * 128];
__device__ bf16  g_wfc2[128 * 512];

__constant__ int c_sh[4] = {-3,-3, 3, 3};
__constant__ int c_sw[4] = {-3, 3,-3, 3};

// -------------------------- helpers -----------------------------------------
__device__ __forceinline__ uint32_t pack_bf2(float x, float y) {
    __nv_bfloat162 p = __floats2bfloat162_rn(x, y);
    return *reinterpret_cast<uint32_t*>(&p);
}

__device__ __forceinline__ void mma_bf16(float c[4], const uint32_t a[4],
                                         const uint32_t b[2]) {
    asm volatile(
        "mma.sync.aligned.m16n8k16.row.col.f32.bf16.bf16.f32 "
        "{%0,%1,%2,%3},{%4,%5,%6,%7},{%8,%9},{%0,%1,%2,%3};"
        : "+f"(c[0]), "+f"(c[1]), "+f"(c[2]), "+f"(c[3])
        : "r"(a[0]), "r"(a[1]), "r"(a[2]), "r"(a[3]), "r"(b[0]), "r"(b[1]));
}

__device__ __forceinline__ void ldsm_x4(uint32_t r[4], uint32_t saddr) {
    asm volatile("ldmatrix.sync.aligned.m8n8.x4.shared.b16 {%0,%1,%2,%3}, [%4];"
        : "=r"(r[0]), "=r"(r[1]), "=r"(r[2]), "=r"(r[3]) : "r"(saddr));
}
__device__ __forceinline__ void ldsm_x2_trans(uint32_t r[2], uint32_t saddr) {
    asm volatile("ldmatrix.sync.aligned.m8n8.x2.trans.shared.b16 {%0,%1}, [%2];"
        : "=r"(r[0]), "=r"(r[1]) : "r"(saddr));
}
__device__ __forceinline__ uint32_t smem_u32(const void* p) {
    return (uint32_t)__cvta_generic_to_shared(p);
}
__device__ __forceinline__ void cp16(uint32_t dst, const void* src) {
    asm volatile("cp.async.cg.shared.global [%0], [%1], 16;" :: "r"(dst), "l"(src));
}
#define CP_COMMIT() asm volatile("cp.async.commit_group;")
#define CP_WAIT1()  asm volatile("cp.async.wait_group 1;" ::: "memory")
#define CP_WAIT0()  asm volatile("cp.async.wait_group 0;" ::: "memory")

__device__ __forceinline__ float gelu_exact(float v) {
    return 0.5f * v * (1.0f + erff(v * 0.70710678118654752f));
}

// -------------------------- one-shot init kernels ----------------------------
__global__ void init_rolled_kernel() {
    if (threadIdx.x == 0 && blockIdx.x == 0) {
        int cnt = 0;
        for (int idx = 0; idx < 256; idx++) {
            int m = idx >> 6, r = (idx >> 3) & 7, c = idx & 7;
            bool valid;
            if      (m == 0) valid = (r >= 5) || (c >= 5);
            else if (m == 1) valid = (r >= 5) || (c < 3);
            else if (m == 2) valid = (r < 3)  || (c >= 5);
            else             valid = (r < 3)  || (c < 3);
            if (valid) g_rolled[cnt++] = idx;
        }
    }
}

__global__ void init_btab_kernel(const float* __restrict__ rpbt,
                                 const float* __restrict__ rpbn,
                                 const float* __restrict__ rpbw) {
    int h = blockIdx.x, q = blockIdx.y;
    int k = threadIdx.x;            // 256
    float v = 0.f;
    int qr = q >> 3, qc = q & 7;
    if (k < 64) {
        int kr = k >> 3, kc = k & 7;
        v = rpbt[((qr - kr + 7) * 15 + (qc - kc + 7)) * HEADS + h];
    } else if (k < NROLL) {
        v = rpbn[(size_t)(h * 64 + q) * 156 + (k - 64)];
    } else if (k < NALL) {
        int p = k - NROLL;
        int kr = p / 3, kc = p % 3;
        v = rpbw[h * 100 + (qr - kr + 2) * 10 + (qc - kc + 2)];
    }
    g_btab[(h * 64 + q) * NPAD + k] = v;
}

__global__ void __launch_bounds__(256) cvt_w_kernel(
    const float* __restrict__ w, bf16* __restrict__ o, int n) {
    int i = (blockIdx.x * 256 + threadIdx.x) * 4;
    if (i < n) {
        float4 v = *(const float4*)&w[i];
        uint2 p;
        p.x = pack_bf2(v.x, v.y);
        p.y = pack_bf2(v.z, v.w);
        *(uint2*)&o[i] = p;
    }
}

// -------------------------- layernorm (fp32 in -> bf16 out) ------------------
__global__ void __launch_bounds__(256) ln_kernel(
    const float* __restrict__ x, const float* __restrict__ g,
    const float* __restrict__ b, bf16* __restrict__ out, int rows)
{
    int row = (blockIdx.x * blockDim.x + threadIdx.x) >> 5;
    if (row >= rows) return;
    int lane = threadIdx.x & 31;
    const float4* xr = (const float4*)(x + (size_t)row * CDIM);
    float4 v = xr[lane];
    float s = v.x + v.y + v.z + v.w;
    #pragma unroll
    for (int o = 16; o > 0; o >>= 1) s += __shfl_xor_sync(~0u, s, o);
    float mu = s * (1.0f / CDIM);
    float dx = v.x-mu, dy = v.y-mu, dz = v.z-mu, dw = v.w-mu;
    float s2 = dx*dx + dy*dy + dz*dz + dw*dw;
    #pragma unroll
    for (int o = 16; o > 0; o >>= 1) s2 += __shfl_xor_sync(~0u, s2, o);
    float rs = rsqrtf(s2 * (1.0f / CDIM) + 1e-5f);
    float4 gg = ((const float4*)g)[lane];
    float4 bb = ((const float4*)b)[lane];
    uint2 o2;
    o2.x = pack_bf2(dx*rs*gg.x + bb.x, dy*rs*gg.y + bb.y);
    o2.y = pack_bf2(dz*rs*gg.z + bb.z, dw*rs*gg.w + bb.w);
    ((uint2*)(out + (size_t)row * CDIM))[lane] = o2;
}

// -------------------------- bf16 GEMM (cp.async 2-stage pipeline) ------------
// A:(M,K) bf16 rm, W:(N,K) bf16 rm. Block 128x128x32, 16 warps, warp 32x32.
// epi: 0 = bf16 out, 3 = +res(fp32)->fp32 x2 AND fused LN -> bf16 xh (N==128)
__global__ void __launch_bounds__(512, 2) gemm_tc(
    const bf16* __restrict__ A, const bf16* __restrict__ W,
    const float* __restrict__ bias, const float* __restrict__ res,
    void* __restrict__ outv, bf16* __restrict__ xh_out,
    const float* __restrict__ lng, const float* __restrict__ lnb,
    int M, int N, int K, int epi)
{
    __shared__ uint32_t As[2][128][20];   // rows of 32 bf16 (16 u32), pad 20
    __shared__ uint32_t Ws[2][128][20];
    __shared__ float sRedS[4 * 128];      // LN fused reductions (epi==3)
    __shared__ float sRedQ[4 * 128];
    int tid = threadIdx.x, lane = tid & 31, warp = tid >> 5;
    int wm = warp >> 2, wn = warp & 3;
    int grp = lane >> 2, tig = lane & 3;
    int m0 = blockIdx.y * 128, n0 = blockIdx.x * 128;

    uint32_t sA = smem_u32(&As[0][0][0]);
    uint32_t sW = smem_u32(&Ws[0][0][0]);
    const int STG = 128 * 20 * 4;         // 10240 B per stage

    int lr = tid >> 2, lc8 = (tid & 3) * 8;

    auto issue = [&](int s, int k0) {
        cp16(sA + s * STG + (lr * 20 + (lc8 >> 1)) * 4,
             A + (size_t)(m0 + lr) * K + k0 + lc8);
        cp16(sW + s * STG + (lr * 20 + (lc8 >> 1)) * 4,
             W + (size_t)(n0 + lr) * K + k0 + lc8);
    };

    uint32_t aA0 = smem_u32(&As[0][wm * 32 + (lane & 15)][(lane >> 4) * 4]);
    uint32_t aA1 = aA0 + 16 * 80;
    int brow = ((lane >> 4) << 3) + (lane & 7), bcol = ((lane >> 3) & 1) * 4;
    uint32_t aB0 = smem_u32(&Ws[0][wn * 32 + brow][bcol]);
    uint32_t aB1 = aB0 + 16 * 80;

    float c[2][4][4];
    #pragma unroll
    for (int mt = 0; mt < 2; mt++)
        #pragma unroll
        for (int nt = 0; nt < 4; nt++)
            #pragma unroll
            for (int j = 0; j < 4; j++) c[mt][nt][j] = 0.f;

    int niter = K >> 5;
    issue(0, 0);
    CP_COMMIT();
    for (int it = 0; it < niter; it++) {
        int s = it & 1;
        if (it + 1 < niter) issue(s ^ 1, (it + 1) * 32);
        CP_COMMIT();
        CP_WAIT1();
        __syncthreads();
        uint32_t off = s * STG;
        #pragma unroll
        for (int ks = 0; ks < 2; ks++) {
            uint32_t boff = ks * 32;
            uint32_t a0[4], a1[4], b0[4], b1[4];
            ldsm_x4(a0, aA0 + off + boff);
            ldsm_x4(a1, aA1 + off + boff);
            ldsm_x4(b0, aB0 + off + boff);
            ldsm_x4(b1, aB1 + off + boff);
            uint32_t bf0[2] = {b0[0], b0[1]}, bf1[2] = {b0[2], b0[3]};
            uint32_t bf2[2] = {b1[0], b1[1]}, bf3[2] = {b1[2], b1[3]};
            mma_bf16(c[0][0], a0, bf0); mma_bf16(c[0][1], a0, bf1);
            mma_bf16(c[0][2], a0, bf2); mma_bf16(c[0][3], a0, bf3);
            mma_bf16(c[1][0], a1, bf0); mma_bf16(c[1][1], a1, bf1);
            mma_bf16(c[1][2], a1, bf2); mma_bf16(c[1][3], a1, bf3);
        }
        __syncthreads();
    }

    if (epi == 3) {
        #pragma unroll
        for (int mt = 0; mt < 2; mt++) {
            #pragma unroll
            for (int nt = 0; nt < 4; nt++) {
                int cn = wn * 32 + nt * 8 + tig * 2;
                float2 bp = *(const float2*)&bias[cn];
                #pragma unroll
                for (int half = 0; half < 2; half++) {
                    int row = m0 + wm * 32 + mt * 16 + half * 8 + grp;
                    float v0 = c[mt][nt][half * 2 + 0] + bp.x;
                    float v1 = c[mt][nt][half * 2 + 1] + bp.y;
                    float2 rr = *(const float2*)&res[(size_t)row * 128 + cn];
                    v0 += rr.x; v1 += rr.y;
                    c[mt][nt][half * 2 + 0] = v0;
                    c[mt][nt][half * 2 + 1] = v1;
                    *(float2*)&((float*)outv)[(size_t)row * 128 + cn] =
                        make_float2(v0, v1);
                }
            }
        }
        #pragma unroll
        for (int mt = 0; mt < 2; mt++)
            #pragma unroll
            for (int half = 0; half < 2; half++) {
                int lrow = wm * 32 + mt * 16 + half * 8 + grp;
                float s = 0.f, q = 0.f;
                #pragma unroll
                for (int nt = 0; nt < 4; nt++) {
                    float v0 = c[mt][nt][half * 2 + 0];
                    float v1 = c[mt][nt][half * 2 + 1];
                    s += v0 + v1;
                    q += v0 * v0 + v1 * v1;
                }
                s += __shfl_xor_sync(~0u, s, 1);
                s += __shfl_xor_sync(~0u, s, 2);
                q += __shfl_xor_sync(~0u, q, 1);
                q += __shfl_xor_sync(~0u, q, 2);
                if (tig == 0) {
                    sRedS[wn * 128 + lrow] = s;
                    sRedQ[wn * 128 + lrow] = q;
                }
            }
        __syncthreads();
        #pragma unroll
        for (int mt = 0; mt < 2; mt++)
            #pragma unroll
            for (int half = 0; half < 2; half++) {
                int lrow = wm * 32 + mt * 16 + half * 8 + grp;
                float S = sRedS[lrow] + sRedS[128 + lrow] +
                          sRedS[256 + lrow] + sRedS[384 + lrow];
                float Q = sRedQ[lrow] + sRedQ[128 + lrow] +
                          sRedQ[256 + lrow] + sRedQ[384 + lrow];
                float mu = S * (1.0f / 128.0f);
                float var = Q * (1.0f / 128.0f) - mu * mu;
                float rs = rsqrtf(var + 1e-5f);
                int row = m0 + lrow;
                #pragma unroll
                for (int nt = 0; nt < 4; nt++) {
                    int cn = wn * 32 + nt * 8 + tig * 2;
                    float2 gg = *(const float2*)&lng[cn];
                    float2 bb = *(const float2*)&lnb[cn];
                    float v0 = (c[mt][nt][half * 2 + 0] - mu) * rs * gg.x + bb.x;
                    float v1 = (c[mt][nt][half * 2 + 1] - mu) * rs * gg.y + bb.y;
                    *(uint32_t*)&xh_out[(size_t)row * 128 + cn] = pack_bf2(v0, v1);
                }
            }
        return;
    }

    #pragma unroll
    for (int mt = 0; mt < 2; mt++) {
        int r0 = m0 + wm * 32 + mt * 16 + grp;
        #pragma unroll
        for (int nt = 0; nt < 4; nt++) {
            int cn = n0 + wn * 32 + nt * 8 + tig * 2;
            float2 bp = *(const float2*)&bias[cn];
            #pragma unroll
            for (int half = 0; half < 2; half++) {
                int row = r0 + half * 8;
                float v0 = c[mt][nt][half * 2 + 0] + bp.x;
                float v1 = c[mt][nt][half * 2 + 1] + bp.y;
                ((uint32_t*)outv)[((size_t)row * N + cn) >> 1] = pack_bf2(v0, v1);
            }
        }
    }
}

// -------------------------- fused MLP: out = gelu(xh@W1^T+b1)@W2^T+b2+x2 -----
// grid (MROWS/128), 512 threads. Chunks of 128 fc1-units; W1 chunk in buf0,
// W2 chunk in buf1 (cp.async streamed). smem rows stride 68 u32 (136 bf16).
__global__ void __launch_bounds__(512) mlp_kernel(
    const bf16* __restrict__ xh, const bf16* __restrict__ w1,
    const float* __restrict__ b1, const bf16* __restrict__ w2,
    const float* __restrict__ b2, const float* __restrict__ x2,
    float* __restrict__ out)
{
    extern __shared__ char sm[];
    const int TSZ = 128 * 68 * 4;        // 34816 B per tile
    uint32_t* sX = (uint32_t*)sm;                    // xh block
    uint32_t* sH = (uint32_t*)(sm + TSZ);            // gelu(fc1) chunk
    uint32_t  wb0 = smem_u32(sm + 2 * TSZ);          // W1 chunk
    uint32_t  wb1 = wb0 + TSZ;                       // W2 chunk

    int tid = threadIdx.x, lane = tid & 31, warp = tid >> 5;
    int wm = warp >> 2, wn = warp & 3;
    int grp = lane >> 2, tig = lane & 3;
    int m0 = blockIdx.x * 128;

    uint32_t sXa = smem_u32(sX);
    uint32_t sHa = smem_u32(sH);

    // ---- load xh block + W1 chunk 0 (one cp.async group) ----
    #pragma unroll
    for (int i = 0; i < 4; i++) {
        int idx = tid + i * 512;
        int row = idx >> 4, c8 = (idx & 15) * 8;
        uint32_t doff = (row * 68 + (c8 >> 1)) * 4;
        cp16(sXa + doff, xh + (size_t)(m0 + row) * 128 + c8);
        cp16(wb0 + doff, w1 + (size_t)row * 128 + c8);
    }
    CP_COMMIT();

    // ldmatrix per-lane addresses
    int arow = lane & 15, aucol = (lane >> 4) * 4;
    uint32_t aX0 = sXa + ((wm * 32 + arow) * 68 + aucol) * 4;
    uint32_t aX1 = aX0 + 16 * 272;
    uint32_t aH0 = sHa + ((wm * 32 + arow) * 68 + aucol) * 4;
    uint32_t aH1 = aH0 + 16 * 272;
    int brow = ((lane >> 4) << 3) + (lane & 7), bcol = ((lane >> 3) & 1) * 4;
    uint32_t b0a = (uint32_t)((wn * 32 + brow) * 68 + bcol) * 4;
    uint32_t b1a = (uint32_t)((wn * 32 + 16 + brow) * 68 + bcol) * 4;

    float cO[2][4][4];
    #pragma unroll
    for (int mt = 0; mt < 2; mt++)
        #pragma unroll
        for (int nt = 0; nt < 4; nt++)
            #pragma unroll
            for (int j = 0; j < 4; j++) cO[mt][nt][j] = 0.f;

    for (int ch = 0; ch < 4; ch++) {
        CP_WAIT0();
        __syncthreads();                 // W1_ch (and xh) ready; sH/B done
        // prefetch W2_ch
        #pragma unroll
        for (int i = 0; i < 4; i++) {
            int idx = tid + i * 512;
            int row = idx >> 4, c8 = (idx & 15) * 8;
            cp16(wb1 + (row * 68 + (c8 >> 1)) * 4,
                 w2 + (size_t)row * 512 + ch * 128 + c8);
        }
        CP_COMMIT();

        // ---- phase A: H = xh @ W1_ch^T ----
        float cA[2][4][4];
        #pragma unroll
        for (int mt = 0; mt < 2; mt++)
            #pragma unroll
            for (int nt = 0; nt < 4; nt++)
                #pragma unroll
                for (int j = 0; j < 4; j++) cA[mt][nt][j] = 0.f;
        #pragma unroll
        for (int ks = 0; ks < 8; ks++) {
            uint32_t koff = ks * 32;
            uint32_t a0[4], a1[4], p0[4], p1[4];
            ldsm_x4(a0, aX0 + koff);
            ldsm_x4(a1, aX1 + koff);
            ldsm_x4(p0, wb0 + b0a + koff);
            ldsm_x4(p1, wb0 + b1a + koff);
            uint32_t f0[2] = {p0[0], p0[1]}, f1[2] = {p0[2], p0[3]};
            uint32_t f2[2] = {p1[0], p1[1]}, f3[2] = {p1[2], p1[3]};
            mma_bf16(cA[0][0], a0, f0); mma_bf16(cA[0][1], a0, f1);
            mma_bf16(cA[0][2], a0, f2); mma_bf16(cA[0][3], a0, f3);
            mma_bf16(cA[1][0], a1, f0); mma_bf16(cA[1][1], a1, f1);
            mma_bf16(cA[1][2], a1, f2); mma_bf16(cA[1][3], a1, f3);
        }
        // gelu(+bias) -> sH (bf16)
        #pragma unroll
        for (int mt = 0; mt < 2; mt++) {
            #pragma unroll
            for (int nt = 0; nt < 4; nt++) {
                int cn = wn * 32 + nt * 8 + tig * 2;
                float2 bp = *(const float2*)&b1[ch * 128 + cn];
                #pragma unroll
                for (int half = 0; half < 2; half++) {
                    int lrow = wm * 32 + mt * 16 + half * 8 + grp;
                    float v0 = gelu_exact(cA[mt][nt][half * 2 + 0] + bp.x);
                    float v1 = gelu_exact(cA[mt][nt][half * 2 + 1] + bp.y);
                    sH[lrow * 68 + (cn >> 1)] = pack_bf2(v0, v1);
                }
            }
        }
        CP_WAIT0();
        __syncthreads();                 // W2_ch ready; sH visible
        // prefetch W1_{ch+1} into wb0 (phase A done with it)
        if (ch < 3) {
            #pragma unroll
            for (int i = 0; i < 4; i++) {
                int idx = tid + i * 512;
                int row = idx >> 4, c8 = (idx & 15) * 8;
                cp16(wb0 + (row * 68 + (c8 >> 1)) * 4,
                     w1 + (size_t)((ch + 1) * 128 + row) * 128 + c8);
            }
            CP_COMMIT();
        }
        // ---- phase B: out += H @ W2_ch^T ----
        #pragma unroll
        for (int ks = 0; ks < 8; ks++) {
            uint32_t koff = ks * 32;
            uint32_t a0[4], a1[4], p0[4], p1[4];
            ldsm_x4(a0, aH0 + koff);
            ldsm_x4(a1, aH1 + koff);
            ldsm_x4(p0, wb1 + b0a + koff);
            ldsm_x4(p1, wb1 + b1a + koff);
            uint32_t f0[2] = {p0[0], p0[1]}, f1[2] = {p0[2], p0[3]};
            uint32_t f2[2] = {p1[0], p1[1]}, f3[2] = {p1[2], p1[3]};
            mma_bf16(cO[0][0], a0, f0); mma_bf16(cO[0][1], a0, f1);
            mma_bf16(cO[0][2], a0, f2); mma_bf16(cO[0][3], a0, f3);
            mma_bf16(cO[1][0], a1, f0); mma_bf16(cO[1][1], a1, f1);
            mma_bf16(cO[1][2], a1, f2); mma_bf16(cO[1][3], a1, f3);
        }
        __syncthreads();                 // protect sH / wb1 for next chunk
    }

    // ---- epilogue: + b2 + x2 -> fp32 out ----
    #pragma unroll
    for (int mt = 0; mt < 2; mt++) {
        #pragma unroll
        for (int nt = 0; nt < 4; nt++) {
            int cn = wn * 32 + nt * 8 + tig * 2;
            float2 bp = *(const float2*)&b2[cn];
            #pragma unroll
            for (int half = 0; half < 2; half++) {
                int row = m0 + wm * 32 + mt * 16 + half * 8 + grp;
                float v0 = cO[mt][nt][half * 2 + 0] + bp.x;
                float v1 = cO[mt][nt][half * 2 + 1] + bp.y;
                float2 rr = *(const float2*)&x2[(size_t)row * 128 + cn];
                *(float2*)&out[(size_t)row * 128 + cn] =
                    make_float2(v0 + rr.x, v1 + rr.y);
            }
        }
    }
}

// -------------------------- window pooling (bf16 in/out) ---------------------
__global__ void __launch_bounds__(128) pool_kernel(
    const bf16* __restrict__ xh, const float* __restrict__ pw,
    const float* __restrict__ pb, bf16* __restrict__ pooled)
{
    int w = blockIdx.x;
    int b = w >> 10, ij = w & 1023;
    int i = ij >> 5, j = ij & 31;
    int c = threadIdx.x;
    float acc = 0.f;
    #pragma unroll
    for (int n = 0; n < 64; n++) {
        int r = n >> 3, cc = n & 7;
        size_t tok = (size_t)(b * HW + (i * 8 + r) * 256 + (j * 8 + cc));
        acc += __bfloat162float(xh[tok * CDIM + c]) * pw[n];
    }
    pooled[(size_t)w * CDIM + c] = __float2bfloat16(acc + pb[0]);
}

// -------------------------- attention (register softmax) ---------------------
__global__ void __launch_bounds__(512, 2) attn_kernel(
    const bf16* __restrict__ qkv, const bf16* __restrict__ qkvp,
    bf16* __restrict__ out)
{
    extern __shared__ char smraw[];
    uint32_t* sQ    = (uint32_t*)smraw;                     // 5120
    uint32_t* sK    = (uint32_t*)(smraw + 5120);            // 20480
    uint32_t* sV    = (uint32_t*)(smraw + 25600);           // 20480
    bf16*     sP    = (bf16*)(smraw + 46080);               // 33792
    float*    sRedM = (float*)(smraw + 79872);              // 1024
    float*    sRedS = (float*)(smraw + 80896);              // 1024

    int tid = threadIdx.x, lane = tid & 31, warp = tid >> 5;
    int grp = lane >> 2, tig = lane & 3;
    int w = blockIdx.x, h = blockIdx.y;
    int b = w >> 10, wi = (w >> 5) & 31, wj = w & 31;
    int bt = b << 16;
    int wm = warp >> 2, ng = warp & 3;

    {
        int q = tid >> 3, d4 = (tid & 7) * 4;
        int gi = wi * 8 + (q >> 3), gj = wj * 8 + (q & 7);
        uint2 v = *(const uint2*)&qkv[(size_t)(bt + gi * 256 + gj) * 384 + h * 32 + d4];
        *(uint2*)&sQ[q * 20 + (d4 >> 1)] = v;
    }
    #pragma unroll
    for (int it = 0; it < 4; it++) {
        int idx = tid + it * 512;
        int krow = idx >> 3, d4 = (idx & 7) * 4;
        uint2 kv = make_uint2(0u, 0u), vv = kv;
        if (krow < NROLL) {
            int gi, gj;
            if (krow < 64) {
                gi = wi * 8 + (krow >> 3);
                gj = wj * 8 + (krow & 7);
            } else {
                int raw = g_rolled[krow - 64];
                int m = raw >> 6, r = (raw >> 3) & 7, c = raw & 7;
                gi = (wi * 8 + r - c_sh[m]) & 255;
                gj = (wj * 8 + c - c_sw[m]) & 255;
            }
            size_t base = (size_t)(bt + gi * 256 + gj) * 384 + 128 + h * 32 + d4;
            kv = *(const uint2*)&qkv[base];
            vv = *(const uint2*)&qkv[base + 128];
        } else if (krow < NALL) {
            int p = krow - NROLL;
            int pi = wi + p / 3 - 1, pj = wj + p % 3 - 1;
            if (pi >= 0 && pi < 32 && pj >= 0 && pj < 32) {
                size_t base = (size_t)((b << 10) + pi * 32 + pj) * 384 + 128 + h * 32 + d4;
                kv = *(const uint2*)&qkvp[base];
                vv = *(const uint2*)&qkvp[base + 128];
            }
        }
        *(uint2*)&sK[krow * 20 + (d4 >> 1)] = kv;
        *(uint2*)&sV[krow * 20 + (d4 >> 1)] = vv;
    }
    __syncthreads();

    float inv0, inv1;
    int r0 = wm * 16 + grp;

    {
        uint32_t aQ = smem_u32(&sQ[(wm * 16 + (lane & 15)) * 20 + (lane >> 4) * 4]);
        int brow = ((lane >> 4) << 3) + (lane & 7), bcol = ((lane >> 3) & 1) * 4;
        uint32_t aK[4];
        #pragma unroll
        for (int p = 0; p < 4; p++)
            aK[p] = smem_u32(&sK[(ng * 64 + p * 16 + brow) * 20 + bcol]);

        float c[8][4];
        #pragma unroll
        for (int nt = 0; nt < 8; nt++)
            #pragma unroll
            for (int j = 0; j < 4; j++) c[nt][j] = 0.f;
        #pragma unroll
        for (int ks = 0; ks < 2; ks++) {
            uint32_t boff = ks * 32;
            uint32_t a[4], bfr[8][2];
            ldsm_x4(a, aQ + boff);
            #pragma unroll
            for (int p = 0; p < 4; p++) {
                uint32_t r4[4];
                ldsm_x4(r4, aK[p] + boff);
                bfr[2*p  ][0] = r4[0]; bfr[2*p  ][1] = r4[1];
                bfr[2*p+1][0] = r4[2]; bfr[2*p+1][1] = r4[3];
            }
            #pragma unroll
            for (int nt = 0; nt < 8; nt++)
                mma_bf16(c[nt], a, bfr[nt]);
        }

        const float* tabh = &g_btab[(h * 64) * NPAD];
        #pragma unroll
        for (int nt = 0; nt < 8; nt++) {
            int cn = ng * 64 + nt * 8 + tig * 2;
            #pragma unroll
            for (int half = 0; half < 2; half++) {
                int row = r0 + half * 8;
                float2 tv = *(const float2*)&tabh[row * NPAD + cn];
                float v0 = c[nt][half * 2 + 0] * SCALE + tv.x;
                float v1 = c[nt][half * 2 + 1] * SCALE + tv.y;
                if (cn + 1 >= NROLL) {
                    #pragma unroll
                    for (int e = 0; e < 2; e++) {
                        int k = cn + e;
                        float* vp = e ? &v1 : &v0;
                        if (k >= NALL) { *vp = -1e30f; }
                        else if (k >= NROLL) {
                            int p = k - NROLL;
                            int kr = p / 3, kc = p % 3;
                            int pi = wi + kr - 1, pj = wj + kc - 1;
                            if (!(pi >= 0 && pi < 32 && pj >= 0 && pj < 32))
                                *vp -= 100.f;
                        }
                    }
                }
                c[nt][half * 2 + 0] = v0;
                c[nt][half * 2 + 1] = v1;
            }
        }

        float m0 = -1e30f, m1 = -1e30f;
        #pragma unroll
        for (int nt = 0; nt < 8; nt++) {
            m0 = fmaxf(m0, fmaxf(c[nt][0], c[nt][1]));
            m1 = fmaxf(m1, fmaxf(c[nt][2], c[nt][3]));
        }
        m0 = fmaxf(m0, __shfl_xor_sync(~0u, m0, 1));
        m0 = fmaxf(m0, __shfl_xor_sync(~0u, m0, 2));
        m1 = fmaxf(m1, __shfl_xor_sync(~0u, m1, 1));
        m1 = fmaxf(m1, __shfl_xor_sync(~0u, m1, 2));
        if (tig == 0) {
            sRedM[ng * 64 + r0]     = m0;
            sRedM[ng * 64 + r0 + 8] = m1;
        }
        __syncthreads();
        float M0 = fmaxf(fmaxf(sRedM[r0], sRedM[64 + r0]),
                         fmaxf(sRedM[128 + r0], sRedM[192 + r0]));
        float M1 = fmaxf(fmaxf(sRedM[r0 + 8], sRedM[64 + r0 + 8]),
                         fmaxf(sRedM[128 + r0 + 8], sRedM[192 + r0 + 8]));

        uint32_t* sP32 = (uint32_t*)sP;
        float s0 = 0.f, s1 = 0.f;
        #pragma unroll
        for (int nt = 0; nt < 8; nt++) {
            float e00 = __expf(c[nt][0] - M0);
            float e01 = __expf(c[nt][1] - M0);
            float e10 = __expf(c[nt][2] - M1);
            float e11 = __expf(c[nt][3] - M1);
            s0 += e00 + e01;
            s1 += e10 + e11;
            int ci = ng * 32 + nt * 4 + tig;
            sP32[r0 * 132 + ci]       = pack_bf2(e00, e01);
            sP32[(r0 + 8) * 132 + ci] = pack_bf2(e10, e11);
        }
        s0 += __shfl_xor_sync(~0u, s0, 1);
        s0 += __shfl_xor_sync(~0u, s0, 2);
        s1 += __shfl_xor_sync(~0u, s1, 1);
        s1 += __shfl_xor_sync(~0u, s1, 2);
        if (tig == 0) {
            sRedS[ng * 64 + r0]     = s0;
            sRedS[ng * 64 + r0 + 8] = s1;
        }
        __syncthreads();
        inv0 = 1.0f / (sRedS[r0] + sRedS[64 + r0] +
                       sRedS[128 + r0] + sRedS[192 + r0]);
        inv1 = 1.0f / (sRedS[r0 + 8] + sRedS[64 + r0 + 8] +
                       sRedS[128 + r0 + 8] + sRedS[192 + r0 + 8]);
    }

    {
        int wn = ng;
        uint32_t aP = smem_u32(&((uint32_t*)sP)[(wm * 16 + (lane & 15)) * 132 + (lane >> 4) * 4]);
        uint32_t aV = smem_u32(&sV[(lane & 15) * 20 + wn * 4]);

        float c[4] = {0.f, 0.f, 0.f, 0.f};
        #pragma unroll 4
        for (int kk = 0; kk < NPAD; kk += 16) {
            uint32_t a[4], bfr[2];
            ldsm_x4(a, aP + (kk >> 1) * 4);
            ldsm_x2_trans(bfr, aV + kk * 80);
            mma_bf16(c, a, bfr);
        }
        int d0 = wn * 8 + tig * 2;
        #pragma unroll
        for (int half = 0; half < 2; half++) {
            int row = r0 + half * 8;
            float inv = half ? inv1 : inv0;
            int gi = wi * 8 + (row >> 3), gj = wj * 8 + (row & 7);
            uint32_t* o = (uint32_t*)&out[(size_t)(bt + gi * 256 + gj) * CDIM + h * 32 + d0];
            *o = pack_bf2(c[half * 2 + 0] * inv, c[half * 2 + 1] * inv);
        }
    }
}

// ----------------------------------------------------------------------------
extern "C" void kernel_launch(void* const* d_in, const int* in_sizes, int n_in,
                              void* d_out, int out_size)
{
    const float* x      = (const float*)d_in[0];
    const float* qkv_w  = (const float*)d_in[1];
    const float* qkv_b  = (const float*)d_in[2];
    const float* proj_w = (const float*)d_in[3];
    const float* proj_b = (const float*)d_in[4];
    const float* n1g    = (const float*)d_in[5];
    const float* n1b    = (const float*)d_in[6];
    const float* n2g    = (const float*)d_in[7];
    const float* n2b    = (const float*)d_in[8];
    const float* rpbt   = (const float*)d_in[9];
    const float* rpbn   = (const float*)d_in[10];
    const float* rpbw   = (const float*)d_in[11];
    const float* poolw  = (const float*)d_in[12];
    const float* poolb  = (const float*)d_in[13];
    const float* fc1_w  = (const float*)d_in[14];
    const float* fc1_b  = (const float*)d_in[15];
    const float* fc2_w  = (const float*)d_in[16];
    const float* fc2_b  = (const float*)d_in[17];
    float* outp = (float*)d_out;

    bf16 *p_xh, *p_qkv, *p_pooled, *p_qkvp, *p_attnout;
    bf16 *p_wqkv, *p_wproj, *p_wfc1, *p_wfc2;
    float *p_x2;
    cudaGetSymbolAddress((void**)&p_xh, g_xh);
    cudaGetSymbolAddress((void**)&p_qkv, g_qkv);
    cudaGetSymbolAddress((void**)&p_pooled, g_pooled);
    cudaGetSymbolAddress((void**)&p_qkvp, g_qkvp);
    cudaGetSymbolAddress((void**)&p_attnout, g_attnout);
    cudaGetSymbolAddress((void**)&p_x2, g_x2);
    cudaGetSymbolAddress((void**)&p_wqkv, g_wqkv);
    cudaGetSymbolAddress((void**)&p_wproj, g_wproj);
    cudaGetSymbolAddress((void**)&p_wfc1, g_wfc1);
    cudaGetSymbolAddress((void**)&p_wfc2, g_wfc2);

    const int ATTN_SMEM = 81920;
    cudaFuncSetAttribute(attn_kernel,
                         cudaFuncAttributeMaxDynamicSharedMemorySize, ATTN_SMEM);
    const int MLP_SMEM = 4 * 128 * 68 * 4;   // 139264 B
    cudaFuncSetAttribute(mlp_kernel,
                         cudaFuncAttributeMaxDynamicSharedMemorySize, MLP_SMEM);

    // 0. one-shot tables + weight conversion
    init_rolled_kernel<<<1, 1>>>();
    init_btab_kernel<<<dim3(HEADS, WA), 256>>>(rpbt, rpbn, rpbw);
    cvt_w_kernel<<<48, 256>>>(qkv_w,  p_wqkv, 384 * 128);
    cvt_w_kernel<<<16, 256>>>(proj_w, p_wproj, 128 * 128);
    cvt_w_kernel<<<64, 256>>>(fc1_w,  p_wfc1, 512 * 128);
    cvt_w_kernel<<<64, 256>>>(fc2_w,  p_wfc2, 128 * 512);
    // 1. LN1 -> bf16 xh
    ln_kernel<<<MROWS / 8, 256>>>(x, n1g, n1b, p_xh, MROWS);
    // 2. qkv GEMM  (131072 x 384, K=128) -> bf16
    gemm_tc<<<dim3(384 / 128, MROWS / 128), 512>>>(
        p_xh, p_wqkv, qkv_b, nullptr, p_qkv, nullptr, nullptr, nullptr,
        MROWS, 384, 128, 0);
    // 3. window pooling
    pool_kernel<<<BATCH * NWIN, 128>>>(p_xh, poolw, poolb, p_pooled);
    // 4. qkv of pooled (2048 x 384, K=128) -> bf16
    gemm_tc<<<dim3(384 / 128, (BATCH * NWIN) / 128), 512>>>(
        p_pooled, p_wqkv, qkv_b, nullptr, p_qkvp, nullptr, nullptr, nullptr,
        BATCH * NWIN, 384, 128, 0);
    // 5. focal attention -> bf16 attnout
    attn_kernel<<<dim3(BATCH * NWIN, HEADS), 512, ATTN_SMEM>>>(
        p_qkv, p_qkvp, p_attnout);
    // 6. proj + residual(x) -> fp32 x2  AND fused LN2 -> bf16 xh
    gemm_tc<<<dim3(1, MROWS / 128), 512>>>(
        p_attnout, p_wproj, proj_b, x, p_x2, p_xh, n2g, n2b,
        MROWS, CDIM, 128, 3);
    // 7. fused MLP: out = gelu(xh@W1^T+b1)@W2^T + b2 + x2
    mlp_kernel<<<MROWS / 128, 512, MLP_SMEM>>>(
        p_xh, p_wfc1, fc1_b, p_wfc2, fc2_b, p_x2, outp);
}

// round 17
// speedup vs baseline: 1.9235x; 1.0248x over previous
#include <cuda_runtime.h>
#include <cuda_bf16.h>
#include <cstdint>
#include <cstddef>

// ----------------------------------------------------------------------------
// FocalTransformerBlock  B=2, H=W=256, C=128, HEADS=4, HD=32, WS=8, EXP=3
// bf16 mma + ldmatrix + cp.async; LN1 fused into qkv; LN2 fused into proj;
// fc1+gelu+fc2 fused MLP
// ----------------------------------------------------------------------------

#define BATCH   2
#define HW      65536
#define CDIM    128
#define MROWS   (BATCH*HW)      // 131072
#define NWH     32
#define NWIN    1024
#define WA      64
#define NROLL   220
#define NALL    229
#define NPAD    256
#define HEADS   4
#define HD      32
#define SCALE   0.17677669529663687f

typedef __nv_bfloat16 bf16;

// -------------------------- scratch (static device) -------------------------
__device__ bf16  g_xh[MROWS * CDIM];
__device__ bf16  g_qkv[MROWS * 3 * CDIM];
__device__ bf16  g_pooled[BATCH * NWIN * CDIM];
__device__ bf16  g_qkvp[BATCH * NWIN * 3 * CDIM];
__device__ bf16  g_attnout[MROWS * CDIM];
__device__ float g_x2[MROWS * CDIM];
__device__ int   g_rolled[156];
__device__ float g_btab[HEADS * WA * NPAD];
__device__ bf16  g_wqkv[384 * 128];
__device__ bf16  g_wproj[128 * 128];
__device__ bf16  g_wfc1[512 * 128];
__device__ bf16  g_wfc2[128 * 512];

__constant__ int c_sh[4] = {-3,-3, 3, 3};
__constant__ int c_sw[4] = {-3, 3,-3, 3};

// -------------------------- helpers -----------------------------------------
__device__ __forceinline__ uint32_t pack_bf2(float x, float y) {
    __nv_bfloat162 p = __floats2bfloat162_rn(x, y);
    return *reinterpret_cast<uint32_t*>(&p);
}

__device__ __forceinline__ void mma_bf16(float c[4], const uint32_t a[4],
                                         const uint32_t b[2]) {
    asm volatile(
        "mma.sync.aligned.m16n8k16.row.col.f32.bf16.bf16.f32 "
        "{%0,%1,%2,%3},{%4,%5,%6,%7},{%8,%9},{%0,%1,%2,%3};"
        : "+f"(c[0]), "+f"(c[1]), "+f"(c[2]), "+f"(c[3])
        : "r"(a[0]), "r"(a[1]), "r"(a[2]), "r"(a[3]), "r"(b[0]), "r"(b[1]));
}

__device__ __forceinline__ void ldsm_x4(uint32_t r[4], uint32_t saddr) {
    asm volatile("ldmatrix.sync.aligned.m8n8.x4.shared.b16 {%0,%1,%2,%3}, [%4];"
        : "=r"(r[0]), "=r"(r[1]), "=r"(r[2]), "=r"(r[3]) : "r"(saddr));
}
__device__ __forceinline__ void ldsm_x2_trans(uint32_t r[2], uint32_t saddr) {
    asm volatile("ldmatrix.sync.aligned.m8n8.x2.trans.shared.b16 {%0,%1}, [%2];"
        : "=r"(r[0]), "=r"(r[1]) : "r"(saddr));
}
__device__ __forceinline__ uint32_t smem_u32(const void* p) {
    return (uint32_t)__cvta_generic_to_shared(p);
}
__device__ __forceinline__ void cp16(uint32_t dst, const void* src) {
    asm volatile("cp.async.cg.shared.global [%0], [%1], 16;" :: "r"(dst), "l"(src));
}
#define CP_COMMIT() asm volatile("cp.async.commit_group;")
#define CP_WAIT1()  asm volatile("cp.async.wait_group 1;" ::: "memory")
#define CP_WAIT0()  asm volatile("cp.async.wait_group 0;" ::: "memory")

__device__ __forceinline__ float gelu_exact(float v) {
    return 0.5f * v * (1.0f + erff(v * 0.70710678118654752f));
}

// -------------------------- one-shot init kernels ----------------------------
__global__ void init_rolled_kernel() {
    if (threadIdx.x == 0 && blockIdx.x == 0) {
        int cnt = 0;
        for (int idx = 0; idx < 256; idx++) {
            int m = idx >> 6, r = (idx >> 3) & 7, c = idx & 7;
            bool valid;
            if      (m == 0) valid = (r >= 5) || (c >= 5);
            else if (m == 1) valid = (r >= 5) || (c < 3);
            else if (m == 2) valid = (r < 3)  || (c >= 5);
            else             valid = (r < 3)  || (c < 3);
            if (valid) g_rolled[cnt++] = idx;
        }
    }
}

__global__ void init_btab_kernel(const float* __restrict__ rpbt,
                                 const float* __restrict__ rpbn,
                                 const float* __restrict__ rpbw) {
    int h = blockIdx.x, q = blockIdx.y;
    int k = threadIdx.x;            // 256
    float v = 0.f;
    int qr = q >> 3, qc = q & 7;
    if (k < 64) {
        int kr = k >> 3, kc = k & 7;
        v = rpbt[((qr - kr + 7) * 15 + (qc - kc + 7)) * HEADS + h];
    } else if (k < NROLL) {
        v = rpbn[(size_t)(h * 64 + q) * 156 + (k - 64)];
    } else if (k < NALL) {
        int p = k - NROLL;
        int kr = p / 3, kc = p % 3;
        v = rpbw[h * 100 + (qr - kr + 2) * 10 + (qc - kc + 2)];
    }
    g_btab[(h * 64 + q) * NPAD + k] = v;
}

__global__ void __launch_bounds__(256) cvt_w_kernel(
    const float* __restrict__ w, bf16* __restrict__ o, int n) {
    int i = (blockIdx.x * 256 + threadIdx.x) * 4;
    if (i < n) {
        float4 v = *(const float4*)&w[i];
        uint2 p;
        p.x = pack_bf2(v.x, v.y);
        p.y = pack_bf2(v.z, v.w);
        *(uint2*)&o[i] = p;
    }
}

// -------------------------- fused LN1 + qkv GEMM -----------------------------
// grid (MROWS/128), 512 threads. LN1 on 128 rows of x -> bf16 sX (+ gmem xh),
// then qkv = sX @ Wqkv^T + b over 3 N-chunks of 128, W cp.async double-buffered.
__global__ void __launch_bounds__(512, 2) qkvln_kernel(
    const float* __restrict__ x, const float* __restrict__ lng,
    const float* __restrict__ lnb, const bf16* __restrict__ W,
    const float* __restrict__ bias, bf16* __restrict__ xh_out,
    bf16* __restrict__ qkv_out)
{
    extern __shared__ char sm[];
    const int TSZ = 128 * 68 * 4;                // 34816 B
    uint32_t* sX = (uint32_t*)sm;                // xh block (bf16, stride 68 u32)
    uint32_t  wb0 = smem_u32(sm + TSZ);          // W chunk buffers
    uint32_t  wb1 = wb0 + TSZ;

    int tid = threadIdx.x, lane = tid & 31, warp = tid >> 5;
    int wm = warp >> 2, wn = warp & 3;
    int grp = lane >> 2, tig = lane & 3;
    int m0 = blockIdx.x * 128;

    uint32_t sXa = smem_u32(sX);

    // prefetch W chunk 0 (full 128x128: 2048 x 16B) — overlaps with LN compute
    #pragma unroll
    for (int i = 0; i < 4; i++) {
        int idx = tid + i * 512;
        int row = idx >> 4, c8 = (idx & 15) * 8;
        cp16(wb0 + (row * 68 + (c8 >> 1)) * 4, W + (size_t)row * 128 + c8);
    }
    CP_COMMIT();

    // ---- LN1: 16 warps x 8 rows, identical math to the old ln_kernel ----
    #pragma unroll
    for (int r8 = 0; r8 < 8; r8++) {
        int row = warp * 8 + r8;
        const float4* xr = (const float4*)(x + (size_t)(m0 + row) * CDIM);
        float4 v = xr[lane];
        float s = v.x + v.y + v.z + v.w;
        #pragma unroll
        for (int o = 16; o > 0; o >>= 1) s += __shfl_xor_sync(~0u, s, o);
        float mu = s * (1.0f / CDIM);
        float dx = v.x-mu, dy = v.y-mu, dz = v.z-mu, dw = v.w-mu;
        float s2 = dx*dx + dy*dy + dz*dz + dw*dw;
        #pragma unroll
        for (int o = 16; o > 0; o >>= 1) s2 += __shfl_xor_sync(~0u, s2, o);
        float rs = rsqrtf(s2 * (1.0f / CDIM) + 1e-5f);
        float4 gg = ((const float4*)lng)[lane];
        float4 bb = ((const float4*)lnb)[lane];
        uint2 o2;
        o2.x = pack_bf2(dx*rs*gg.x + bb.x, dy*rs*gg.y + bb.y);
        o2.y = pack_bf2(dz*rs*gg.z + bb.z, dw*rs*gg.w + bb.w);
        sX[row * 68 + lane * 2]     = o2.x;
        sX[row * 68 + lane * 2 + 1] = o2.y;
        ((uint2*)(xh_out + (size_t)(m0 + row) * CDIM))[lane] = o2;
    }
    __syncthreads();

    // ldmatrix per-lane addresses
    int arow = lane & 15, aucol = (lane >> 4) * 4;
    uint32_t aX0 = sXa + ((wm * 32 + arow) * 68 + aucol) * 4;
    uint32_t aX1 = aX0 + 16 * 272;
    int brow = ((lane >> 4) << 3) + (lane & 7), bcol = ((lane >> 3) & 1) * 4;
    uint32_t b0a = (uint32_t)((wn * 32 + brow) * 68 + bcol) * 4;
    uint32_t b1a = (uint32_t)((wn * 32 + 16 + brow) * 68 + bcol) * 4;

    for (int ch = 0; ch < 3; ch++) {
        uint32_t wb = (ch & 1) ? wb1 : wb0;
        if (ch < 2) {   // prefetch next W chunk (full) into other buffer
            uint32_t wbn = (ch & 1) ? wb0 : wb1;
            #pragma unroll
            for (int i = 0; i < 4; i++) {
                int idx = tid + i * 512;
                int row = idx >> 4, c8 = (idx & 15) * 8;
                cp16(wbn + (row * 68 + (c8 >> 1)) * 4,
                     W + (size_t)((ch + 1) * 128 + row) * 128 + c8);
            }
        }
        CP_COMMIT();
        CP_WAIT1();
        __syncthreads();

        float c[2][4][4];
        #pragma unroll
        for (int mt = 0; mt < 2; mt++)
            #pragma unroll
            for (int nt = 0; nt < 4; nt++)
                #pragma unroll
                for (int j = 0; j < 4; j++) c[mt][nt][j] = 0.f;
        #pragma unroll
        for (int ks = 0; ks < 8; ks++) {
            uint32_t koff = ks * 32;
            uint32_t a0[4], a1[4], p0[4], p1[4];
            ldsm_x4(a0, aX0 + koff);
            ldsm_x4(a1, aX1 + koff);
            ldsm_x4(p0, wb + b0a + koff);
            ldsm_x4(p1, wb + b1a + koff);
            uint32_t f0[2] = {p0[0], p0[1]}, f1[2] = {p0[2], p0[3]};
            uint32_t f2[2] = {p1[0], p1[1]}, f3[2] = {p1[2], p1[3]};
            mma_bf16(c[0][0], a0, f0); mma_bf16(c[0][1], a0, f1);
            mma_bf16(c[0][2], a0, f2); mma_bf16(c[0][3], a0, f3);
            mma_bf16(c[1][0], a1, f0); mma_bf16(c[1][1], a1, f1);
            mma_bf16(c[1][2], a1, f2); mma_bf16(c[1][3], a1, f3);
        }
        // epilogue: + bias -> bf16 qkv
        #pragma unroll
        for (int mt = 0; mt < 2; mt++) {
            #pragma unroll
            for (int nt = 0; nt < 4; nt++) {
                int cn = wn * 32 + nt * 8 + tig * 2;
                float2 bp = *(const float2*)&bias[ch * 128 + cn];
                #pragma unroll
                for (int half = 0; half < 2; half++) {
                    int row = m0 + wm * 32 + mt * 16 + half * 8 + grp;
                    float v0 = c[mt][nt][half * 2 + 0] + bp.x;
                    float v1 = c[mt][nt][half * 2 + 1] + bp.y;
                    ((uint32_t*)qkv_out)[((size_t)row * 384 + ch * 128 + cn) >> 1]
                        = pack_bf2(v0, v1);
                }
            }
        }
        __syncthreads();   // protect W buffer reuse
    }
}

// -------------------------- bf16 GEMM (cp.async 2-stage pipeline) ------------
// A:(M,K) bf16 rm, W:(N,K) bf16 rm. Block 128x128x32, 16 warps, warp 32x32.
// epi: 0 = bf16 out, 3 = +res(fp32)->fp32 x2 AND fused LN -> bf16 xh (N==128)
__global__ void __launch_bounds__(512, 2) gemm_tc(
    const bf16* __restrict__ A, const bf16* __restrict__ W,
    const float* __restrict__ bias, const float* __restrict__ res,
    void* __restrict__ outv, bf16* __restrict__ xh_out,
    const float* __restrict__ lng, const float* __restrict__ lnb,
    int M, int N, int K, int epi)
{
    __shared__ uint32_t As[2][128][20];
    __shared__ uint32_t Ws[2][128][20];
    __shared__ float sRedS[4 * 128];
    __shared__ float sRedQ[4 * 128];
    int tid = threadIdx.x, lane = tid & 31, warp = tid >> 5;
    int wm = warp >> 2, wn = warp & 3;
    int grp = lane >> 2, tig = lane & 3;
    int m0 = blockIdx.y * 128, n0 = blockIdx.x * 128;

    uint32_t sA = smem_u32(&As[0][0][0]);
    uint32_t sW = smem_u32(&Ws[0][0][0]);
    const int STG = 128 * 20 * 4;

    int lr = tid >> 2, lc8 = (tid & 3) * 8;

    auto issue = [&](int s, int k0) {
        cp16(sA + s * STG + (lr * 20 + (lc8 >> 1)) * 4,
             A + (size_t)(m0 + lr) * K + k0 + lc8);
        cp16(sW + s * STG + (lr * 20 + (lc8 >> 1)) * 4,
             W + (size_t)(n0 + lr) * K + k0 + lc8);
    };

    uint32_t aA0 = smem_u32(&As[0][wm * 32 + (lane & 15)][(lane >> 4) * 4]);
    uint32_t aA1 = aA0 + 16 * 80;
    int brow = ((lane >> 4) << 3) + (lane & 7), bcol = ((lane >> 3) & 1) * 4;
    uint32_t aB0 = smem_u32(&Ws[0][wn * 32 + brow][bcol]);
    uint32_t aB1 = aB0 + 16 * 80;

    float c[2][4][4];
    #pragma unroll
    for (int mt = 0; mt < 2; mt++)
        #pragma unroll
        for (int nt = 0; nt < 4; nt++)
            #pragma unroll
            for (int j = 0; j < 4; j++) c[mt][nt][j] = 0.f;

    int niter = K >> 5;
    issue(0, 0);
    CP_COMMIT();
    for (int it = 0; it < niter; it++) {
        int s = it & 1;
        if (it + 1 < niter) issue(s ^ 1, (it + 1) * 32);
        CP_COMMIT();
        CP_WAIT1();
        __syncthreads();
        uint32_t off = s * STG;
        #pragma unroll
        for (int ks = 0; ks < 2; ks++) {
            uint32_t boff = ks * 32;
            uint32_t a0[4], a1[4], b0[4], b1[4];
            ldsm_x4(a0, aA0 + off + boff);
            ldsm_x4(a1, aA1 + off + boff);
            ldsm_x4(b0, aB0 + off + boff);
            ldsm_x4(b1, aB1 + off + boff);
            uint32_t bf0[2] = {b0[0], b0[1]}, bf1[2] = {b0[2], b0[3]};
            uint32_t bf2[2] = {b1[0], b1[1]}, bf3[2] = {b1[2], b1[3]};
            mma_bf16(c[0][0], a0, bf0); mma_bf16(c[0][1], a0, bf1);
            mma_bf16(c[0][2], a0, bf2); mma_bf16(c[0][3], a0, bf3);
            mma_bf16(c[1][0], a1, bf0); mma_bf16(c[1][1], a1, bf1);
            mma_bf16(c[1][2], a1, bf2); mma_bf16(c[1][3], a1, bf3);
        }
        __syncthreads();
    }

    if (epi == 3) {
        #pragma unroll
        for (int mt = 0; mt < 2; mt++) {
            #pragma unroll
            for (int nt = 0; nt < 4; nt++) {
                int cn = wn * 32 + nt * 8 + tig * 2;
                float2 bp = *(const float2*)&bias[cn];
                #pragma unroll
                for (int half = 0; half < 2; half++) {
                    int row = m0 + wm * 32 + mt * 16 + half * 8 + grp;
                    float v0 = c[mt][nt][half * 2 + 0] + bp.x;
                    float v1 = c[mt][nt][half * 2 + 1] + bp.y;
                    float2 rr = *(const float2*)&res[(size_t)row * 128 + cn];
                    v0 += rr.x; v1 += rr.y;
                    c[mt][nt][half * 2 + 0] = v0;
                    c[mt][nt][half * 2 + 1] = v1;
                    *(float2*)&((float*)outv)[(size_t)row * 128 + cn] =
                        make_float2(v0, v1);
                }
            }
        }
        #pragma unroll
        for (int mt = 0; mt < 2; mt++)
            #pragma unroll
            for (int half = 0; half < 2; half++) {
                int lrow = wm * 32 + mt * 16 + half * 8 + grp;
                float s = 0.f, q = 0.f;
                #pragma unroll
                for (int nt = 0; nt < 4; nt++) {
                    float v0 = c[mt][nt][half * 2 + 0];
                    float v1 = c[mt][nt][half * 2 + 1];
                    s += v0 + v1;
                    q += v0 * v0 + v1 * v1;
                }
                s += __shfl_xor_sync(~0u, s, 1);
                s += __shfl_xor_sync(~0u, s, 2);
                q += __shfl_xor_sync(~0u, q, 1);
                q += __shfl_xor_sync(~0u, q, 2);
                if (tig == 0) {
                    sRedS[wn * 128 + lrow] = s;
                    sRedQ[wn * 128 + lrow] = q;
                }
            }
        __syncthreads();
        #pragma unroll
        for (int mt = 0; mt < 2; mt++)
            #pragma unroll
            for (int half = 0; half < 2; half++) {
                int lrow = wm * 32 + mt * 16 + half * 8 + grp;
                float S = sRedS[lrow] + sRedS[128 + lrow] +
                          sRedS[256 + lrow] + sRedS[384 + lrow];
                float Q = sRedQ[lrow] + sRedQ[128 + lrow] +
                          sRedQ[256 + lrow] + sRedQ[384 + lrow];
                float mu = S * (1.0f / 128.0f);
                float var = Q * (1.0f / 128.0f) - mu * mu;
                float rs = rsqrtf(var + 1e-5f);
                int row = m0 + lrow;
                #pragma unroll
                for (int nt = 0; nt < 4; nt++) {
                    int cn = wn * 32 + nt * 8 + tig * 2;
                    float2 gg = *(const float2*)&lng[cn];
                    float2 bb = *(const float2*)&lnb[cn];
                    float v0 = (c[mt][nt][half * 2 + 0] - mu) * rs * gg.x + bb.x;
                    float v1 = (c[mt][nt][half * 2 + 1] - mu) * rs * gg.y + bb.y;
                    *(uint32_t*)&xh_out[(size_t)row * 128 + cn] = pack_bf2(v0, v1);
                }
            }
        return;
    }

    #pragma unroll
    for (int mt = 0; mt < 2; mt++) {
        int r0 = m0 + wm * 32 + mt * 16 + grp;
        #pragma unroll
        for (int nt = 0; nt < 4; nt++) {
            int cn = n0 + wn * 32 + nt * 8 + tig * 2;
            float2 bp = *(const float2*)&bias[cn];
            #pragma unroll
            for (int half = 0; half < 2; half++) {
                int row = r0 + half * 8;
                float v0 = c[mt][nt][half * 2 + 0] + bp.x;
                float v1 = c[mt][nt][half * 2 + 1] + bp.y;
                ((uint32_t*)outv)[((size_t)row * N + cn) >> 1] = pack_bf2(v0, v1);
            }
        }
    }
}

// -------------------------- fused MLP ----------------------------------------
__global__ void __launch_bounds__(512) mlp_kernel(
    const bf16* __restrict__ xh, const bf16* __restrict__ w1,
    const float* __restrict__ b1, const bf16* __restrict__ w2,
    const float* __restrict__ b2, const float* __restrict__ x2,
    float* __restrict__ out)
{
    extern __shared__ char sm[];
    const int TSZ = 128 * 68 * 4;        // 34816 B per tile
    uint32_t* sX = (uint32_t*)sm;
    uint32_t* sH = (uint32_t*)(sm + TSZ);
    uint32_t  wb0 = smem_u32(sm + 2 * TSZ);
    uint32_t  wb1 = wb0 + TSZ;

    int tid = threadIdx.x, lane = tid & 31, warp = tid >> 5;
    int wm = warp >> 2, wn = warp & 3;
    int grp = lane >> 2, tig = lane & 3;
    int m0 = blockIdx.x * 128;

    uint32_t sXa = smem_u32(sX);
    uint32_t sHa = smem_u32(sH);

    #pragma unroll
    for (int i = 0; i < 4; i++) {
        int idx = tid + i * 512;
        int row = idx >> 4, c8 = (idx & 15) * 8;
        uint32_t doff = (row * 68 + (c8 >> 1)) * 4;
        cp16(sXa + doff, xh + (size_t)(m0 + row) * 128 + c8);
        cp16(wb0 + doff, w1 + (size_t)row * 128 + c8);
    }
    CP_COMMIT();

    int arow = lane & 15, aucol = (lane >> 4) * 4;
    uint32_t aX0 = sXa + ((wm * 32 + arow) * 68 + aucol) * 4;
    uint32_t aX1 = aX0 + 16 * 272;
    uint32_t aH0 = sHa + ((wm * 32 + arow) * 68 + aucol) * 4;
    uint32_t aH1 = aH0 + 16 * 272;
    int brow = ((lane >> 4) << 3) + (lane & 7), bcol = ((lane >> 3) & 1) * 4;
    uint32_t b0a = (uint32_t)((wn * 32 + brow) * 68 + bcol) * 4;
    uint32_t b1a = (uint32_t)((wn * 32 + 16 + brow) * 68 + bcol) * 4;

    float cO[2][4][4];
    #pragma unroll
    for (int mt = 0; mt < 2; mt++)
        #pragma unroll
        for (int nt = 0; nt < 4; nt++)
            #pragma unroll
            for (int j = 0; j < 4; j++) cO[mt][nt][j] = 0.f;

    for (int ch = 0; ch < 4; ch++) {
        CP_WAIT0();
        __syncthreads();
        #pragma unroll
        for (int i = 0; i < 4; i++) {
            int idx = tid + i * 512;
            int row = idx >> 4, c8 = (idx & 15) * 8;
            cp16(wb1 + (row * 68 + (c8 >> 1)) * 4,
                 w2 + (size_t)row * 512 + ch * 128 + c8);
        }
        CP_COMMIT();

        float cA[2][4][4];
        #pragma unroll
        for (int mt = 0; mt < 2; mt++)
            #pragma unroll
            for (int nt = 0; nt < 4; nt++)
                #pragma unroll
                for (int j = 0; j < 4; j++) cA[mt][nt][j] = 0.f;
        #pragma unroll
        for (int ks = 0; ks < 8; ks++) {
            uint32_t koff = ks * 32;
            uint32_t a0[4], a1[4], p0[4], p1[4];
            ldsm_x4(a0, aX0 + koff);
            ldsm_x4(a1, aX1 + koff);
            ldsm_x4(p0, wb0 + b0a + koff);
            ldsm_x4(p1, wb0 + b1a + koff);
            uint32_t f0[2] = {p0[0], p0[1]}, f1[2] = {p0[2], p0[3]};
            uint32_t f2[2] = {p1[0], p1[1]}, f3[2] = {p1[2], p1[3]};
            mma_bf16(cA[0][0], a0, f0); mma_bf16(cA[0][1], a0, f1);
            mma_bf16(cA[0][2], a0, f2); mma_bf16(cA[0][3], a0, f3);
            mma_bf16(cA[1][0], a1, f0); mma_bf16(cA[1][1], a1, f1);
            mma_bf16(cA[1][2], a1, f2); mma_bf16(cA[1][3], a1, f3);
        }
        #pragma unroll
        for (int mt = 0; mt < 2; mt++) {
            #pragma unroll
            for (int nt = 0; nt < 4; nt++) {
                int cn = wn * 32 + nt * 8 + tig * 2;
                float2 bp = *(const float2*)&b1[ch * 128 + cn];
                #pragma unroll
                for (int half = 0; half < 2; half++) {
                    int lrow = wm * 32 + mt * 16 + half * 8 + grp;
                    float v0 = gelu_exact(cA[mt][nt][half * 2 + 0] + bp.x);
                    float v1 = gelu_exact(cA[mt][nt][half * 2 + 1] + bp.y);
                    sH[lrow * 68 + (cn >> 1)] = pack_bf2(v0, v1);
                }
            }
        }
        CP_WAIT0();
        __syncthreads();
        if (ch < 3) {
            #pragma unroll
            for (int i = 0; i < 4; i++) {
                int idx = tid + i * 512;
                int row = idx >> 4, c8 = (idx & 15) * 8;
                cp16(wb0 + (row * 68 + (c8 >> 1)) * 4,
                     w1 + (size_t)((ch + 1) * 128 + row) * 128 + c8);
            }
            CP_COMMIT();
        }
        #pragma unroll
        for (int ks = 0; ks < 8; ks++) {
            uint32_t koff = ks * 32;
            uint32_t a0[4], a1[4], p0[4], p1[4];
            ldsm_x4(a0, aH0 + koff);
            ldsm_x4(a1, aH1 + koff);
            ldsm_x4(p0, wb1 + b0a + koff);
            ldsm_x4(p1, wb1 + b1a + koff);
            uint32_t f0[2] = {p0[0], p0[1]}, f1[2] = {p0[2], p0[3]};
            uint32_t f2[2] = {p1[0], p1[1]}, f3[2] = {p1[2], p1[3]};
            mma_bf16(cO[0][0], a0, f0); mma_bf16(cO[0][1], a0, f1);
            mma_bf16(cO[0][2], a0, f2); mma_bf16(cO[0][3], a0, f3);
            mma_bf16(cO[1][0], a1, f0); mma_bf16(cO[1][1], a1, f1);
            mma_bf16(cO[1][2], a1, f2); mma_bf16(cO[1][3], a1, f3);
        }
        __syncthreads();
    }

    #pragma unroll
    for (int mt = 0; mt < 2; mt++) {
        #pragma unroll
        for (int nt = 0; nt < 4; nt++) {
            int cn = wn * 32 + nt * 8 + tig * 2;
            float2 bp = *(const float2*)&b2[cn];
            #pragma unroll
            for (int half = 0; half < 2; half++) {
                int row = m0 + wm * 32 + mt * 16 + half * 8 + grp;
                float v0 = cO[mt][nt][half * 2 + 0] + bp.x;
                float v1 = cO[mt][nt][half * 2 + 1] + bp.y;
                float2 rr = *(const float2*)&x2[(size_t)row * 128 + cn];
                *(float2*)&out[(size_t)row * 128 + cn] =
                    make_float2(v0 + rr.x, v1 + rr.y);
            }
        }
    }
}

// -------------------------- window pooling (bf16 in/out) ---------------------
__global__ void __launch_bounds__(128) pool_kernel(
    const bf16* __restrict__ xh, const float* __restrict__ pw,
    const float* __restrict__ pb, bf16* __restrict__ pooled)
{
    int w = blockIdx.x;
    int b = w >> 10, ij = w & 1023;
    int i = ij >> 5, j = ij & 31;
    int c = threadIdx.x;
    float acc = 0.f;
    #pragma unroll
    for (int n = 0; n < 64; n++) {
        int r = n >> 3, cc = n & 7;
        size_t tok = (size_t)(b * HW + (i * 8 + r) * 256 + (j * 8 + cc));
        acc += __bfloat162float(xh[tok * CDIM + c]) * pw[n];
    }
    pooled[(size_t)w * CDIM + c] = __float2bfloat16(acc + pb[0]);
}

// -------------------------- attention (register softmax) ---------------------
__global__ void __launch_bounds__(512, 2) attn_kernel(
    const bf16* __restrict__ qkv, const bf16* __restrict__ qkvp,
    bf16* __restrict__ out)
{
    extern __shared__ char smraw[];
    uint32_t* sQ    = (uint32_t*)smraw;                     // 5120
    uint32_t* sK    = (uint32_t*)(smraw + 5120);            // 20480
    uint32_t* sV    = (uint32_t*)(smraw + 25600);           // 20480
    bf16*     sP    = (bf16*)(smraw + 46080);               // 33792
    float*    sRedM = (float*)(smraw + 79872);              // 1024
    float*    sRedS = (float*)(smraw + 80896);              // 1024

    int tid = threadIdx.x, lane = tid & 31, warp = tid >> 5;
    int grp = lane >> 2, tig = lane & 3;
    int w = blockIdx.x, h = blockIdx.y;
    int b = w >> 10, wi = (w >> 5) & 31, wj = w & 31;
    int bt = b << 16;
    int wm = warp >> 2, ng = warp & 3;

    {
        int q = tid >> 3, d4 = (tid & 7) * 4;
        int gi = wi * 8 + (q >> 3), gj = wj * 8 + (q & 7);
        uint2 v = *(const uint2*)&qkv[(size_t)(bt + gi * 256 + gj) * 384 + h * 32 + d4];
        *(uint2*)&sQ[q * 20 + (d4 >> 1)] = v;
    }
    #pragma unroll
    for (int it = 0; it < 4; it++) {
        int idx = tid + it * 512;
        int krow = idx >> 3, d4 = (idx & 7) * 4;
        uint2 kv = make_uint2(0u, 0u), vv = kv;
        if (krow < NROLL) {
            int gi, gj;
            if (krow < 64) {
                gi = wi * 8 + (krow >> 3);
                gj = wj * 8 + (krow & 7);
            } else {
                int raw = g_rolled[krow - 64];
                int m = raw >> 6, r = (raw >> 3) & 7, c = raw & 7;
                gi = (wi * 8 + r - c_sh[m]) & 255;
                gj = (wj * 8 + c - c_sw[m]) & 255;
            }
            size_t base = (size_t)(bt + gi * 256 + gj) * 384 + 128 + h * 32 + d4;
            kv = *(const uint2*)&qkv[base];
            vv = *(const uint2*)&qkv[base + 128];
        } else if (krow < NALL) {
            int p = krow - NROLL;
            int pi = wi + p / 3 - 1, pj = wj + p % 3 - 1;
            if (pi >= 0 && pi < 32 && pj >= 0 && pj < 32) {
                size_t base = (size_t)((b << 10) + pi * 32 + pj) * 384 + 128 + h * 32 + d4;
                kv = *(const uint2*)&qkvp[base];
                vv = *(const uint2*)&qkvp[base + 128];
            }
        }
        *(uint2*)&sK[krow * 20 + (d4 >> 1)] = kv;
        *(uint2*)&sV[krow * 20 + (d4 >> 1)] = vv;
    }
    __syncthreads();

    float inv0, inv1;
    int r0 = wm * 16 + grp;

    {
        uint32_t aQ = smem_u32(&sQ[(wm * 16 + (lane & 15)) * 20 + (lane >> 4) * 4]);
        int brow = ((lane >> 4) << 3) + (lane & 7), bcol = ((lane >> 3) & 1) * 4;
        uint32_t aK[4];
        #pragma unroll
        for (int p = 0; p < 4; p++)
            aK[p] = smem_u32(&sK[(ng * 64 + p * 16 + brow) * 20 + bcol]);

        float c[8][4];
        #pragma unroll
        for (int nt = 0; nt < 8; nt++)
            #pragma unroll
            for (int j = 0; j < 4; j++) c[nt][j] = 0.f;
        #pragma unroll
        for (int ks = 0; ks < 2; ks++) {
            uint32_t boff = ks * 32;
            uint32_t a[4], bfr[8][2];
            ldsm_x4(a, aQ + boff);
            #pragma unroll
            for (int p = 0; p < 4; p++) {
                uint32_t r4[4];
                ldsm_x4(r4, aK[p] + boff);
                bfr[2*p  ][0] = r4[0]; bfr[2*p  ][1] = r4[1];
                bfr[2*p+1][0] = r4[2]; bfr[2*p+1][1] = r4[3];
            }
            #pragma unroll
            for (int nt = 0; nt < 8; nt++)
                mma_bf16(c[nt], a, bfr[nt]);
        }

        const float* tabh = &g_btab[(h * 64) * NPAD];
        #pragma unroll
        for (int nt = 0; nt < 8; nt++) {
            int cn = ng * 64 + nt * 8 + tig * 2;
            #pragma unroll
            for (int half = 0; half < 2; half++) {
                int row = r0 + half * 8;
                float2 tv = *(const float2*)&tabh[row * NPAD + cn];
                float v0 = c[nt][half * 2 + 0] * SCALE + tv.x;
                float v1 = c[nt][half * 2 + 1] * SCALE + tv.y;
                if (cn + 1 >= NROLL) {
                    #pragma unroll
                    for (int e = 0; e < 2; e++) {
                        int k = cn + e;
                        float* vp = e ? &v1 : &v0;
                        if (k >= NALL) { *vp = -1e30f; }
                        else if (k >= NROLL) {
                            int p = k - NROLL;
                            int kr = p / 3, kc = p % 3;
                            int pi = wi + kr - 1, pj = wj + kc - 1;
                            if (!(pi >= 0 && pi < 32 && pj >= 0 && pj < 32))
                                *vp -= 100.f;
                        }
                    }
                }
                c[nt][half * 2 + 0] = v0;
                c[nt][half * 2 + 1] = v1;
            }
        }

        float m0 = -1e30f, m1 = -1e30f;
        #pragma unroll
        for (int nt = 0; nt < 8; nt++) {
            m0 = fmaxf(m0, fmaxf(c[nt][0], c[nt][1]));
            m1 = fmaxf(m1, fmaxf(c[nt][2], c[nt][3]));
        }
        m0 = fmaxf(m0, __shfl_xor_sync(~0u, m0, 1));
        m0 = fmaxf(m0, __shfl_xor_sync(~0u, m0, 2));
        m1 = fmaxf(m1, __shfl_xor_sync(~0u, m1, 1));
        m1 = fmaxf(m1, __shfl_xor_sync(~0u, m1, 2));
        if (tig == 0) {
            sRedM[ng * 64 + r0]     = m0;
            sRedM[ng * 64 + r0 + 8] = m1;
        }
        __syncthreads();
        float M0 = fmaxf(fmaxf(sRedM[r0], sRedM[64 + r0]),
                         fmaxf(sRedM[128 + r0], sRedM[192 + r0]));
        float M1 = fmaxf(fmaxf(sRedM[r0 + 8], sRedM[64 + r0 + 8]),
                         fmaxf(sRedM[128 + r0 + 8], sRedM[192 + r0 + 8]));

        uint32_t* sP32 = (uint32_t*)sP;
        float s0 = 0.f, s1 = 0.f;
        #pragma unroll
        for (int nt = 0; nt < 8; nt++) {
            float e00 = __expf(c[nt][0] - M0);
            float e01 = __expf(c[nt][1] - M0);
            float e10 = __expf(c[nt][2] - M1);
            float e11 = __expf(c[nt][3] - M1);
            s0 += e00 + e01;
            s1 += e10 + e11;
            int ci = ng * 32 + nt * 4 + tig;
            sP32[r0 * 132 + ci]       = pack_bf2(e00, e01);
            sP32[(r0 + 8) * 132 + ci] = pack_bf2(e10, e11);
        }
        s0 += __shfl_xor_sync(~0u, s0, 1);
        s0 += __shfl_xor_sync(~0u, s0, 2);
        s1 += __shfl_xor_sync(~0u, s1, 1);
        s1 += __shfl_xor_sync(~0u, s1, 2);
        if (tig == 0) {
            sRedS[ng * 64 + r0]     = s0;
            sRedS[ng * 64 + r0 + 8] = s1;
        }
        __syncthreads();
        inv0 = 1.0f / (sRedS[r0] + sRedS[64 + r0] +
                       sRedS[128 + r0] + sRedS[192 + r0]);
        inv1 = 1.0f / (sRedS[r0 + 8] + sRedS[64 + r0 + 8] +
                       sRedS[128 + r0 + 8] + sRedS[192 + r0 + 8]);
    }

    {
        int wn = ng;
        uint32_t aP = smem_u32(&((uint32_t*)sP)[(wm * 16 + (lane & 15)) * 132 + (lane >> 4) * 4]);
        uint32_t aV = smem_u32(&sV[(lane & 15) * 20 + wn * 4]);

        float c[4] = {0.f, 0.f, 0.f, 0.f};
        #pragma unroll 4
        for (int kk = 0; kk < NPAD; kk += 16) {
            uint32_t a[4], bfr[2];
            ldsm_x4(a, aP + (kk >> 1) * 4);
            ldsm_x2_trans(bfr, aV + kk * 80);
            mma_bf16(c, a, bfr);
        }
        int d0 = wn * 8 + tig * 2;
        #pragma unroll
        for (int half = 0; half < 2; half++) {
            int row = r0 + half * 8;
            float inv = half ? inv1 : inv0;
            int gi = wi * 8 + (row >> 3), gj = wj * 8 + (row & 7);
            uint32_t* o = (uint32_t*)&out[(size_t)(bt + gi * 256 + gj) * CDIM + h * 32 + d0];
            *o = pack_bf2(c[half * 2 + 0] * inv, c[half * 2 + 1] * inv);
        }
    }
}

// ----------------------------------------------------------------------------
extern "C" void kernel_launch(void* const* d_in, const int* in_sizes, int n_in,
                              void* d_out, int out_size)
{
    const float* x      = (const float*)d_in[0];
    const float* qkv_w  = (const float*)d_in[1];
    const float* qkv_b  = (const float*)d_in[2];
    const float* proj_w = (const float*)d_in[3];
    const float* proj_b = (const float*)d_in[4];
    const float* n1g    = (const float*)d_in[5];
    const float* n1b    = (const float*)d_in[6];
    const float* n2g    = (const float*)d_in[7];
    const float* n2b    = (const float*)d_in[8];
    const float* rpbt   = (const float*)d_in[9];
    const float* rpbn   = (const float*)d_in[10];
    const float* rpbw   = (const float*)d_in[11];
    const float* poolw  = (const float*)d_in[12];
    const float* poolb  = (const float*)d_in[13];
    const float* fc1_w  = (const float*)d_in[14];
    const float* fc1_b  = (const float*)d_in[15];
    const float* fc2_w  = (const float*)d_in[16];
    const float* fc2_b  = (const float*)d_in[17];
    float* outp = (float*)d_out;

    bf16 *p_xh, *p_qkv, *p_pooled, *p_qkvp, *p_attnout;
    bf16 *p_wqkv, *p_wproj, *p_wfc1, *p_wfc2;
    float *p_x2;
    cudaGetSymbolAddress((void**)&p_xh, g_xh);
    cudaGetSymbolAddress((void**)&p_qkv, g_qkv);
    cudaGetSymbolAddress((void**)&p_pooled, g_pooled);
    cudaGetSymbolAddress((void**)&p_qkvp, g_qkvp);
    cudaGetSymbolAddress((void**)&p_attnout, g_attnout);
    cudaGetSymbolAddress((void**)&p_x2, g_x2);
    cudaGetSymbolAddress((void**)&p_wqkv, g_wqkv);
    cudaGetSymbolAddress((void**)&p_wproj, g_wproj);
    cudaGetSymbolAddress((void**)&p_wfc1, g_wfc1);
    cudaGetSymbolAddress((void**)&p_wfc2, g_wfc2);

    const int ATTN_SMEM = 81920;
    cudaFuncSetAttribute(attn_kernel,
                         cudaFuncAttributeMaxDynamicSharedMemorySize, ATTN_SMEM);
    const int MLP_SMEM = 4 * 128 * 68 * 4;   // 139264 B
    cudaFuncSetAttribute(mlp_kernel,
                         cudaFuncAttributeMaxDynamicSharedMemorySize, MLP_SMEM);
    const int QKV_SMEM = 3 * 128 * 68 * 4;   // 104448 B
    cudaFuncSetAttribute(qkvln_kernel,
                         cudaFuncAttributeMaxDynamicSharedMemorySize, QKV_SMEM);

    // 0. one-shot tables + weight conversion
    init_rolled_kernel<<<1, 1>>>();
    init_btab_kernel<<<dim3(HEADS, WA), 256>>>(rpbt, rpbn, rpbw);
    cvt_w_kernel<<<48, 256>>>(qkv_w,  p_wqkv, 384 * 128);
    cvt_w_kernel<<<16, 256>>>(proj_w, p_wproj, 128 * 128);
    cvt_w_kernel<<<64, 256>>>(fc1_w,  p_wfc1, 512 * 128);
    cvt_w_kernel<<<64, 256>>>(fc2_w,  p_wfc2, 128 * 512);
    // 1. fused LN1 + qkv GEMM (writes xh and qkv)
    qkvln_kernel<<<MROWS / 128, 512, QKV_SMEM>>>(
        x, n1g, n1b, p_wqkv, qkv_b, p_xh, p_qkv);
    // 2. window pooling
    pool_kernel<<<BATCH * NWIN, 128>>>(p_xh, poolw, poolb, p_pooled);
    // 3. qkv of pooled (2048 x 384, K=128) -> bf16
    gemm_tc<<<dim3(384 / 128, (BATCH * NWIN) / 128), 512>>>(
        p_pooled, p_wqkv, qkv_b, nullptr, p_qkvp, nullptr, nullptr, nullptr,
        BATCH * NWIN, 384, 128, 0);
    // 4. focal attention -> bf16 attnout
    attn_kernel<<<dim3(BATCH * NWIN, HEADS), 512, ATTN_SMEM>>>(
        p_qkv, p_qkvp, p_attnout);
    // 5. proj + residual(x) -> fp32 x2  AND fused LN2 -> bf16 xh
    gemm_tc<<<dim3(1, MROWS / 128), 512>>>(
        p_attnout, p_wproj, proj_b, x, p_x2, p_xh, n2g, n2b,
        MROWS, CDIM, 128, 3);
    // 6. fused MLP: out = gelu(xh@W1^T+b1)@W2^T + b2 + x2
    mlp_kernel<<<MROWS / 128, 512, MLP_SMEM>>>(
        p_xh, p_wfc1, fc1_b, p_wfc2, fc2_b, p_x2, outp);
}